// round 11
// baseline (speedup 1.0000x reference)
#include <cuda_runtime.h>
#include <cuda_bf16.h>
#include <math.h>
#include <stdint.h>

// Problem constants
#define Bc   32
#define Nn   256
#define Hh   1024
#define HEADS 8
#define NHID 128
#define NCLS 7
#define BAND 24
#define ROWS (Bc*Nn)          // 8192
#define ALPHA_LRELU 0.2f

typedef __nv_bfloat16 bf16;

// ---------------- device scratch (no allocs allowed) ----------------
__device__ float g_s1b[ROWS];
__device__ float g_s2b[ROWS];
__device__ float g_mean1[Bc*Hh];
__device__ float g_loggat[ROWS*NCLS];
__device__ float g_Bprob[ROWS*NCLS];
__device__ float g_loghmm[ROWS*NCLS];
__device__ float g_blocksums[32];
// bf16 tensors
__device__ bf16 g_hid_cls_bf[ROWS*Hh];
__device__ bf16 g_hid_emo_bf[ROWS*Hh];
__device__ bf16 g_fea_cls_bf[ROWS*Hh];
__device__ bf16 g_fea_emo_bf[ROWS*Hh];
__device__ bf16 g_Wh_bf[ROWS*Hh];
__device__ bf16 g_Wh2_bf[ROWS*Hh];
__device__ bf16 g_h1_bf[ROWS*Hh];
__device__ bf16 g_h2_bf[ROWS*Hh];
__device__ bf16 g_poolWt[Hh*Hh];   // [N][K] k-major
__device__ bf16 g_Wgt[Hh*Hh];
__device__ bf16 g_outWt[Hh*Hh];
// folded classifier tables ([7][1024] row-major)
__device__ float g_U0t[NCLS*Hh];
__device__ float g_U1t[NCLS*Hh];
__device__ float g_U2t[NCLS*Hh];
__device__ float g_Uet[NCLS*Hh];
__device__ float g_cvec[NCLS];

// =================== bf16 mma.sync GEMM (4-stage cp.async pipeline) ==========
#define BM 128
#define BN 128
#define BKg 32
#define GSTG 4
#define APITCH 40                             // halves per smem row (80 B)
#define STAGE_BYTES (2 * BM * APITCH * 2)     // A + B = 20480 B
#define GEMM_SMEM (GSTG * STAGE_BYTES)        // 81920 B

__device__ __forceinline__ uint32_t smem_u32(const void* p) {
    uint32_t a;
    asm("{ .reg .u64 t; cvta.to.shared.u64 t, %1; cvt.u32.u64 %0, t; }" : "=r"(a) : "l"(p));
    return a;
}
__device__ __forceinline__ void cp16(uint32_t s, const void* g) {
    asm volatile("cp.async.cg.shared.global [%0], [%1], 16;" :: "r"(s), "l"(g));
}
#define CP_COMMIT() asm volatile("cp.async.commit_group;" ::: "memory")
#define CP_WAIT2()  asm volatile("cp.async.wait_group 2;" ::: "memory")

__device__ __forceinline__ void ldsm4(uint32_t& r0, uint32_t& r1, uint32_t& r2, uint32_t& r3,
                                      uint32_t addr) {
    asm volatile("ldmatrix.sync.aligned.m8n8.x4.shared.b16 {%0,%1,%2,%3}, [%4];"
                 : "=r"(r0), "=r"(r1), "=r"(r2), "=r"(r3) : "r"(addr));
}
__device__ __forceinline__ void mma_bf16(float& d0, float& d1, float& d2, float& d3,
                                         uint32_t a0, uint32_t a1, uint32_t a2, uint32_t a3,
                                         uint32_t b0, uint32_t b1) {
    asm volatile("mma.sync.aligned.m16n8k16.row.col.f32.bf16.bf16.f32 "
                 "{%0,%1,%2,%3}, {%4,%5,%6,%7}, {%8,%9}, {%0,%1,%2,%3};"
                 : "+f"(d0), "+f"(d1), "+f"(d2), "+f"(d3)
                 : "r"(a0), "r"(a1), "r"(a2), "r"(a3), "r"(b0), "r"(b1));
}

__device__ __forceinline__ void gemm_load_stage(uint32_t sb, int stage, int tid,
                                                const bf16* Ag, const bf16* Bg) {
    uint32_t abase = sb + stage * STAGE_BYTES;
    uint32_t bbase = abase + BM * APITCH * 2;
#pragma unroll
    for (int i = 0; i < 2; i++) {
        int idx = tid + 256 * i;
        int r = idx >> 2;
        int q = idx & 3;
        cp16(abase + r * (APITCH * 2) + q * 16, Ag + (size_t)r * Hh + q * 8);
        cp16(bbase + r * (APITCH * 2) + q * 16, Bg + (size_t)r * Hh + q * 8);
    }
}

// z-batched: blockIdx.z selects (Aa,Ca) or (Ab,Cb). B shared. bf16 output only.
__global__ void __launch_bounds__(256, 2)
mma_gemm(const bf16* __restrict__ Aa, const bf16* __restrict__ Ab,
         bf16* __restrict__ Ca, bf16* __restrict__ Cb,
         const bf16* __restrict__ Bt,
         const float* __restrict__ bias, int dotanh, int T)
{
    extern __shared__ char smem[];
    uint32_t sb = smem_u32(smem);
    const int tid = threadIdx.x;
    const int wid = tid >> 5, lane = tid & 31;
    const int wm = wid >> 2, wn = wid & 3;   // 2x4 warp grid, warp tile 64x32
    const int n0 = blockIdx.x * BN;
    const size_t m0 = (size_t)blockIdx.y * BM;
    const bf16* A = (blockIdx.z == 0) ? Aa : Ab;
    bf16* C = (blockIdx.z == 0) ? Ca : Cb;

    float acc[4][4][4];
#pragma unroll
    for (int mi = 0; mi < 4; mi++)
#pragma unroll
        for (int ni = 0; ni < 4; ni++)
#pragma unroll
            for (int k = 0; k < 4; k++) acc[mi][ni][k] = 0.f;

    const bf16* Arow = A + m0 * Hh;
    const bf16* Brow = Bt + (size_t)n0 * Hh;

    gemm_load_stage(sb, 0, tid, Arow, Brow);
    CP_COMMIT();
    gemm_load_stage(sb, 1, tid, Arow + BKg, Brow + BKg);
    CP_COMMIT();
    gemm_load_stage(sb, 2, tid, Arow + 2 * BKg, Brow + 2 * BKg);
    CP_COMMIT();

    const int tl = lane >> 3;          // ldmatrix tile selector
    const int l7 = lane & 7;

    for (int t = 0; t < T; t++) {
        CP_WAIT2();
        __syncthreads();
        int nc = t + 3;
        if (nc < T)
            gemm_load_stage(sb, nc % GSTG, tid, Arow + nc * BKg, Brow + nc * BKg);
        CP_COMMIT();   // always commit to keep group counting sound

        uint32_t sA = sb + (t % GSTG) * STAGE_BYTES;
        uint32_t sB = sA + BM * APITCH * 2;
#pragma unroll
        for (int ks = 0; ks < 2; ks++) {
            uint32_t a[4][4];
#pragma unroll
            for (int mi = 0; mi < 4; mi++) {
                int row = wm * 64 + mi * 16 + (tl & 1) * 8 + l7;
                int col = ks * 16 + (tl >> 1) * 8;
                ldsm4(a[mi][0], a[mi][1], a[mi][2], a[mi][3],
                      sA + row * (APITCH * 2) + col * 2);
            }
            uint32_t bq[2][4];
#pragma unroll
            for (int nn = 0; nn < 2; nn++) {
                int row = wn * 32 + nn * 16 + (tl >> 1) * 8 + l7;
                int col = ks * 16 + (tl & 1) * 8;
                ldsm4(bq[nn][0], bq[nn][1], bq[nn][2], bq[nn][3],
                      sB + row * (APITCH * 2) + col * 2);
            }
#pragma unroll
            for (int mi = 0; mi < 4; mi++)
#pragma unroll
                for (int ni = 0; ni < 4; ni++)
                    mma_bf16(acc[mi][ni][0], acc[mi][ni][1], acc[mi][ni][2], acc[mi][ni][3],
                             a[mi][0], a[mi][1], a[mi][2], a[mi][3],
                             bq[ni >> 1][(ni & 1) * 2], bq[ni >> 1][(ni & 1) * 2 + 1]);
        }
    }

    const int lq = lane >> 2;
    const int lr = lane & 3;
#pragma unroll
    for (int mi = 0; mi < 4; mi++) {
        int row = (int)m0 + wm * 64 + mi * 16 + lq;
#pragma unroll
        for (int ni = 0; ni < 4; ni++) {
            int col = n0 + wn * 32 + ni * 8 + lr * 2;
            float b0 = 0.f, b1 = 0.f;
            if (bias) { b0 = bias[col]; b1 = bias[col + 1]; }
            float2 v0, v1;
            v0.x = acc[mi][ni][0] + b0; v0.y = acc[mi][ni][1] + b1;
            v1.x = acc[mi][ni][2] + b0; v1.y = acc[mi][ni][3] + b1;
            if (dotanh) {
                v0.x = tanhf(v0.x); v0.y = tanhf(v0.y);
                v1.x = tanhf(v1.x); v1.y = tanhf(v1.y);
            }
            __nv_bfloat162 w0, w1;
            w0.x = __float2bfloat16_rn(v0.x); w0.y = __float2bfloat16_rn(v0.y);
            w1.x = __float2bfloat16_rn(v1.x); w1.y = __float2bfloat16_rn(v1.y);
            *(__nv_bfloat162*)(C + (size_t)row * Hh + col) = w0;
            *(__nv_bfloat162*)(C + (size_t)(row + 8) * Hh + col) = w1;
        }
    }
}

// =================== weight prep / converts ===================
__global__ void transpose_bf_kernel(const float* __restrict__ in, bf16* __restrict__ out,
                                    int K, int N)
{
    __shared__ float tile[32][33];
    int k0 = blockIdx.y * 32, n0 = blockIdx.x * 32;
    int tx = threadIdx.x, ty = threadIdx.y;
    for (int r = ty; r < 32; r += 8) tile[r][tx] = in[(size_t)(k0 + r) * N + n0 + tx];
    __syncthreads();
    for (int r = ty; r < 32; r += 8)
        out[(size_t)(n0 + r) * K + k0 + tx] = __float2bfloat16_rn(tile[tx][r]);
}
__global__ void repack_gatWt_kernel(const float* __restrict__ gw, bf16* __restrict__ Wgt)
{
    int idx = blockIdx.x * 256 + threadIdx.x;
    int n = idx >> 10, f = idx & 1023;
    int h = n >> 7, d = n & 127;
    Wgt[idx] = __float2bfloat16_rn(gw[((size_t)(h << 10 | f)) * NHID + d]);
}
__global__ void cvt_bf_kernel(const float* __restrict__ a, const float* __restrict__ b,
                              bf16* __restrict__ oa, bf16* __restrict__ ob)
{
    const float* src = blockIdx.y ? b : a;
    bf16* dst = blockIdx.y ? ob : oa;
    int idx = (blockIdx.x * 256 + threadIdx.x) * 4;
    float4 v = *(const float4*)(src + idx);
    __nv_bfloat162 w0, w1;
    w0.x = __float2bfloat16_rn(v.x); w0.y = __float2bfloat16_rn(v.y);
    w1.x = __float2bfloat16_rn(v.z); w1.y = __float2bfloat16_rn(v.w);
    *(__nv_bfloat162*)(dst + idx) = w0;
    *(__nv_bfloat162*)(dst + idx + 2) = w1;
}

__global__ void fold_u_kernel(const float* __restrict__ lin0W,
                              const float* __restrict__ clsW,
                              float* __restrict__ U0t, float* __restrict__ U1t)
{
    int r = blockIdx.x;
    int c = threadIdx.x >> 5, l = threadIdx.x & 31;
    const float* row = lin0W + (size_t)r * Hh;
    float acc = 0.f;
    for (int k = l; k < Hh; k += 32) acc += row[k] * clsW[k * NCLS + c];
    for (int o = 16; o > 0; o >>= 1) acc += __shfl_down_sync(0xffffffffu, acc, o);
    if (l == 0) {
        if (r < Hh) U0t[c * Hh + r] = acc;
        else        U1t[c * Hh + (r - Hh)] = acc;
    }
}
__global__ void fold_u2_kernel(const float* __restrict__ lin1W,
                               const float* __restrict__ U1t,
                               float* __restrict__ U2t)
{
    int r = blockIdx.x;
    int c = threadIdx.x >> 5, l = threadIdx.x & 31;
    const float* row = lin1W + (size_t)r * Hh;
    const float* u1 = U1t + c * Hh;
    float acc = 0.f;
    for (int k = l; k < Hh; k += 32) acc += row[k] * u1[k];
    for (int o = 16; o > 0; o >>= 1) acc += __shfl_down_sync(0xffffffffu, acc, o);
    if (l == 0) U2t[c * Hh + r] = acc;
}
__global__ void fold_cvec_kernel(const float* __restrict__ lin0b,
                                 const float* __restrict__ lin1b,
                                 const float* __restrict__ clsW,
                                 const float* __restrict__ clsb,
                                 const float* __restrict__ U1t,
                                 float* __restrict__ cvec)
{
    int c = threadIdx.x >> 5, l = threadIdx.x & 31;
    float acc = 0.f;
    for (int k = l; k < Hh; k += 32)
        acc += lin0b[k] * clsW[k * NCLS + c] + lin1b[k] * U1t[c * Hh + k];
    for (int o = 16; o > 0; o >>= 1) acc += __shfl_down_sync(0xffffffffu, acc, o);
    if (l == 0) cvec[c] = acc + clsb[c];
}
// Uet[c][k] = clsW[k][c]
__global__ void build_uet_kernel(const float* __restrict__ clsW, float* __restrict__ Uet)
{
    int idx = blockIdx.x * 256 + threadIdx.x;
    if (idx < NCLS * Hh) {
        int c = idx / Hh, k = idx % Hh;
        Uet[idx] = clsW[k * NCLS + c];
    }
}

// =================== small kernels ===================
__global__ void mean_rows_kernel(const bf16* __restrict__ X, float* __restrict__ out)
{
    int b = blockIdx.y;
    int c = blockIdx.x * 256 + threadIdx.x;
    const bf16* p = X + (size_t)b * Nn * Hh + c;
    float s = 0.f;
    for (int n = 0; n < Nn; n++) s += __bfloat162float(p[(size_t)n * Hh]);
    out[b * Hh + c] = s * (1.0f / Nn);
}

__device__ __forceinline__ float eluf(float x) { return x > 0.f ? x : expf(x) - 1.0f; }

__global__ void att1_tile_kernel(const bf16* __restrict__ Wh,
                                 const float* __restrict__ gat_a1,
                                 const float* __restrict__ gat_a2,
                                 bf16* __restrict__ h1)
{
    __shared__ float sW[55][128];
    __shared__ float sc1[55], sc2[55];
    __shared__ float sw[32][24];
    int b = blockIdx.z, h = blockIdx.y, it = blockIdx.x;
    int i0 = it * 32;
    int jlo0 = i0 - 23; if (jlo0 < 0) jlo0 = 0;
    int nrows = (i0 + 31) - jlo0 + 1;          // <= 55
    int tid = threadIdx.x;
    int warp = tid >> 5, lane = tid & 31;
    const bf16* base = Wh + (size_t)b * Nn * Hh + h * NHID;
    for (int rr = 0; rr < nrows; rr++)
        sW[rr][tid] = __bfloat162float(base[(size_t)(jlo0 + rr) * Hh + tid]);
    __syncthreads();
    {
        float a1v[4], a2v[4];
#pragma unroll
        for (int t = 0; t < 4; t++) {
            a1v[t] = gat_a1[h * NHID + lane + 32 * t];
            a2v[t] = gat_a2[h * NHID + lane + 32 * t];
        }
        for (int rr = warp; rr < nrows; rr += 4) {
            float d1 = 0.f, d2 = 0.f;
#pragma unroll
            for (int t = 0; t < 4; t++) {
                float v = sW[rr][lane + 32 * t];
                d1 += v * a1v[t];
                d2 += v * a2v[t];
            }
            for (int o = 16; o > 0; o >>= 1) {
                d1 += __shfl_down_sync(0xffffffffu, d1, o);
                d2 += __shfl_down_sync(0xffffffffu, d2, o);
            }
            if (lane == 0) { sc1[rr] = d1; sc2[rr] = d2; }
        }
    }
    __syncthreads();
    if (tid < 32) {
        int i = i0 + tid;
        if (i > 0) {
            int jl = i - 23; if (jl < 0) jl = 0;
            int L = i - jl;
            float si = sc1[i - jlo0];
            float mx = -1e30f;
            for (int t = 0; t < L; t++) {
                float v = si + sc2[jl + t - jlo0];
                v = v > 0.f ? v : ALPHA_LRELU * v;
                sw[tid][t] = v; mx = fmaxf(mx, v);
            }
            float ssum = 0.f;
            for (int t = 0; t < L; t++) { float ex = expf(sw[tid][t] - mx); sw[tid][t] = ex; ssum += ex; }
            float inv = 1.0f / ssum;
            for (int t = 0; t < L; t++) sw[tid][t] *= inv;
        }
    }
    __syncthreads();
    for (int il = 0; il < 32; il++) {
        int i = i0 + il;
        if (i == 0) continue;
        int jl = i - 23; if (jl < 0) jl = 0;
        int L = i - jl, roff = jl - jlo0;
        float acc = 0.f;
        for (int t = 0; t < L; t++) acc += sw[il][t] * sW[roff + t][tid];
        h1[((size_t)b * Nn + i) * Hh + h * NHID + tid] = __float2bfloat16_rn(eluf(acc));
    }
}

__global__ void att1_row0_kernel(const float* __restrict__ mean1, bf16* __restrict__ h1)
{
    int b = blockIdx.x;
    for (int c = threadIdx.x; c < Hh; c += 256)
        h1[(size_t)b * Nn * Hh + c] = __float2bfloat16_rn(eluf(mean1[b * Hh + c]));
}

__global__ void out_scores_kernel(const bf16* __restrict__ Wh2,
                                  const float* __restrict__ a1,
                                  const float* __restrict__ a2,
                                  float* __restrict__ s1, float* __restrict__ s2)
{
    int n = blockIdx.x;
    int tid = threadIdx.x;
    float x1 = 0.f, x2 = 0.f;
    const bf16* x = Wh2 + (size_t)n * Hh;
    for (int c = tid; c < Hh; c += 256) {
        float v = __bfloat162float(x[c]);
        x1 += v * a1[c]; x2 += v * a2[c];
    }
    __shared__ float sh1[8], sh2[8];
    for (int o = 16; o > 0; o >>= 1) {
        x1 += __shfl_down_sync(0xffffffffu, x1, o);
        x2 += __shfl_down_sync(0xffffffffu, x2, o);
    }
    if ((tid & 31) == 0) { sh1[tid >> 5] = x1; sh2[tid >> 5] = x2; }
    __syncthreads();
    if (tid == 0) {
        float t1 = 0.f, t2 = 0.f;
        for (int k = 0; k < 8; k++) { t1 += sh1[k]; t2 += sh2[k]; }
        s1[n] = t1; s2[n] = t2;
    }
}

__global__ void att2_tile_kernel(const bf16* __restrict__ Wh2,
                                 const float* __restrict__ s1,
                                 const float* __restrict__ s2,
                                 bf16* __restrict__ out)
{
    __shared__ float sW[54][128];
    __shared__ float sw[32][24];
    int b = blockIdx.z, ct = blockIdx.y, it = blockIdx.x;
    int i0 = it * 32, c0 = ct * 128;
    int jlo0 = i0 - 23; if (jlo0 < 0) jlo0 = 0;
    int nrows = (i0 + 30) - jlo0 + 1;
    int tid = threadIdx.x;
    const bf16* base = Wh2 + (size_t)b * Nn * Hh + c0;
    for (int rr = 0; rr < nrows; rr++)
        sW[rr][tid] = __bfloat162float(base[(size_t)(jlo0 + rr) * Hh + tid]);
    if (tid < 32) {
        int i = i0 + tid;
        if (i > 0) {
            int jl = i - 23; if (jl < 0) jl = 0;
            int L = i - jl;
            float si = s1[(size_t)b * Nn + i];
            float mx = -1e30f;
            for (int t = 0; t < L; t++) {
                float v = si + s2[(size_t)b * Nn + jl + t];
                v = v > 0.f ? v : ALPHA_LRELU * v;
                sw[tid][t] = v; mx = fmaxf(mx, v);
            }
            float ssum = 0.f;
            for (int t = 0; t < L; t++) { float ex = expf(sw[tid][t] - mx); sw[tid][t] = ex; ssum += ex; }
            float inv = 1.0f / ssum;
            for (int t = 0; t < L; t++) sw[tid][t] *= inv;
        }
    }
    __syncthreads();
    for (int il = 0; il < 32; il++) {
        int i = i0 + il;
        if (i == 0) continue;
        int jl = i - 23; if (jl < 0) jl = 0;
        int L = i - jl, roff = jl - jlo0;
        float acc = 0.f;
        for (int t = 0; t < L; t++) acc += sw[il][t] * sW[roff + t][tid];
        out[((size_t)b * Nn + i) * Hh + c0 + tid] = __float2bfloat16_rn(eluf(acc));
    }
}

// GAT logits with table amortization: 128 blocks x 256 thr, 64 rows/block.
// Dynamic smem: U0 [7][1024] + U2 [7][1024] fp32 = 57344 B.
__global__ void gat_logits_kernel(const bf16* __restrict__ fea_cls,
                                  const bf16* __restrict__ h2,
                                  const float* __restrict__ U0t,
                                  const float* __restrict__ U2t,
                                  const float* __restrict__ cvec,
                                  float* __restrict__ out)
{
    extern __shared__ float us[];          // [0:7168) U0, [7168:14336) U2
    float* U0s = us;
    float* U2s = us + NCLS * Hh;
    int tid = threadIdx.x;
    for (int idx = tid; idx < NCLS * Hh; idx += 256) {
        U0s[idx] = U0t[idx];
        U2s[idx] = U2t[idx];
    }
    float cv[NCLS];
#pragma unroll
    for (int c = 0; c < NCLS; c++) cv[c] = cvec[c];
    __syncthreads();

    int warp = tid >> 5, lane = tid & 31;
    for (int r8 = 0; r8 < 8; r8++) {
        int n = blockIdx.x * 64 + r8 * 8 + warp;
        int i = n & (Nn - 1);
        const bf16* frow = fea_cls + (size_t)n * Hh;
        const bf16* hrow = (i == 0) ? frow : h2 + (size_t)n * Hh;
        float acc[NCLS];
#pragma unroll
        for (int c = 0; c < NCLS; c++) acc[c] = 0.f;
        for (int t = 0; t < 32; t++) {
            int k = lane + 32 * t;
            float xf = __bfloat162float(frow[k]);
            float xh = __bfloat162float(hrow[k]);
#pragma unroll
            for (int c = 0; c < NCLS; c++)
                acc[c] += xf * U0s[c * Hh + k] + xh * U2s[c * Hh + k];
        }
#pragma unroll
        for (int c = 0; c < NCLS; c++)
            for (int o = 16; o > 0; o >>= 1)
                acc[c] += __shfl_down_sync(0xffffffffu, acc[c], o);
        if (lane == 0) {
            float lg[NCLS];
            float mx = -1e30f;
#pragma unroll
            for (int c = 0; c < NCLS; c++) { lg[c] = acc[c] + cv[c]; mx = fmaxf(mx, lg[c]); }
            float s = 0.f;
#pragma unroll
            for (int c = 0; c < NCLS; c++) { lg[c] = expf(lg[c] - mx); s += lg[c]; }
            float inv = 1.0f / s;
#pragma unroll
            for (int c = 0; c < NCLS; c++) out[n * NCLS + c] = lg[c] * inv;
        }
    }
}

// emission probs with table amortization: 128 blocks x 256 thr, 64 rows/block.
// Dynamic smem: Uet [7][1024] fp32 = 28672 B.
__global__ void cls_softmax_kernel(const bf16* __restrict__ X,
                                   const float* __restrict__ Uet,
                                   const float* __restrict__ bcls,
                                   float* __restrict__ out)
{
    extern __shared__ float ws[];          // [7][1024]
    int tid = threadIdx.x;
    for (int idx = tid; idx < NCLS * Hh; idx += 256) ws[idx] = Uet[idx];
    float bv[NCLS];
#pragma unroll
    for (int c = 0; c < NCLS; c++) bv[c] = bcls[c];
    __syncthreads();

    int warp = tid >> 5, lane = tid & 31;
    for (int r8 = 0; r8 < 8; r8++) {
        int n = blockIdx.x * 64 + r8 * 8 + warp;
        const bf16* x = X + (size_t)n * Hh;
        float acc[NCLS];
#pragma unroll
        for (int c = 0; c < NCLS; c++) acc[c] = 0.f;
        for (int t = 0; t < 32; t++) {
            int k = lane + 32 * t;
            float xv = __bfloat162float(x[k]);
#pragma unroll
            for (int c = 0; c < NCLS; c++)
                acc[c] += xv * ws[c * Hh + k];
        }
#pragma unroll
        for (int c = 0; c < NCLS; c++)
            for (int o = 16; o > 0; o >>= 1)
                acc[c] += __shfl_down_sync(0xffffffffu, acc[c], o);
        if (lane == 0) {
            float lg[NCLS];
            float mx = -1e30f;
#pragma unroll
            for (int c = 0; c < NCLS; c++) { lg[c] = acc[c] + bv[c]; mx = fmaxf(mx, lg[c]); }
            float s = 0.f;
#pragma unroll
            for (int c = 0; c < NCLS; c++) { lg[c] = expf(lg[c] - mx); s += lg[c]; }
            float inv = 1.0f / s;
#pragma unroll
            for (int c = 0; c < NCLS; c++) out[n * NCLS + c] = lg[c] * inv;
        }
    }
}

__global__ void hmm_kernel(const float* __restrict__ Bprob,
                           const float* __restrict__ hmmA,
                           float* __restrict__ out)
{
    __shared__ float sAT[NCLS * NCLS];
    int tid = threadIdx.x;
    if (tid < NCLS * NCLS) sAT[tid] = hmmA[(tid % NCLS) * NCLS + (tid / NCLS)];
    __syncthreads();
    int gidx = blockIdx.x * 128 + tid;
    int b = gidx >> 8, i = gidx & 255;
    const float* Bp = Bprob + (size_t)b * Nn * NCLS;
    int t0 = i - (BAND - 1); if (t0 < 0) t0 = 0;
    float p[NCLS]; float s = 0.f;
#pragma unroll
    for (int r = 0; r < NCLS; r++) { p[r] = Bp[t0 * NCLS + r]; s += p[r]; }
    float inv = 1.0f / s;
#pragma unroll
    for (int r = 0; r < NCLS; r++) p[r] *= inv;
    for (int t = t0 + 1; t <= i; t++) {
        float q[NCLS]; s = 0.f;
#pragma unroll
        for (int r = 0; r < NCLS; r++) {
            float a = 0.f;
#pragma unroll
            for (int c = 0; c < NCLS; c++) a += sAT[r * NCLS + c] * p[c];
            a *= Bp[t * NCLS + r];
            q[r] = a; s += a;
        }
        inv = 1.0f / s;
#pragma unroll
        for (int r = 0; r < NCLS; r++) p[r] = q[r] * inv;
    }
#pragma unroll
    for (int r = 0; r < NCLS; r++) out[gidx * NCLS + r] = p[r];
}

__global__ void final_kernel(const float* __restrict__ log_gat,
                             const float* __restrict__ log_hmm,
                             const int* __restrict__ labels,
                             float* __restrict__ outLogits)
{
    int r = blockIdx.x * 256 + threadIdx.x;
    float lg[NCLS];
#pragma unroll
    for (int k = 0; k < NCLS; k++) {
        lg[k] = logf(0.5f * (log_gat[r * NCLS + k] + log_hmm[r * NCLS + k]));
        outLogits[r * NCLS + k] = lg[k];
    }
    int lab = labels[r];
    float picked = (lab >= 0) ? lg[lab] : 0.f;
    for (int o = 16; o > 0; o >>= 1) picked += __shfl_down_sync(0xffffffffu, picked, o);
    __shared__ float sh[8];
    if ((threadIdx.x & 31) == 0) sh[threadIdx.x >> 5] = picked;
    __syncthreads();
    if (threadIdx.x == 0) {
        float s = 0.f;
        for (int k = 0; k < 8; k++) s += sh[k];
        g_blocksums[blockIdx.x] = s;
    }
}

__global__ void finalize_kernel(float* d_out, int has_loss)
{
    if (has_loss) {
        float s = 0.f;
        for (int k = 0; k < 32; k++) s += g_blocksums[k];
        d_out[0] = -s / (float)ROWS;
    }
}

// ---------------- host launch ----------------
template <typename T>
static T* sym(const void* symbol)
{
    void* p = nullptr;
    cudaGetSymbolAddress(&p, symbol);
    return (T*)p;
}

static void gemm_tc(const bf16* A, bf16* C, const bf16* Bt,
                    const float* bias, int dotanh,
                    const bf16* A2 = nullptr, bf16* C2 = nullptr)
{
    dim3 grid(Hh / BN, ROWS / BM, A2 ? 2 : 1);
    mma_gemm<<<grid, 256, GEMM_SMEM>>>(A, A2 ? A2 : A, C, C2 ? C2 : C,
                                       Bt, bias, dotanh, Hh / BKg);
}

extern "C" void kernel_launch(void* const* d_in, const int* in_sizes, int n_in,
                              void* d_out, int out_size)
{
    (void)in_sizes; (void)n_in;
    const float* hidden_cls = (const float*)d_in[0];
    const float* hidden_emo = (const float*)d_in[1];
    const int*   labels     = (const int*)d_in[3];
    const float* pooler_W   = (const float*)d_in[4];
    const float* pooler_b   = (const float*)d_in[5];
    const float* gat_W      = (const float*)d_in[6];
    const float* gat_a1     = (const float*)d_in[7];
    const float* gat_a2     = (const float*)d_in[8];
    const float* out_W      = (const float*)d_in[9];
    const float* out_a1     = (const float*)d_in[10];
    const float* out_a2     = (const float*)d_in[11];
    const float* lin1_W     = (const float*)d_in[12];
    const float* lin1_b     = (const float*)d_in[13];
    const float* lin0_W     = (const float*)d_in[14];
    const float* lin0_b     = (const float*)d_in[15];
    const float* cls_W      = (const float*)d_in[16];
    const float* cls_b      = (const float*)d_in[17];
    const float* hmm_A      = (const float*)d_in[18];

    float* s1b     = sym<float>(g_s1b);
    float* s2b     = sym<float>(g_s2b);
    float* mean1   = sym<float>(g_mean1);
    float* loggat  = sym<float>(g_loggat);
    float* Bprob   = sym<float>(g_Bprob);
    float* loghmm  = sym<float>(g_loghmm);
    bf16* hidcbf   = sym<bf16>(g_hid_cls_bf);
    bf16* hidebf   = sym<bf16>(g_hid_emo_bf);
    bf16* feacbf   = sym<bf16>(g_fea_cls_bf);
    bf16* feaebf   = sym<bf16>(g_fea_emo_bf);
    bf16* Whbf     = sym<bf16>(g_Wh_bf);
    bf16* Wh2bf    = sym<bf16>(g_Wh2_bf);
    bf16* h1bf     = sym<bf16>(g_h1_bf);
    bf16* h2bf     = sym<bf16>(g_h2_bf);
    bf16* poolWt   = sym<bf16>(g_poolWt);
    bf16* Wgt      = sym<bf16>(g_Wgt);
    bf16* outWt    = sym<bf16>(g_outWt);
    float* U0t     = sym<float>(g_U0t);
    float* U1t     = sym<float>(g_U1t);
    float* U2t     = sym<float>(g_U2t);
    float* Uet     = sym<float>(g_Uet);
    float* cvec    = sym<float>(g_cvec);

    cudaFuncSetAttribute(mma_gemm, cudaFuncAttributeMaxDynamicSharedMemorySize, GEMM_SMEM);
    cudaFuncSetAttribute(gat_logits_kernel, cudaFuncAttributeMaxDynamicSharedMemorySize,
                         2 * NCLS * Hh * (int)sizeof(float));
    cudaFuncSetAttribute(cls_softmax_kernel, cudaFuncAttributeMaxDynamicSharedMemorySize,
                         NCLS * Hh * (int)sizeof(float));

    int has_loss = (out_size == ROWS * NCLS + 1) ? 1 : 0;
    float* outLogits = has_loss ? ((float*)d_out + 1) : (float*)d_out;

    // 0) weight prep + input converts + classifier folding
    {
        dim3 blk(32, 8);
        transpose_bf_kernel<<<dim3(Hh / 32, Hh / 32), blk>>>(pooler_W, poolWt, Hh, Hh);
        transpose_bf_kernel<<<dim3(Hh / 32, Hh / 32), blk>>>(out_W, outWt, Hh, Hh);
        repack_gatWt_kernel<<<(Hh * Hh) / 256, 256>>>(gat_W, Wgt);
        cvt_bf_kernel<<<dim3(ROWS * Hh / 1024, 2), 256>>>(hidden_cls, hidden_emo, hidcbf, hidebf);
        fold_u_kernel<<<2 * Hh, 224>>>(lin0_W, cls_W, U0t, U1t);
        fold_u2_kernel<<<Hh, 224>>>(lin1_W, U1t, U2t);
        fold_cvec_kernel<<<1, 224>>>(lin0_b, lin1_b, cls_W, cls_b, U1t, cvec);
        build_uet_kernel<<<(NCLS * Hh + 255) / 256, 256>>>(cls_W, Uet);
    }

    // 1) poolers (tanh + bias), z-batched; bf16 outputs
    gemm_tc(hidcbf, feacbf, poolWt, pooler_b, 1, hidebf, feaebf);

    // 2) GAT layer 1 (scores fused into att1)
    gemm_tc(feacbf, Whbf, Wgt, nullptr, 0);
    mean_rows_kernel<<<dim3(Hh / 256, Bc), 256>>>(Whbf, mean1);
    att1_tile_kernel<<<dim3(8, 8, Bc), 128>>>(Whbf, gat_a1, gat_a2, h1bf);
    att1_row0_kernel<<<Bc, 256>>>(mean1, h1bf);

    // 3) GAT out layer
    gemm_tc(h1bf, Wh2bf, outWt, nullptr, 0);
    out_scores_kernel<<<ROWS, 256>>>(Wh2bf, out_a1, out_a2, s1b, s2b);
    att2_tile_kernel<<<dim3(8, 8, Bc), 128>>>(Wh2bf, s1b, s2b, h2bf);

    // 4) folded classifier head (table-amortized)
    gat_logits_kernel<<<ROWS / 64, 256, 2 * NCLS * Hh * sizeof(float)>>>(
        feacbf, h2bf, U0t, U2t, cvec, loggat);

    // 5) HMM emission probs (table-amortized)
    cls_softmax_kernel<<<ROWS / 64, 256, NCLS * Hh * sizeof(float)>>>(
        feaebf, Uet, cls_b, Bprob);

    // 6) HMM band filter
    hmm_kernel<<<ROWS / 128, 128>>>(Bprob, hmm_A, loghmm);

    // 7) final logits + loss
    final_kernel<<<ROWS / 256, 256>>>(loggat, loghmm, labels, outLogits);
    finalize_kernel<<<1, 1>>>((float*)d_out, has_loss);
}

// round 12
// speedup vs baseline: 1.1530x; 1.1530x over previous
#include <cuda_runtime.h>
#include <cuda_bf16.h>
#include <math.h>
#include <stdint.h>

// Problem constants
#define Bc   32
#define Nn   256
#define Hh   1024
#define HEADS 8
#define NHID 128
#define NCLS 7
#define BAND 24
#define ROWS (Bc*Nn)          // 8192
#define ALPHA_LRELU 0.2f

typedef __nv_bfloat16 bf16;

// ---------------- device scratch (no allocs allowed) ----------------
__device__ float g_s1b[ROWS];
__device__ float g_s2b[ROWS];
__device__ float g_loggat[ROWS*NCLS];
__device__ float g_Bprob[ROWS*NCLS];
__device__ float g_loghmm[ROWS*NCLS];
__device__ float g_blocksums[32];
// bf16 tensors
__device__ bf16 g_hid_cls_bf[ROWS*Hh];
__device__ bf16 g_hid_emo_bf[ROWS*Hh];
__device__ bf16 g_fea_cls_bf[ROWS*Hh];
__device__ bf16 g_fea_emo_bf[ROWS*Hh];
__device__ bf16 g_Wh_bf[ROWS*Hh];
__device__ bf16 g_Wh2_bf[ROWS*Hh];
__device__ bf16 g_h1_bf[ROWS*Hh];
__device__ bf16 g_h2_bf[ROWS*Hh];
__device__ bf16 g_poolWt[Hh*Hh];   // [N][K] k-major
__device__ bf16 g_Wgt[Hh*Hh];
__device__ bf16 g_outWt[Hh*Hh];
// folded classifier tables ([7][1024] row-major)
__device__ float g_U0t[NCLS*Hh];
__device__ float g_U1t[NCLS*Hh];
__device__ float g_U2t[NCLS*Hh];
__device__ float g_cvec[NCLS];

// =================== bf16 mma.sync GEMM (4-stage cp.async pipeline) ==========
#define BM 128
#define BN 128
#define BKg 32
#define GSTG 4
#define APITCH 40                             // halves per smem row (80 B)
#define STAGE_BYTES (2 * BM * APITCH * 2)     // A + B = 20480 B
#define GEMM_SMEM (GSTG * STAGE_BYTES)        // 81920 B

__device__ __forceinline__ uint32_t smem_u32(const void* p) {
    uint32_t a;
    asm("{ .reg .u64 t; cvta.to.shared.u64 t, %1; cvt.u32.u64 %0, t; }" : "=r"(a) : "l"(p));
    return a;
}
__device__ __forceinline__ void cp16(uint32_t s, const void* g) {
    asm volatile("cp.async.cg.shared.global [%0], [%1], 16;" :: "r"(s), "l"(g));
}
#define CP_COMMIT() asm volatile("cp.async.commit_group;" ::: "memory")
#define CP_WAIT2()  asm volatile("cp.async.wait_group 2;" ::: "memory")

__device__ __forceinline__ void ldsm4(uint32_t& r0, uint32_t& r1, uint32_t& r2, uint32_t& r3,
                                      uint32_t addr) {
    asm volatile("ldmatrix.sync.aligned.m8n8.x4.shared.b16 {%0,%1,%2,%3}, [%4];"
                 : "=r"(r0), "=r"(r1), "=r"(r2), "=r"(r3) : "r"(addr));
}
__device__ __forceinline__ void mma_bf16(float& d0, float& d1, float& d2, float& d3,
                                         uint32_t a0, uint32_t a1, uint32_t a2, uint32_t a3,
                                         uint32_t b0, uint32_t b1) {
    asm volatile("mma.sync.aligned.m16n8k16.row.col.f32.bf16.bf16.f32 "
                 "{%0,%1,%2,%3}, {%4,%5,%6,%7}, {%8,%9}, {%0,%1,%2,%3};"
                 : "+f"(d0), "+f"(d1), "+f"(d2), "+f"(d3)
                 : "r"(a0), "r"(a1), "r"(a2), "r"(a3), "r"(b0), "r"(b1));
}

__device__ __forceinline__ void gemm_load_stage(uint32_t sb, int stage, int tid,
                                                const bf16* Ag, const bf16* Bg) {
    uint32_t abase = sb + stage * STAGE_BYTES;
    uint32_t bbase = abase + BM * APITCH * 2;
#pragma unroll
    for (int i = 0; i < 2; i++) {
        int idx = tid + 256 * i;
        int r = idx >> 2;
        int q = idx & 3;
        cp16(abase + r * (APITCH * 2) + q * 16, Ag + (size_t)r * Hh + q * 8);
        cp16(bbase + r * (APITCH * 2) + q * 16, Bg + (size_t)r * Hh + q * 8);
    }
}

// z-batched: blockIdx.z selects (Aa,Ca) or (Ab,Cb). B shared. bf16 output only.
__global__ void __launch_bounds__(256, 2)
mma_gemm(const bf16* __restrict__ Aa, const bf16* __restrict__ Ab,
         bf16* __restrict__ Ca, bf16* __restrict__ Cb,
         const bf16* __restrict__ Bt,
         const float* __restrict__ bias, int dotanh, int T)
{
    extern __shared__ char smem[];
    uint32_t sb = smem_u32(smem);
    const int tid = threadIdx.x;
    const int wid = tid >> 5, lane = tid & 31;
    const int wm = wid >> 2, wn = wid & 3;   // 2x4 warp grid, warp tile 64x32
    const int n0 = blockIdx.x * BN;
    const size_t m0 = (size_t)blockIdx.y * BM;
    const bf16* A = (blockIdx.z == 0) ? Aa : Ab;
    bf16* C = (blockIdx.z == 0) ? Ca : Cb;

    float acc[4][4][4];
#pragma unroll
    for (int mi = 0; mi < 4; mi++)
#pragma unroll
        for (int ni = 0; ni < 4; ni++)
#pragma unroll
            for (int k = 0; k < 4; k++) acc[mi][ni][k] = 0.f;

    const bf16* Arow = A + m0 * Hh;
    const bf16* Brow = Bt + (size_t)n0 * Hh;

    gemm_load_stage(sb, 0, tid, Arow, Brow);
    CP_COMMIT();
    gemm_load_stage(sb, 1, tid, Arow + BKg, Brow + BKg);
    CP_COMMIT();
    gemm_load_stage(sb, 2, tid, Arow + 2 * BKg, Brow + 2 * BKg);
    CP_COMMIT();

    const int tl = lane >> 3;          // ldmatrix tile selector
    const int l7 = lane & 7;

    for (int t = 0; t < T; t++) {
        CP_WAIT2();
        __syncthreads();
        int nc = t + 3;
        if (nc < T)
            gemm_load_stage(sb, nc % GSTG, tid, Arow + nc * BKg, Brow + nc * BKg);
        CP_COMMIT();   // always commit to keep group counting sound

        uint32_t sA = sb + (t % GSTG) * STAGE_BYTES;
        uint32_t sB = sA + BM * APITCH * 2;
#pragma unroll
        for (int ks = 0; ks < 2; ks++) {
            uint32_t a[4][4];
#pragma unroll
            for (int mi = 0; mi < 4; mi++) {
                int row = wm * 64 + mi * 16 + (tl & 1) * 8 + l7;
                int col = ks * 16 + (tl >> 1) * 8;
                ldsm4(a[mi][0], a[mi][1], a[mi][2], a[mi][3],
                      sA + row * (APITCH * 2) + col * 2);
            }
            uint32_t bq[2][4];
#pragma unroll
            for (int nn = 0; nn < 2; nn++) {
                int row = wn * 32 + nn * 16 + (tl >> 1) * 8 + l7;
                int col = ks * 16 + (tl & 1) * 8;
                ldsm4(bq[nn][0], bq[nn][1], bq[nn][2], bq[nn][3],
                      sB + row * (APITCH * 2) + col * 2);
            }
#pragma unroll
            for (int mi = 0; mi < 4; mi++)
#pragma unroll
                for (int ni = 0; ni < 4; ni++)
                    mma_bf16(acc[mi][ni][0], acc[mi][ni][1], acc[mi][ni][2], acc[mi][ni][3],
                             a[mi][0], a[mi][1], a[mi][2], a[mi][3],
                             bq[ni >> 1][(ni & 1) * 2], bq[ni >> 1][(ni & 1) * 2 + 1]);
        }
    }

    const int lq = lane >> 2;
    const int lr = lane & 3;
#pragma unroll
    for (int mi = 0; mi < 4; mi++) {
        int row = (int)m0 + wm * 64 + mi * 16 + lq;
#pragma unroll
        for (int ni = 0; ni < 4; ni++) {
            int col = n0 + wn * 32 + ni * 8 + lr * 2;
            float b0 = 0.f, b1 = 0.f;
            if (bias) { b0 = bias[col]; b1 = bias[col + 1]; }
            float2 v0, v1;
            v0.x = acc[mi][ni][0] + b0; v0.y = acc[mi][ni][1] + b1;
            v1.x = acc[mi][ni][2] + b0; v1.y = acc[mi][ni][3] + b1;
            if (dotanh) {
                v0.x = tanhf(v0.x); v0.y = tanhf(v0.y);
                v1.x = tanhf(v1.x); v1.y = tanhf(v1.y);
            }
            __nv_bfloat162 w0, w1;
            w0.x = __float2bfloat16_rn(v0.x); w0.y = __float2bfloat16_rn(v0.y);
            w1.x = __float2bfloat16_rn(v1.x); w1.y = __float2bfloat16_rn(v1.y);
            *(__nv_bfloat162*)(C + (size_t)row * Hh + col) = w0;
            *(__nv_bfloat162*)(C + (size_t)(row + 8) * Hh + col) = w1;
        }
    }
}

// =================== weight prep / converts ===================
// z-merged: z=0 transposes in0->out0, z=1 transposes in1->out1 (both 1024x1024)
__global__ void transpose2_bf_kernel(const float* __restrict__ in0, bf16* __restrict__ out0,
                                     const float* __restrict__ in1, bf16* __restrict__ out1)
{
    __shared__ float tile[32][33];
    const float* in = blockIdx.z ? in1 : in0;
    bf16* out = blockIdx.z ? out1 : out0;
    int k0 = blockIdx.y * 32, n0 = blockIdx.x * 32;
    int tx = threadIdx.x, ty = threadIdx.y;
    for (int r = ty; r < 32; r += 8) tile[r][tx] = in[(size_t)(k0 + r) * Hh + n0 + tx];
    __syncthreads();
    for (int r = ty; r < 32; r += 8)
        out[(size_t)(n0 + r) * Hh + k0 + tx] = __float2bfloat16_rn(tile[tx][r]);
}
__global__ void repack_gatWt_kernel(const float* __restrict__ gw, bf16* __restrict__ Wgt)
{
    int idx = blockIdx.x * 256 + threadIdx.x;
    int n = idx >> 10, f = idx & 1023;
    int h = n >> 7, d = n & 127;
    Wgt[idx] = __float2bfloat16_rn(gw[((size_t)(h << 10 | f)) * NHID + d]);
}
__global__ void cvt_bf_kernel(const float* __restrict__ a, const float* __restrict__ b,
                              bf16* __restrict__ oa, bf16* __restrict__ ob)
{
    const float* src = blockIdx.y ? b : a;
    bf16* dst = blockIdx.y ? ob : oa;
    int idx = (blockIdx.x * 256 + threadIdx.x) * 4;
    float4 v = *(const float4*)(src + idx);
    __nv_bfloat162 w0, w1;
    w0.x = __float2bfloat16_rn(v.x); w0.y = __float2bfloat16_rn(v.y);
    w1.x = __float2bfloat16_rn(v.z); w1.y = __float2bfloat16_rn(v.w);
    *(__nv_bfloat162*)(dst + idx) = w0;
    *(__nv_bfloat162*)(dst + idx + 2) = w1;
}

__global__ void fold_u_kernel(const float* __restrict__ lin0W,
                              const float* __restrict__ clsW,
                              float* __restrict__ U0t, float* __restrict__ U1t)
{
    int r = blockIdx.x;
    int c = threadIdx.x >> 5, l = threadIdx.x & 31;
    const float* row = lin0W + (size_t)r * Hh;
    float acc = 0.f;
    for (int k = l; k < Hh; k += 32) acc += row[k] * clsW[k * NCLS + c];
    for (int o = 16; o > 0; o >>= 1) acc += __shfl_down_sync(0xffffffffu, acc, o);
    if (l == 0) {
        if (r < Hh) U0t[c * Hh + r] = acc;
        else        U1t[c * Hh + (r - Hh)] = acc;
    }
}
__global__ void fold_u2_kernel(const float* __restrict__ lin1W,
                               const float* __restrict__ U1t,
                               float* __restrict__ U2t)
{
    int r = blockIdx.x;
    int c = threadIdx.x >> 5, l = threadIdx.x & 31;
    const float* row = lin1W + (size_t)r * Hh;
    const float* u1 = U1t + c * Hh;
    float acc = 0.f;
    for (int k = l; k < Hh; k += 32) acc += row[k] * u1[k];
    for (int o = 16; o > 0; o >>= 1) acc += __shfl_down_sync(0xffffffffu, acc, o);
    if (l == 0) U2t[c * Hh + r] = acc;
}
__global__ void fold_cvec_kernel(const float* __restrict__ lin0b,
                                 const float* __restrict__ lin1b,
                                 const float* __restrict__ clsW,
                                 const float* __restrict__ clsb,
                                 const float* __restrict__ U1t,
                                 float* __restrict__ cvec)
{
    int c = threadIdx.x >> 5, l = threadIdx.x & 31;
    float acc = 0.f;
    for (int k = l; k < Hh; k += 32)
        acc += lin0b[k] * clsW[k * NCLS + c] + lin1b[k] * U1t[c * Hh + k];
    for (int o = 16; o > 0; o >>= 1) acc += __shfl_down_sync(0xffffffffu, acc, o);
    if (l == 0) cvec[c] = acc + clsb[c];
}

// =================== small kernels ===================
__device__ __forceinline__ float eluf(float x) { return x > 0.f ? x : expf(x) - 1.0f; }

// fused: column mean over 256 rows of bf16 Wh per batch -> elu -> h1 row 0
__global__ void mean_row0_kernel(const bf16* __restrict__ X, bf16* __restrict__ h1)
{
    int b = blockIdx.y;
    int c = blockIdx.x * 256 + threadIdx.x;
    const bf16* p = X + (size_t)b * Nn * Hh + c;
    float s = 0.f;
    for (int n = 0; n < Nn; n++) s += __bfloat162float(p[(size_t)n * Hh]);
    h1[(size_t)b * Nn * Hh + c] = __float2bfloat16_rn(eluf(s * (1.0f / Nn)));
}

__global__ void att1_tile_kernel(const bf16* __restrict__ Wh,
                                 const float* __restrict__ gat_a1,
                                 const float* __restrict__ gat_a2,
                                 bf16* __restrict__ h1)
{
    __shared__ float sW[55][128];
    __shared__ float sc1[55], sc2[55];
    __shared__ float sw[32][24];
    int b = blockIdx.z, h = blockIdx.y, it = blockIdx.x;
    int i0 = it * 32;
    int jlo0 = i0 - 23; if (jlo0 < 0) jlo0 = 0;
    int nrows = (i0 + 31) - jlo0 + 1;          // <= 55
    int tid = threadIdx.x;
    int warp = tid >> 5, lane = tid & 31;
    const bf16* base = Wh + (size_t)b * Nn * Hh + h * NHID;
    for (int rr = 0; rr < nrows; rr++)
        sW[rr][tid] = __bfloat162float(base[(size_t)(jlo0 + rr) * Hh + tid]);
    __syncthreads();
    {
        float a1v[4], a2v[4];
#pragma unroll
        for (int t = 0; t < 4; t++) {
            a1v[t] = gat_a1[h * NHID + lane + 32 * t];
            a2v[t] = gat_a2[h * NHID + lane + 32 * t];
        }
        for (int rr = warp; rr < nrows; rr += 4) {
            float d1 = 0.f, d2 = 0.f;
#pragma unroll
            for (int t = 0; t < 4; t++) {
                float v = sW[rr][lane + 32 * t];
                d1 += v * a1v[t];
                d2 += v * a2v[t];
            }
            for (int o = 16; o > 0; o >>= 1) {
                d1 += __shfl_down_sync(0xffffffffu, d1, o);
                d2 += __shfl_down_sync(0xffffffffu, d2, o);
            }
            if (lane == 0) { sc1[rr] = d1; sc2[rr] = d2; }
        }
    }
    __syncthreads();
    if (tid < 32) {
        int i = i0 + tid;
        if (i > 0) {
            int jl = i - 23; if (jl < 0) jl = 0;
            int L = i - jl;
            float si = sc1[i - jlo0];
            float mx = -1e30f;
            for (int t = 0; t < L; t++) {
                float v = si + sc2[jl + t - jlo0];
                v = v > 0.f ? v : ALPHA_LRELU * v;
                sw[tid][t] = v; mx = fmaxf(mx, v);
            }
            float ssum = 0.f;
            for (int t = 0; t < L; t++) { float ex = expf(sw[tid][t] - mx); sw[tid][t] = ex; ssum += ex; }
            float inv = 1.0f / ssum;
            for (int t = 0; t < L; t++) sw[tid][t] *= inv;
        }
    }
    __syncthreads();
    for (int il = 0; il < 32; il++) {
        int i = i0 + il;
        if (i == 0) continue;
        int jl = i - 23; if (jl < 0) jl = 0;
        int L = i - jl, roff = jl - jlo0;
        float acc = 0.f;
        for (int t = 0; t < L; t++) acc += sw[il][t] * sW[roff + t][tid];
        h1[((size_t)b * Nn + i) * Hh + h * NHID + tid] = __float2bfloat16_rn(eluf(acc));
    }
}

__global__ void out_scores_kernel(const bf16* __restrict__ Wh2,
                                  const float* __restrict__ a1,
                                  const float* __restrict__ a2,
                                  float* __restrict__ s1, float* __restrict__ s2)
{
    int n = blockIdx.x;
    int tid = threadIdx.x;
    float x1 = 0.f, x2 = 0.f;
    const bf16* x = Wh2 + (size_t)n * Hh;
    for (int c = tid; c < Hh; c += 256) {
        float v = __bfloat162float(x[c]);
        x1 += v * a1[c]; x2 += v * a2[c];
    }
    __shared__ float sh1[8], sh2[8];
    for (int o = 16; o > 0; o >>= 1) {
        x1 += __shfl_down_sync(0xffffffffu, x1, o);
        x2 += __shfl_down_sync(0xffffffffu, x2, o);
    }
    if ((tid & 31) == 0) { sh1[tid >> 5] = x1; sh2[tid >> 5] = x2; }
    __syncthreads();
    if (tid == 0) {
        float t1 = 0.f, t2 = 0.f;
        for (int k = 0; k < 8; k++) { t1 += sh1[k]; t2 += sh2[k]; }
        s1[n] = t1; s2[n] = t2;
    }
}

__global__ void att2_tile_kernel(const bf16* __restrict__ Wh2,
                                 const float* __restrict__ s1,
                                 const float* __restrict__ s2,
                                 bf16* __restrict__ out)
{
    __shared__ float sW[54][128];
    __shared__ float sw[32][24];
    int b = blockIdx.z, ct = blockIdx.y, it = blockIdx.x;
    int i0 = it * 32, c0 = ct * 128;
    int jlo0 = i0 - 23; if (jlo0 < 0) jlo0 = 0;
    int nrows = (i0 + 30) - jlo0 + 1;
    int tid = threadIdx.x;
    const bf16* base = Wh2 + (size_t)b * Nn * Hh + c0;
    for (int rr = 0; rr < nrows; rr++)
        sW[rr][tid] = __bfloat162float(base[(size_t)(jlo0 + rr) * Hh + tid]);
    if (tid < 32) {
        int i = i0 + tid;
        if (i > 0) {
            int jl = i - 23; if (jl < 0) jl = 0;
            int L = i - jl;
            float si = s1[(size_t)b * Nn + i];
            float mx = -1e30f;
            for (int t = 0; t < L; t++) {
                float v = si + s2[(size_t)b * Nn + jl + t];
                v = v > 0.f ? v : ALPHA_LRELU * v;
                sw[tid][t] = v; mx = fmaxf(mx, v);
            }
            float ssum = 0.f;
            for (int t = 0; t < L; t++) { float ex = expf(sw[tid][t] - mx); sw[tid][t] = ex; ssum += ex; }
            float inv = 1.0f / ssum;
            for (int t = 0; t < L; t++) sw[tid][t] *= inv;
        }
    }
    __syncthreads();
    for (int il = 0; il < 32; il++) {
        int i = i0 + il;
        if (i == 0) continue;
        int jl = i - 23; if (jl < 0) jl = 0;
        int L = i - jl, roff = jl - jlo0;
        float acc = 0.f;
        for (int t = 0; t < L; t++) acc += sw[il][t] * sW[roff + t][tid];
        out[((size_t)b * Nn + i) * Hh + c0 + tid] = __float2bfloat16_rn(eluf(acc));
    }
}

__global__ void gat_logits_kernel(const bf16* __restrict__ fea_cls,
                                  const bf16* __restrict__ h2,
                                  const float* __restrict__ U0t,
                                  const float* __restrict__ U2t,
                                  const float* __restrict__ cvec,
                                  float* __restrict__ out)
{
    int n = blockIdx.x;
    int i = n & (Nn - 1);
    int c = threadIdx.x >> 5, l = threadIdx.x & 31;
    const bf16* frow = fea_cls + (size_t)n * Hh;
    const bf16* hrow = (i == 0) ? frow : h2 + (size_t)n * Hh;
    const float* u0 = U0t + c * Hh;
    const float* u2 = U2t + c * Hh;
    float acc = 0.f;
    for (int k = l; k < Hh; k += 32)
        acc += __bfloat162float(frow[k]) * u0[k] + __bfloat162float(hrow[k]) * u2[k];
    for (int o = 16; o > 0; o >>= 1) acc += __shfl_down_sync(0xffffffffu, acc, o);
    __shared__ float sh[NCLS];
    if (l == 0) sh[c] = acc + cvec[c];
    __syncthreads();
    if (threadIdx.x == 0) {
        float mx = sh[0];
        for (int k = 1; k < NCLS; k++) mx = fmaxf(mx, sh[k]);
        float e[NCLS], s = 0.f;
        for (int k = 0; k < NCLS; k++) { e[k] = expf(sh[k] - mx); s += e[k]; }
        float inv = 1.0f / s;
        for (int k = 0; k < NCLS; k++) out[n * NCLS + k] = e[k] * inv;
    }
}

__global__ void cls_softmax_kernel(const bf16* __restrict__ X,
                                   const float* __restrict__ W,
                                   const float* __restrict__ bcls,
                                   float* __restrict__ out)
{
    int n = blockIdx.x;
    int wid = threadIdx.x >> 5, l = threadIdx.x & 31;
    __shared__ float sh[NCLS];
    const bf16* x = X + (size_t)n * Hh;
    float acc = 0.f;
    for (int t = l; t < Hh; t += 32) acc += __bfloat162float(x[t]) * W[t * NCLS + wid];
    for (int o = 16; o > 0; o >>= 1) acc += __shfl_down_sync(0xffffffffu, acc, o);
    if (l == 0) sh[wid] = acc + bcls[wid];
    __syncthreads();
    if (threadIdx.x == 0) {
        float mx = sh[0];
        for (int k = 1; k < NCLS; k++) mx = fmaxf(mx, sh[k]);
        float e[NCLS], s = 0.f;
        for (int k = 0; k < NCLS; k++) { e[k] = expf(sh[k] - mx); s += e[k]; }
        float inv = 1.0f / s;
        for (int k = 0; k < NCLS; k++) out[n * NCLS + k] = e[k] * inv;
    }
}

__global__ void hmm_kernel(const float* __restrict__ Bprob,
                           const float* __restrict__ hmmA,
                           float* __restrict__ out)
{
    __shared__ float sAT[NCLS * NCLS];
    int tid = threadIdx.x;
    if (tid < NCLS * NCLS) sAT[tid] = hmmA[(tid % NCLS) * NCLS + (tid / NCLS)];
    __syncthreads();
    int gidx = blockIdx.x * 128 + tid;
    int b = gidx >> 8, i = gidx & 255;
    const float* Bp = Bprob + (size_t)b * Nn * NCLS;
    int t0 = i - (BAND - 1); if (t0 < 0) t0 = 0;
    float p[NCLS]; float s = 0.f;
#pragma unroll
    for (int r = 0; r < NCLS; r++) { p[r] = Bp[t0 * NCLS + r]; s += p[r]; }
    float inv = 1.0f / s;
#pragma unroll
    for (int r = 0; r < NCLS; r++) p[r] *= inv;
    for (int t = t0 + 1; t <= i; t++) {
        float q[NCLS]; s = 0.f;
#pragma unroll
        for (int r = 0; r < NCLS; r++) {
            float a = 0.f;
#pragma unroll
            for (int c = 0; c < NCLS; c++) a += sAT[r * NCLS + c] * p[c];
            a *= Bp[t * NCLS + r];
            q[r] = a; s += a;
        }
        inv = 1.0f / s;
#pragma unroll
        for (int r = 0; r < NCLS; r++) p[r] = q[r] * inv;
    }
#pragma unroll
    for (int r = 0; r < NCLS; r++) out[gidx * NCLS + r] = p[r];
}

__global__ void final_kernel(const float* __restrict__ log_gat,
                             const float* __restrict__ log_hmm,
                             const int* __restrict__ labels,
                             float* __restrict__ outLogits)
{
    int r = blockIdx.x * 256 + threadIdx.x;
    float lg[NCLS];
#pragma unroll
    for (int k = 0; k < NCLS; k++) {
        lg[k] = logf(0.5f * (log_gat[r * NCLS + k] + log_hmm[r * NCLS + k]));
        outLogits[r * NCLS + k] = lg[k];
    }
    int lab = labels[r];
    float picked = (lab >= 0) ? lg[lab] : 0.f;
    for (int o = 16; o > 0; o >>= 1) picked += __shfl_down_sync(0xffffffffu, picked, o);
    __shared__ float sh[8];
    if ((threadIdx.x & 31) == 0) sh[threadIdx.x >> 5] = picked;
    __syncthreads();
    if (threadIdx.x == 0) {
        float s = 0.f;
        for (int k = 0; k < 8; k++) s += sh[k];
        g_blocksums[blockIdx.x] = s;
    }
}

__global__ void finalize_kernel(float* d_out, int has_loss)
{
    if (has_loss) {
        float s = 0.f;
        for (int k = 0; k < 32; k++) s += g_blocksums[k];
        d_out[0] = -s / (float)ROWS;
    }
}

// ---------------- host launch ----------------
template <typename T>
static T* sym(const void* symbol)
{
    void* p = nullptr;
    cudaGetSymbolAddress(&p, symbol);
    return (T*)p;
}

static void gemm_tc(const bf16* A, bf16* C, const bf16* Bt,
                    const float* bias, int dotanh,
                    const bf16* A2 = nullptr, bf16* C2 = nullptr)
{
    dim3 grid(Hh / BN, ROWS / BM, A2 ? 2 : 1);
    mma_gemm<<<grid, 256, GEMM_SMEM>>>(A, A2 ? A2 : A, C, C2 ? C2 : C,
                                       Bt, bias, dotanh, Hh / BKg);
}

extern "C" void kernel_launch(void* const* d_in, const int* in_sizes, int n_in,
                              void* d_out, int out_size)
{
    (void)in_sizes; (void)n_in;
    const float* hidden_cls = (const float*)d_in[0];
    const float* hidden_emo = (const float*)d_in[1];
    const int*   labels     = (const int*)d_in[3];
    const float* pooler_W   = (const float*)d_in[4];
    const float* pooler_b   = (const float*)d_in[5];
    const float* gat_W      = (const float*)d_in[6];
    const float* gat_a1     = (const float*)d_in[7];
    const float* gat_a2     = (const float*)d_in[8];
    const float* out_W      = (const float*)d_in[9];
    const float* out_a1     = (const float*)d_in[10];
    const float* out_a2     = (const float*)d_in[11];
    const float* lin1_W     = (const float*)d_in[12];
    const float* lin1_b     = (const float*)d_in[13];
    const float* lin0_W     = (const float*)d_in[14];
    const float* lin0_b     = (const float*)d_in[15];
    const float* cls_W      = (const float*)d_in[16];
    const float* cls_b      = (const float*)d_in[17];
    const float* hmm_A      = (const float*)d_in[18];

    float* s1b     = sym<float>(g_s1b);
    float* s2b     = sym<float>(g_s2b);
    float* loggat  = sym<float>(g_loggat);
    float* Bprob   = sym<float>(g_Bprob);
    float* loghmm  = sym<float>(g_loghmm);
    bf16* hidcbf   = sym<bf16>(g_hid_cls_bf);
    bf16* hidebf   = sym<bf16>(g_hid_emo_bf);
    bf16* feacbf   = sym<bf16>(g_fea_cls_bf);
    bf16* feaebf   = sym<bf16>(g_fea_emo_bf);
    bf16* Whbf     = sym<bf16>(g_Wh_bf);
    bf16* Wh2bf    = sym<bf16>(g_Wh2_bf);
    bf16* h1bf     = sym<bf16>(g_h1_bf);
    bf16* h2bf     = sym<bf16>(g_h2_bf);
    bf16* poolWt   = sym<bf16>(g_poolWt);
    bf16* Wgt      = sym<bf16>(g_Wgt);
    bf16* outWt    = sym<bf16>(g_outWt);
    float* U0t     = sym<float>(g_U0t);
    float* U1t     = sym<float>(g_U1t);
    float* U2t     = sym<float>(g_U2t);
    float* cvec    = sym<float>(g_cvec);

    cudaFuncSetAttribute(mma_gemm, cudaFuncAttributeMaxDynamicSharedMemorySize, GEMM_SMEM);

    int has_loss = (out_size == ROWS * NCLS + 1) ? 1 : 0;
    float* outLogits = has_loss ? ((float*)d_out + 1) : (float*)d_out;

    // 0) weight prep + input converts + classifier folding
    {
        dim3 blk(32, 8);
        transpose2_bf_kernel<<<dim3(Hh / 32, Hh / 32, 2), blk>>>(pooler_W, poolWt, out_W, outWt);
        repack_gatWt_kernel<<<(Hh * Hh) / 256, 256>>>(gat_W, Wgt);
        cvt_bf_kernel<<<dim3(ROWS * Hh / 1024, 2), 256>>>(hidden_cls, hidden_emo, hidcbf, hidebf);
        fold_u_kernel<<<2 * Hh, 224>>>(lin0_W, cls_W, U0t, U1t);
        fold_u2_kernel<<<Hh, 224>>>(lin1_W, U1t, U2t);
        fold_cvec_kernel<<<1, 224>>>(lin0_b, lin1_b, cls_W, cls_b, U1t, cvec);
    }

    // 1) poolers (tanh + bias), z-batched; bf16 outputs
    gemm_tc(hidcbf, feacbf, poolWt, pooler_b, 1, hidebf, feaebf);

    // 2) GAT layer 1 (scores fused into att1; mean+row0 fused)
    gemm_tc(feacbf, Whbf, Wgt, nullptr, 0);
    att1_tile_kernel<<<dim3(8, 8, Bc), 128>>>(Whbf, gat_a1, gat_a2, h1bf);
    mean_row0_kernel<<<dim3(Hh / 256, Bc), 256>>>(Whbf, h1bf);

    // 3) GAT out layer
    gemm_tc(h1bf, Wh2bf, outWt, nullptr, 0);
    out_scores_kernel<<<ROWS, 256>>>(Wh2bf, out_a1, out_a2, s1b, s2b);
    att2_tile_kernel<<<dim3(8, 8, Bc), 128>>>(Wh2bf, s1b, s2b, h2bf);

    // 4) folded classifier head
    gat_logits_kernel<<<ROWS, 224>>>(feacbf, h2bf, U0t, U2t, cvec, loggat);

    // 5) HMM emission probs
    cls_softmax_kernel<<<ROWS, 224>>>(feaebf, cls_W, cls_b, Bprob);

    // 6) HMM band filter
    hmm_kernel<<<ROWS / 128, 128>>>(Bprob, hmm_A, loghmm);

    // 7) final logits + loss
    final_kernel<<<ROWS / 256, 256>>>(loggat, loghmm, labels, outLogits);
    finalize_kernel<<<1, 1>>>((float*)d_out, has_loss);
}

// round 13
// speedup vs baseline: 1.2202x; 1.0583x over previous
#include <cuda_runtime.h>
#include <cuda_bf16.h>
#include <math.h>
#include <stdint.h>

// Problem constants
#define Bc   32
#define Nn   256
#define Hh   1024
#define HEADS 8
#define NHID 128
#define NCLS 7
#define BAND 24
#define ROWS (Bc*Nn)          // 8192
#define ALPHA_LRELU 0.2f

typedef __nv_bfloat16 bf16;

// ---------------- device scratch (no allocs allowed) ----------------
__device__ float g_s1b[ROWS];
__device__ float g_s2b[ROWS];
__device__ float g_loggat[ROWS*NCLS];
__device__ float g_Bprob[ROWS*NCLS];
__device__ float g_loghmm[ROWS*NCLS];
__device__ float g_blocksums[32];
// bf16 tensors
__device__ bf16 g_hid_cls_bf[ROWS*Hh];
__device__ bf16 g_hid_emo_bf[ROWS*Hh];
__device__ bf16 g_fea_cls_bf[ROWS*Hh];
__device__ bf16 g_fea_emo_bf[ROWS*Hh];
__device__ bf16 g_Wh_bf[ROWS*Hh];
__device__ bf16 g_Wh2_bf[ROWS*Hh];
__device__ bf16 g_h1_bf[ROWS*Hh];
__device__ bf16 g_h2_bf[ROWS*Hh];
__device__ bf16 g_poolWt[Hh*Hh];   // [N][K] k-major
__device__ bf16 g_Wgt[Hh*Hh];
__device__ bf16 g_outWt[Hh*Hh];
// folded classifier tables ([7][1024] row-major)
__device__ float g_U0t[NCLS*Hh];
__device__ float g_U1t[NCLS*Hh];
__device__ float g_U2t[NCLS*Hh];
__device__ float g_cvec[NCLS];

// =================== bf16 mma.sync GEMM (4-stage cp.async pipeline) ==========
#define BM 128
#define BN 128
#define BKg 32
#define GSTG 4
#define APITCH 40                             // halves per smem row (80 B)
#define STAGE_BYTES (2 * BM * APITCH * 2)     // A + B = 20480 B
#define GEMM_SMEM (GSTG * STAGE_BYTES)        // 81920 B

__device__ __forceinline__ uint32_t smem_u32(const void* p) {
    uint32_t a;
    asm("{ .reg .u64 t; cvta.to.shared.u64 t, %1; cvt.u32.u64 %0, t; }" : "=r"(a) : "l"(p));
    return a;
}
__device__ __forceinline__ void cp16(uint32_t s, const void* g) {
    asm volatile("cp.async.cg.shared.global [%0], [%1], 16;" :: "r"(s), "l"(g));
}
#define CP_COMMIT() asm volatile("cp.async.commit_group;" ::: "memory")
#define CP_WAIT2()  asm volatile("cp.async.wait_group 2;" ::: "memory")

__device__ __forceinline__ void ldsm4(uint32_t& r0, uint32_t& r1, uint32_t& r2, uint32_t& r3,
                                      uint32_t addr) {
    asm volatile("ldmatrix.sync.aligned.m8n8.x4.shared.b16 {%0,%1,%2,%3}, [%4];"
                 : "=r"(r0), "=r"(r1), "=r"(r2), "=r"(r3) : "r"(addr));
}
__device__ __forceinline__ void mma_bf16(float& d0, float& d1, float& d2, float& d3,
                                         uint32_t a0, uint32_t a1, uint32_t a2, uint32_t a3,
                                         uint32_t b0, uint32_t b1) {
    asm volatile("mma.sync.aligned.m16n8k16.row.col.f32.bf16.bf16.f32 "
                 "{%0,%1,%2,%3}, {%4,%5,%6,%7}, {%8,%9}, {%0,%1,%2,%3};"
                 : "+f"(d0), "+f"(d1), "+f"(d2), "+f"(d3)
                 : "r"(a0), "r"(a1), "r"(a2), "r"(a3), "r"(b0), "r"(b1));
}

__device__ __forceinline__ void gemm_load_stage(uint32_t sb, int stage, int tid,
                                                const bf16* Ag, const bf16* Bg) {
    uint32_t abase = sb + stage * STAGE_BYTES;
    uint32_t bbase = abase + BM * APITCH * 2;
#pragma unroll
    for (int i = 0; i < 2; i++) {
        int idx = tid + 256 * i;
        int r = idx >> 2;
        int q = idx & 3;
        cp16(abase + r * (APITCH * 2) + q * 16, Ag + (size_t)r * Hh + q * 8);
        cp16(bbase + r * (APITCH * 2) + q * 16, Bg + (size_t)r * Hh + q * 8);
    }
}

// z-batched: blockIdx.z selects (Aa,Ca) or (Ab,Cb). B shared. bf16 output only.
__global__ void __launch_bounds__(256, 2)
mma_gemm(const bf16* __restrict__ Aa, const bf16* __restrict__ Ab,
         bf16* __restrict__ Ca, bf16* __restrict__ Cb,
         const bf16* __restrict__ Bt,
         const float* __restrict__ bias, int dotanh, int T)
{
    extern __shared__ char smem[];
    uint32_t sb = smem_u32(smem);
    const int tid = threadIdx.x;
    const int wid = tid >> 5, lane = tid & 31;
    const int wm = wid >> 2, wn = wid & 3;   // 2x4 warp grid, warp tile 64x32
    const int n0 = blockIdx.x * BN;
    const size_t m0 = (size_t)blockIdx.y * BM;
    const bf16* A = (blockIdx.z == 0) ? Aa : Ab;
    bf16* C = (blockIdx.z == 0) ? Ca : Cb;

    float acc[4][4][4];
#pragma unroll
    for (int mi = 0; mi < 4; mi++)
#pragma unroll
        for (int ni = 0; ni < 4; ni++)
#pragma unroll
            for (int k = 0; k < 4; k++) acc[mi][ni][k] = 0.f;

    const bf16* Arow = A + m0 * Hh;
    const bf16* Brow = Bt + (size_t)n0 * Hh;

    gemm_load_stage(sb, 0, tid, Arow, Brow);
    CP_COMMIT();
    gemm_load_stage(sb, 1, tid, Arow + BKg, Brow + BKg);
    CP_COMMIT();
    gemm_load_stage(sb, 2, tid, Arow + 2 * BKg, Brow + 2 * BKg);
    CP_COMMIT();

    const int tl = lane >> 3;          // ldmatrix tile selector
    const int l7 = lane & 7;

    for (int t = 0; t < T; t++) {
        CP_WAIT2();
        __syncthreads();
        int nc = t + 3;
        if (nc < T)
            gemm_load_stage(sb, nc % GSTG, tid, Arow + nc * BKg, Brow + nc * BKg);
        CP_COMMIT();   // always commit to keep group counting sound

        uint32_t sA = sb + (t % GSTG) * STAGE_BYTES;
        uint32_t sB = sA + BM * APITCH * 2;
#pragma unroll
        for (int ks = 0; ks < 2; ks++) {
            uint32_t a[4][4];
#pragma unroll
            for (int mi = 0; mi < 4; mi++) {
                int row = wm * 64 + mi * 16 + (tl & 1) * 8 + l7;
                int col = ks * 16 + (tl >> 1) * 8;
                ldsm4(a[mi][0], a[mi][1], a[mi][2], a[mi][3],
                      sA + row * (APITCH * 2) + col * 2);
            }
            uint32_t bq[2][4];
#pragma unroll
            for (int nn = 0; nn < 2; nn++) {
                int row = wn * 32 + nn * 16 + (tl >> 1) * 8 + l7;
                int col = ks * 16 + (tl & 1) * 8;
                ldsm4(bq[nn][0], bq[nn][1], bq[nn][2], bq[nn][3],
                      sB + row * (APITCH * 2) + col * 2);
            }
#pragma unroll
            for (int mi = 0; mi < 4; mi++)
#pragma unroll
                for (int ni = 0; ni < 4; ni++)
                    mma_bf16(acc[mi][ni][0], acc[mi][ni][1], acc[mi][ni][2], acc[mi][ni][3],
                             a[mi][0], a[mi][1], a[mi][2], a[mi][3],
                             bq[ni >> 1][(ni & 1) * 2], bq[ni >> 1][(ni & 1) * 2 + 1]);
        }
    }

    const int lq = lane >> 2;
    const int lr = lane & 3;
#pragma unroll
    for (int mi = 0; mi < 4; mi++) {
        int row = (int)m0 + wm * 64 + mi * 16 + lq;
#pragma unroll
        for (int ni = 0; ni < 4; ni++) {
            int col = n0 + wn * 32 + ni * 8 + lr * 2;
            float b0 = 0.f, b1 = 0.f;
            if (bias) { b0 = bias[col]; b1 = bias[col + 1]; }
            float2 v0, v1;
            v0.x = acc[mi][ni][0] + b0; v0.y = acc[mi][ni][1] + b1;
            v1.x = acc[mi][ni][2] + b0; v1.y = acc[mi][ni][3] + b1;
            if (dotanh) {
                v0.x = tanhf(v0.x); v0.y = tanhf(v0.y);
                v1.x = tanhf(v1.x); v1.y = tanhf(v1.y);
            }
            __nv_bfloat162 w0, w1;
            w0.x = __float2bfloat16_rn(v0.x); w0.y = __float2bfloat16_rn(v0.y);
            w1.x = __float2bfloat16_rn(v1.x); w1.y = __float2bfloat16_rn(v1.y);
            *(__nv_bfloat162*)(C + (size_t)row * Hh + col) = w0;
            *(__nv_bfloat162*)(C + (size_t)(row + 8) * Hh + col) = w1;
        }
    }
}

// =================== weight prep / converts ===================
__global__ void transpose_bf_kernel(const float* __restrict__ in, bf16* __restrict__ out)
{
    __shared__ float tile[32][33];
    int k0 = blockIdx.y * 32, n0 = blockIdx.x * 32;
    int tx = threadIdx.x, ty = threadIdx.y;
    for (int r = ty; r < 32; r += 8) tile[r][tx] = in[(size_t)(k0 + r) * Hh + n0 + tx];
    __syncthreads();
    for (int r = ty; r < 32; r += 8)
        out[(size_t)(n0 + r) * Hh + k0 + tx] = __float2bfloat16_rn(tile[tx][r]);
}
__global__ void repack_gatWt_kernel(const float* __restrict__ gw, bf16* __restrict__ Wgt)
{
    int idx = blockIdx.x * 256 + threadIdx.x;
    int n = idx >> 10, f = idx & 1023;
    int h = n >> 7, d = n & 127;
    Wgt[idx] = __float2bfloat16_rn(gw[((size_t)(h << 10 | f)) * NHID + d]);
}
__global__ void cvt_bf_kernel(const float* __restrict__ a, const float* __restrict__ b,
                              bf16* __restrict__ oa, bf16* __restrict__ ob)
{
    const float* src = blockIdx.y ? b : a;
    bf16* dst = blockIdx.y ? ob : oa;
    int idx = (blockIdx.x * 256 + threadIdx.x) * 4;
    float4 v = *(const float4*)(src + idx);
    __nv_bfloat162 w0, w1;
    w0.x = __float2bfloat16_rn(v.x); w0.y = __float2bfloat16_rn(v.y);
    w1.x = __float2bfloat16_rn(v.z); w1.y = __float2bfloat16_rn(v.w);
    *(__nv_bfloat162*)(dst + idx) = w0;
    *(__nv_bfloat162*)(dst + idx + 2) = w1;
}

__global__ void fold_u_kernel(const float* __restrict__ lin0W,
                              const float* __restrict__ clsW,
                              float* __restrict__ U0t, float* __restrict__ U1t)
{
    int r = blockIdx.x;
    int c = threadIdx.x >> 5, l = threadIdx.x & 31;
    const float* row = lin0W + (size_t)r * Hh;
    float acc = 0.f;
    for (int k = l; k < Hh; k += 32) acc += row[k] * clsW[k * NCLS + c];
    for (int o = 16; o > 0; o >>= 1) acc += __shfl_down_sync(0xffffffffu, acc, o);
    if (l == 0) {
        if (r < Hh) U0t[c * Hh + r] = acc;
        else        U1t[c * Hh + (r - Hh)] = acc;
    }
}
__global__ void fold_u2_kernel(const float* __restrict__ lin1W,
                               const float* __restrict__ U1t,
                               float* __restrict__ U2t)
{
    int r = blockIdx.x;
    int c = threadIdx.x >> 5, l = threadIdx.x & 31;
    const float* row = lin1W + (size_t)r * Hh;
    const float* u1 = U1t + c * Hh;
    float acc = 0.f;
    for (int k = l; k < Hh; k += 32) acc += row[k] * u1[k];
    for (int o = 16; o > 0; o >>= 1) acc += __shfl_down_sync(0xffffffffu, acc, o);
    if (l == 0) U2t[c * Hh + r] = acc;
}
__global__ void fold_cvec_kernel(const float* __restrict__ lin0b,
                                 const float* __restrict__ lin1b,
                                 const float* __restrict__ clsW,
                                 const float* __restrict__ clsb,
                                 const float* __restrict__ U1t,
                                 float* __restrict__ cvec)
{
    int c = threadIdx.x >> 5, l = threadIdx.x & 31;
    float acc = 0.f;
    for (int k = l; k < Hh; k += 32)
        acc += lin0b[k] * clsW[k * NCLS + c] + lin1b[k] * U1t[c * Hh + k];
    for (int o = 16; o > 0; o >>= 1) acc += __shfl_down_sync(0xffffffffu, acc, o);
    if (l == 0) cvec[c] = acc + clsb[c];
}

// =================== small kernels ===================
__device__ __forceinline__ float eluf(float x) { return x > 0.f ? x : expf(x) - 1.0f; }

__global__ void mean_row0_kernel(const bf16* __restrict__ X, bf16* __restrict__ h1)
{
    int b = blockIdx.y;
    int c = blockIdx.x * 256 + threadIdx.x;
    const bf16* p = X + (size_t)b * Nn * Hh + c;
    float s = 0.f;
    for (int n = 0; n < Nn; n++) s += __bfloat162float(p[(size_t)n * Hh]);
    h1[(size_t)b * Nn * Hh + c] = __float2bfloat16_rn(eluf(s * (1.0f / Nn)));
}

__global__ void att1_tile_kernel(const bf16* __restrict__ Wh,
                                 const float* __restrict__ gat_a1,
                                 const float* __restrict__ gat_a2,
                                 bf16* __restrict__ h1)
{
    __shared__ float sW[55][128];
    __shared__ float sc1[55], sc2[55];
    __shared__ float sw[32][24];
    int b = blockIdx.z, h = blockIdx.y, it = blockIdx.x;
    int i0 = it * 32;
    int jlo0 = i0 - 23; if (jlo0 < 0) jlo0 = 0;
    int nrows = (i0 + 31) - jlo0 + 1;          // <= 55
    int tid = threadIdx.x;
    int warp = tid >> 5, lane = tid & 31;
    const bf16* base = Wh + (size_t)b * Nn * Hh + h * NHID;
    for (int rr = 0; rr < nrows; rr++)
        sW[rr][tid] = __bfloat162float(base[(size_t)(jlo0 + rr) * Hh + tid]);
    __syncthreads();
    {
        float a1v[4], a2v[4];
#pragma unroll
        for (int t = 0; t < 4; t++) {
            a1v[t] = gat_a1[h * NHID + lane + 32 * t];
            a2v[t] = gat_a2[h * NHID + lane + 32 * t];
        }
        for (int rr = warp; rr < nrows; rr += 4) {
            float d1 = 0.f, d2 = 0.f;
#pragma unroll
            for (int t = 0; t < 4; t++) {
                float v = sW[rr][lane + 32 * t];
                d1 += v * a1v[t];
                d2 += v * a2v[t];
            }
            for (int o = 16; o > 0; o >>= 1) {
                d1 += __shfl_down_sync(0xffffffffu, d1, o);
                d2 += __shfl_down_sync(0xffffffffu, d2, o);
            }
            if (lane == 0) { sc1[rr] = d1; sc2[rr] = d2; }
        }
    }
    __syncthreads();
    if (tid < 32) {
        int i = i0 + tid;
        if (i > 0) {
            int jl = i - 23; if (jl < 0) jl = 0;
            int L = i - jl;
            float si = sc1[i - jlo0];
            float mx = -1e30f;
            for (int t = 0; t < L; t++) {
                float v = si + sc2[jl + t - jlo0];
                v = v > 0.f ? v : ALPHA_LRELU * v;
                sw[tid][t] = v; mx = fmaxf(mx, v);
            }
            float ssum = 0.f;
            for (int t = 0; t < L; t++) { float ex = expf(sw[tid][t] - mx); sw[tid][t] = ex; ssum += ex; }
            float inv = 1.0f / ssum;
            for (int t = 0; t < L; t++) sw[tid][t] *= inv;
        }
    }
    __syncthreads();
    for (int il = 0; il < 32; il++) {
        int i = i0 + il;
        if (i == 0) continue;
        int jl = i - 23; if (jl < 0) jl = 0;
        int L = i - jl, roff = jl - jlo0;
        float acc = 0.f;
        for (int t = 0; t < L; t++) acc += sw[il][t] * sW[roff + t][tid];
        h1[((size_t)b * Nn + i) * Hh + h * NHID + tid] = __float2bfloat16_rn(eluf(acc));
    }
}

__global__ void out_scores_kernel(const bf16* __restrict__ Wh2,
                                  const float* __restrict__ a1,
                                  const float* __restrict__ a2,
                                  float* __restrict__ s1, float* __restrict__ s2)
{
    int n = blockIdx.x;
    int tid = threadIdx.x;
    float x1 = 0.f, x2 = 0.f;
    const bf16* x = Wh2 + (size_t)n * Hh;
    for (int c = tid; c < Hh; c += 256) {
        float v = __bfloat162float(x[c]);
        x1 += v * a1[c]; x2 += v * a2[c];
    }
    __shared__ float sh1[8], sh2[8];
    for (int o = 16; o > 0; o >>= 1) {
        x1 += __shfl_down_sync(0xffffffffu, x1, o);
        x2 += __shfl_down_sync(0xffffffffu, x2, o);
    }
    if ((tid & 31) == 0) { sh1[tid >> 5] = x1; sh2[tid >> 5] = x2; }
    __syncthreads();
    if (tid == 0) {
        float t1 = 0.f, t2 = 0.f;
        for (int k = 0; k < 8; k++) { t1 += sh1[k]; t2 += sh2[k]; }
        s1[n] = t1; s2[n] = t2;
    }
}

__global__ void att2_tile_kernel(const bf16* __restrict__ Wh2,
                                 const float* __restrict__ s1,
                                 const float* __restrict__ s2,
                                 bf16* __restrict__ out)
{
    __shared__ float sW[54][128];
    __shared__ float sw[32][24];
    int b = blockIdx.z, ct = blockIdx.y, it = blockIdx.x;
    int i0 = it * 32, c0 = ct * 128;
    int jlo0 = i0 - 23; if (jlo0 < 0) jlo0 = 0;
    int nrows = (i0 + 30) - jlo0 + 1;
    int tid = threadIdx.x;
    const bf16* base = Wh2 + (size_t)b * Nn * Hh + c0;
    for (int rr = 0; rr < nrows; rr++)
        sW[rr][tid] = __bfloat162float(base[(size_t)(jlo0 + rr) * Hh + tid]);
    if (tid < 32) {
        int i = i0 + tid;
        if (i > 0) {
            int jl = i - 23; if (jl < 0) jl = 0;
            int L = i - jl;
            float si = s1[(size_t)b * Nn + i];
            float mx = -1e30f;
            for (int t = 0; t < L; t++) {
                float v = si + s2[(size_t)b * Nn + jl + t];
                v = v > 0.f ? v : ALPHA_LRELU * v;
                sw[tid][t] = v; mx = fmaxf(mx, v);
            }
            float ssum = 0.f;
            for (int t = 0; t < L; t++) { float ex = expf(sw[tid][t] - mx); sw[tid][t] = ex; ssum += ex; }
            float inv = 1.0f / ssum;
            for (int t = 0; t < L; t++) sw[tid][t] *= inv;
        }
    }
    __syncthreads();
    for (int il = 0; il < 32; il++) {
        int i = i0 + il;
        if (i == 0) continue;
        int jl = i - 23; if (jl < 0) jl = 0;
        int L = i - jl, roff = jl - jlo0;
        float acc = 0.f;
        for (int t = 0; t < L; t++) acc += sw[il][t] * sW[roff + t][tid];
        out[((size_t)b * Nn + i) * Hh + c0 + tid] = __float2bfloat16_rn(eluf(acc));
    }
}

__global__ void gat_logits_kernel(const bf16* __restrict__ fea_cls,
                                  const bf16* __restrict__ h2,
                                  const float* __restrict__ U0t,
                                  const float* __restrict__ U2t,
                                  const float* __restrict__ cvec,
                                  float* __restrict__ out)
{
    int n = blockIdx.x;
    int i = n & (Nn - 1);
    int c = threadIdx.x >> 5, l = threadIdx.x & 31;
    const bf16* frow = fea_cls + (size_t)n * Hh;
    const bf16* hrow = (i == 0) ? frow : h2 + (size_t)n * Hh;
    const float* u0 = U0t + c * Hh;
    const float* u2 = U2t + c * Hh;
    float acc = 0.f;
    for (int k = l; k < Hh; k += 32)
        acc += __bfloat162float(frow[k]) * u0[k] + __bfloat162float(hrow[k]) * u2[k];
    for (int o = 16; o > 0; o >>= 1) acc += __shfl_down_sync(0xffffffffu, acc, o);
    __shared__ float sh[NCLS];
    if (l == 0) sh[c] = acc + cvec[c];
    __syncthreads();
    if (threadIdx.x == 0) {
        float mx = sh[0];
        for (int k = 1; k < NCLS; k++) mx = fmaxf(mx, sh[k]);
        float e[NCLS], s = 0.f;
        for (int k = 0; k < NCLS; k++) { e[k] = expf(sh[k] - mx); s += e[k]; }
        float inv = 1.0f / s;
        for (int k = 0; k < NCLS; k++) out[n * NCLS + k] = e[k] * inv;
    }
}

__global__ void cls_softmax_kernel(const bf16* __restrict__ X,
                                   const float* __restrict__ W,
                                   const float* __restrict__ bcls,
                                   float* __restrict__ out)
{
    int n = blockIdx.x;
    int wid = threadIdx.x >> 5, l = threadIdx.x & 31;
    __shared__ float sh[NCLS];
    const bf16* x = X + (size_t)n * Hh;
    float acc = 0.f;
    for (int t = l; t < Hh; t += 32) acc += __bfloat162float(x[t]) * W[t * NCLS + wid];
    for (int o = 16; o > 0; o >>= 1) acc += __shfl_down_sync(0xffffffffu, acc, o);
    if (l == 0) sh[wid] = acc + bcls[wid];
    __syncthreads();
    if (threadIdx.x == 0) {
        float mx = sh[0];
        for (int k = 1; k < NCLS; k++) mx = fmaxf(mx, sh[k]);
        float e[NCLS], s = 0.f;
        for (int k = 0; k < NCLS; k++) { e[k] = expf(sh[k] - mx); s += e[k]; }
        float inv = 1.0f / s;
        for (int k = 0; k < NCLS; k++) out[n * NCLS + k] = e[k] * inv;
    }
}

__global__ void hmm_kernel(const float* __restrict__ Bprob,
                           const float* __restrict__ hmmA,
                           float* __restrict__ out)
{
    __shared__ float sAT[NCLS * NCLS];
    int tid = threadIdx.x;
    if (tid < NCLS * NCLS) sAT[tid] = hmmA[(tid % NCLS) * NCLS + (tid / NCLS)];
    __syncthreads();
    int gidx = blockIdx.x * 128 + tid;
    int b = gidx >> 8, i = gidx & 255;
    const float* Bp = Bprob + (size_t)b * Nn * NCLS;
    int t0 = i - (BAND - 1); if (t0 < 0) t0 = 0;
    float p[NCLS]; float s = 0.f;
#pragma unroll
    for (int r = 0; r < NCLS; r++) { p[r] = Bp[t0 * NCLS + r]; s += p[r]; }
    float inv = 1.0f / s;
#pragma unroll
    for (int r = 0; r < NCLS; r++) p[r] *= inv;
    for (int t = t0 + 1; t <= i; t++) {
        float q[NCLS]; s = 0.f;
#pragma unroll
        for (int r = 0; r < NCLS; r++) {
            float a = 0.f;
#pragma unroll
            for (int c = 0; c < NCLS; c++) a += sAT[r * NCLS + c] * p[c];
            a *= Bp[t * NCLS + r];
            q[r] = a; s += a;
        }
        inv = 1.0f / s;
#pragma unroll
        for (int r = 0; r < NCLS; r++) p[r] = q[r] * inv;
    }
#pragma unroll
    for (int r = 0; r < NCLS; r++) out[gidx * NCLS + r] = p[r];
}

__global__ void final_kernel(const float* __restrict__ log_gat,
                             const float* __restrict__ log_hmm,
                             const int* __restrict__ labels,
                             float* __restrict__ outLogits)
{
    int r = blockIdx.x * 256 + threadIdx.x;
    float lg[NCLS];
#pragma unroll
    for (int k = 0; k < NCLS; k++) {
        lg[k] = logf(0.5f * (log_gat[r * NCLS + k] + log_hmm[r * NCLS + k]));
        outLogits[r * NCLS + k] = lg[k];
    }
    int lab = labels[r];
    float picked = (lab >= 0) ? lg[lab] : 0.f;
    for (int o = 16; o > 0; o >>= 1) picked += __shfl_down_sync(0xffffffffu, picked, o);
    __shared__ float sh[8];
    if ((threadIdx.x & 31) == 0) sh[threadIdx.x >> 5] = picked;
    __syncthreads();
    if (threadIdx.x == 0) {
        float s = 0.f;
        for (int k = 0; k < 8; k++) s += sh[k];
        g_blocksums[blockIdx.x] = s;
    }
}

__global__ void finalize_kernel(float* d_out, int has_loss)
{
    if (has_loss) {
        float s = 0.f;
        for (int k = 0; k < 32; k++) s += g_blocksums[k];
        d_out[0] = -s / (float)ROWS;
    }
}

// ---------------- host launch ----------------
template <typename T>
static T* sym(const void* symbol)
{
    void* p = nullptr;
    cudaGetSymbolAddress(&p, symbol);
    return (T*)p;
}

extern "C" void kernel_launch(void* const* d_in, const int* in_sizes, int n_in,
                              void* d_out, int out_size)
{
    (void)in_sizes; (void)n_in;
    const float* hidden_cls = (const float*)d_in[0];
    const float* hidden_emo = (const float*)d_in[1];
    const int*   labels     = (const int*)d_in[3];
    const float* pooler_W   = (const float*)d_in[4];
    const float* pooler_b   = (const float*)d_in[5];
    const float* gat_W      = (const float*)d_in[6];
    const float* gat_a1     = (const float*)d_in[7];
    const float* gat_a2     = (const float*)d_in[8];
    const float* out_W      = (const float*)d_in[9];
    const float* out_a1     = (const float*)d_in[10];
    const float* out_a2     = (const float*)d_in[11];
    const float* lin1_W     = (const float*)d_in[12];
    const float* lin1_b     = (const float*)d_in[13];
    const float* lin0_W     = (const float*)d_in[14];
    const float* lin0_b     = (const float*)d_in[15];
    const float* cls_W      = (const float*)d_in[16];
    const float* cls_b      = (const float*)d_in[17];
    const float* hmm_A      = (const float*)d_in[18];

    float* s1b     = sym<float>(g_s1b);
    float* s2b     = sym<float>(g_s2b);
    float* loggat  = sym<float>(g_loggat);
    float* Bprob   = sym<float>(g_Bprob);
    float* loghmm  = sym<float>(g_loghmm);
    bf16* hidcbf   = sym<bf16>(g_hid_cls_bf);
    bf16* hidebf   = sym<bf16>(g_hid_emo_bf);
    bf16* feacbf   = sym<bf16>(g_fea_cls_bf);
    bf16* feaebf   = sym<bf16>(g_fea_emo_bf);
    bf16* Whbf     = sym<bf16>(g_Wh_bf);
    bf16* Wh2bf    = sym<bf16>(g_Wh2_bf);
    bf16* h1bf     = sym<bf16>(g_h1_bf);
    bf16* h2bf     = sym<bf16>(g_h2_bf);
    bf16* poolWt   = sym<bf16>(g_poolWt);
    bf16* Wgt      = sym<bf16>(g_Wgt);
    bf16* outWt    = sym<bf16>(g_outWt);
    float* U0t     = sym<float>(g_U0t);
    float* U1t     = sym<float>(g_U1t);
    float* U2t     = sym<float>(g_U2t);
    float* cvec    = sym<float>(g_cvec);

    cudaFuncSetAttribute(mma_gemm, cudaFuncAttributeMaxDynamicSharedMemorySize, GEMM_SMEM);

    int has_loss = (out_size == ROWS * NCLS + 1) ? 1 : 0;
    float* outLogits = has_loss ? ((float*)d_out + 1) : (float*)d_out;

    // side streams + events (created once; captured work identical each call)
    static cudaStream_t sPrep = nullptr, sHmm = nullptr;
    static cudaEvent_t eFork = nullptr, eWgt = nullptr, eTab = nullptr,
                       ePool = nullptr, eHmm = nullptr;
    if (!sPrep) {
        cudaStreamCreateWithFlags(&sPrep, cudaStreamNonBlocking);
        cudaStreamCreateWithFlags(&sHmm, cudaStreamNonBlocking);
        cudaEventCreateWithFlags(&eFork, cudaEventDisableTiming);
        cudaEventCreateWithFlags(&eWgt, cudaEventDisableTiming);
        cudaEventCreateWithFlags(&eTab, cudaEventDisableTiming);
        cudaEventCreateWithFlags(&ePool, cudaEventDisableTiming);
        cudaEventCreateWithFlags(&eHmm, cudaEventDisableTiming);
    }
    cudaStream_t s0 = 0;
    dim3 tblk(32, 8);

    // ---- fork prep stream ----
    cudaEventRecord(eFork, s0);
    cudaStreamWaitEvent(sPrep, eFork, 0);
    repack_gatWt_kernel<<<(Hh * Hh) / 256, 256, 0, sPrep>>>(gat_W, Wgt);
    cudaEventRecord(eWgt, sPrep);
    transpose_bf_kernel<<<dim3(Hh / 32, Hh / 32), tblk, 0, sPrep>>>(out_W, outWt);
    fold_u_kernel<<<2 * Hh, 224, 0, sPrep>>>(lin0_W, cls_W, U0t, U1t);
    fold_u2_kernel<<<Hh, 224, 0, sPrep>>>(lin1_W, U1t, U2t);
    fold_cvec_kernel<<<1, 224, 0, sPrep>>>(lin0_b, lin1_b, cls_W, cls_b, U1t, cvec);
    cudaEventRecord(eTab, sPrep);

    // ---- main chain: pooler prereqs ----
    transpose_bf_kernel<<<dim3(Hh / 32, Hh / 32), tblk, 0, s0>>>(pooler_W, poolWt);
    cvt_bf_kernel<<<dim3(ROWS * Hh / 1024, 2), 256, 0, s0>>>(hidden_cls, hidden_emo,
                                                             hidcbf, hidebf);
    // poolers (tanh + bias), z-batched
    mma_gemm<<<dim3(Hh / BN, ROWS / BM, 2), 256, GEMM_SMEM, s0>>>(
        hidcbf, hidebf, feacbf, feaebf, poolWt, pooler_b, 1, Hh / BKg);
    cudaEventRecord(ePool, s0);

    // ---- fork HMM branch (needs only fea_emo) ----
    cudaStreamWaitEvent(sHmm, ePool, 0);
    cls_softmax_kernel<<<ROWS, 224, 0, sHmm>>>(feaebf, cls_W, cls_b, Bprob);
    hmm_kernel<<<ROWS / 128, 128, 0, sHmm>>>(Bprob, hmm_A, loghmm);
    cudaEventRecord(eHmm, sHmm);

    // ---- GAT chain on s0 ----
    cudaStreamWaitEvent(s0, eWgt, 0);
    mma_gemm<<<dim3(Hh / BN, ROWS / BM, 1), 256, GEMM_SMEM, s0>>>(
        feacbf, feacbf, Whbf, Whbf, Wgt, nullptr, 0, Hh / BKg);
    att1_tile_kernel<<<dim3(8, 8, Bc), 128, 0, s0>>>(Whbf, gat_a1, gat_a2, h1bf);
    mean_row0_kernel<<<dim3(Hh / 256, Bc), 256, 0, s0>>>(Whbf, h1bf);

    cudaStreamWaitEvent(s0, eTab, 0);      // outWt + U tables ready
    mma_gemm<<<dim3(Hh / BN, ROWS / BM, 1), 256, GEMM_SMEM, s0>>>(
        h1bf, h1bf, Wh2bf, Wh2bf, outWt, nullptr, 0, Hh / BKg);
    out_scores_kernel<<<ROWS, 256, 0, s0>>>(Wh2bf, out_a1, out_a2, s1b, s2b);
    att2_tile_kernel<<<dim3(8, 8, Bc), 128, 0, s0>>>(Wh2bf, s1b, s2b, h2bf);

    gat_logits_kernel<<<ROWS, 224, 0, s0>>>(feacbf, h2bf, U0t, U2t, cvec, loggat);

    // ---- join HMM branch, final ----
    cudaStreamWaitEvent(s0, eHmm, 0);
    final_kernel<<<ROWS / 256, 256, 0, s0>>>(loggat, loghmm, labels, outLogits);
    finalize_kernel<<<1, 1, 0, s0>>>((float*)d_out, has_loss);
}

// round 14
// speedup vs baseline: 1.2621x; 1.0343x over previous
#include <cuda_runtime.h>
#include <cuda_bf16.h>
#include <math.h>
#include <stdint.h>

// Problem constants
#define Bc   32
#define Nn   256
#define Hh   1024
#define HEADS 8
#define NHID 128
#define NCLS 7
#define BAND 24
#define ROWS (Bc*Nn)          // 8192
#define ALPHA_LRELU 0.2f

typedef __nv_bfloat16 bf16;

// ---------------- device scratch (no allocs allowed) ----------------
__device__ float g_s1b[ROWS];
__device__ float g_s2b[ROWS];
__device__ float g_loggat[ROWS*NCLS];
__device__ float g_Bprob[ROWS*NCLS];
__device__ float g_loghmm[ROWS*NCLS];
__device__ float g_blocksums[32];
// bf16 tensors
__device__ bf16 g_hid_cls_bf[ROWS*Hh];
__device__ bf16 g_hid_emo_bf[ROWS*Hh];
__device__ bf16 g_fea_cls_bf[ROWS*Hh];
__device__ bf16 g_fea_emo_bf[ROWS*Hh];
__device__ bf16 g_Wh_bf[ROWS*Hh];
__device__ bf16 g_Wh2_bf[ROWS*Hh];
__device__ bf16 g_h1_bf[ROWS*Hh];
__device__ bf16 g_h2_bf[ROWS*Hh];
__device__ bf16 g_poolWt[Hh*Hh];   // [N][K] k-major
__device__ bf16 g_Wgt[Hh*Hh];
__device__ bf16 g_outWt[Hh*Hh];
// folded classifier tables ([7][1024] row-major)
__device__ float g_U0t[NCLS*Hh];
__device__ float g_U1t[NCLS*Hh];
__device__ float g_U2t[NCLS*Hh];
__device__ float g_cvec[NCLS];

// =================== bf16 mma.sync GEMM (4-stage cp.async pipeline) ==========
#define BM 128
#define BN 128
#define BKg 32
#define GSTG 4
#define APITCH 40                             // halves per smem row (80 B)
#define STAGE_BYTES (2 * BM * APITCH * 2)     // A + B = 20480 B
#define GEMM_SMEM (GSTG * STAGE_BYTES)        // 81920 B

__device__ __forceinline__ uint32_t smem_u32(const void* p) {
    uint32_t a;
    asm("{ .reg .u64 t; cvta.to.shared.u64 t, %1; cvt.u32.u64 %0, t; }" : "=r"(a) : "l"(p));
    return a;
}
__device__ __forceinline__ void cp16(uint32_t s, const void* g) {
    asm volatile("cp.async.cg.shared.global [%0], [%1], 16;" :: "r"(s), "l"(g));
}
#define CP_COMMIT() asm volatile("cp.async.commit_group;" ::: "memory")
#define CP_WAIT2()  asm volatile("cp.async.wait_group 2;" ::: "memory")

__device__ __forceinline__ void ldsm4(uint32_t& r0, uint32_t& r1, uint32_t& r2, uint32_t& r3,
                                      uint32_t addr) {
    asm volatile("ldmatrix.sync.aligned.m8n8.x4.shared.b16 {%0,%1,%2,%3}, [%4];"
                 : "=r"(r0), "=r"(r1), "=r"(r2), "=r"(r3) : "r"(addr));
}
__device__ __forceinline__ void mma_bf16(float& d0, float& d1, float& d2, float& d3,
                                         uint32_t a0, uint32_t a1, uint32_t a2, uint32_t a3,
                                         uint32_t b0, uint32_t b1) {
    asm volatile("mma.sync.aligned.m16n8k16.row.col.f32.bf16.bf16.f32 "
                 "{%0,%1,%2,%3}, {%4,%5,%6,%7}, {%8,%9}, {%0,%1,%2,%3};"
                 : "+f"(d0), "+f"(d1), "+f"(d2), "+f"(d3)
                 : "r"(a0), "r"(a1), "r"(a2), "r"(a3), "r"(b0), "r"(b1));
}

__device__ __forceinline__ void gemm_load_stage(uint32_t sb, int stage, int tid,
                                                const bf16* Ag, const bf16* Bg) {
    uint32_t abase = sb + stage * STAGE_BYTES;
    uint32_t bbase = abase + BM * APITCH * 2;
#pragma unroll
    for (int i = 0; i < 2; i++) {
        int idx = tid + 256 * i;
        int r = idx >> 2;
        int q = idx & 3;
        cp16(abase + r * (APITCH * 2) + q * 16, Ag + (size_t)r * Hh + q * 8);
        cp16(bbase + r * (APITCH * 2) + q * 16, Bg + (size_t)r * Hh + q * 8);
    }
}

__global__ void __launch_bounds__(256, 2)
mma_gemm(const bf16* __restrict__ A, bf16* __restrict__ C,
         const bf16* __restrict__ Bt,
         const float* __restrict__ bias, int dotanh, int T)
{
    extern __shared__ char smem[];
    uint32_t sb = smem_u32(smem);
    const int tid = threadIdx.x;
    const int wid = tid >> 5, lane = tid & 31;
    const int wm = wid >> 2, wn = wid & 3;   // 2x4 warp grid, warp tile 64x32
    const int n0 = blockIdx.x * BN;
    const size_t m0 = (size_t)blockIdx.y * BM;

    float acc[4][4][4];
#pragma unroll
    for (int mi = 0; mi < 4; mi++)
#pragma unroll
        for (int ni = 0; ni < 4; ni++)
#pragma unroll
            for (int k = 0; k < 4; k++) acc[mi][ni][k] = 0.f;

    const bf16* Arow = A + m0 * Hh;
    const bf16* Brow = Bt + (size_t)n0 * Hh;

    gemm_load_stage(sb, 0, tid, Arow, Brow);
    CP_COMMIT();
    gemm_load_stage(sb, 1, tid, Arow + BKg, Brow + BKg);
    CP_COMMIT();
    gemm_load_stage(sb, 2, tid, Arow + 2 * BKg, Brow + 2 * BKg);
    CP_COMMIT();

    const int tl = lane >> 3;          // ldmatrix tile selector
    const int l7 = lane & 7;

    for (int t = 0; t < T; t++) {
        CP_WAIT2();
        __syncthreads();
        int nc = t + 3;
        if (nc < T)
            gemm_load_stage(sb, nc % GSTG, tid, Arow + nc * BKg, Brow + nc * BKg);
        CP_COMMIT();   // always commit to keep group counting sound

        uint32_t sA = sb + (t % GSTG) * STAGE_BYTES;
        uint32_t sB = sA + BM * APITCH * 2;
#pragma unroll
        for (int ks = 0; ks < 2; ks++) {
            uint32_t a[4][4];
#pragma unroll
            for (int mi = 0; mi < 4; mi++) {
                int row = wm * 64 + mi * 16 + (tl & 1) * 8 + l7;
                int col = ks * 16 + (tl >> 1) * 8;
                ldsm4(a[mi][0], a[mi][1], a[mi][2], a[mi][3],
                      sA + row * (APITCH * 2) + col * 2);
            }
            uint32_t bq[2][4];
#pragma unroll
            for (int nn = 0; nn < 2; nn++) {
                int row = wn * 32 + nn * 16 + (tl >> 1) * 8 + l7;
                int col = ks * 16 + (tl & 1) * 8;
                ldsm4(bq[nn][0], bq[nn][1], bq[nn][2], bq[nn][3],
                      sB + row * (APITCH * 2) + col * 2);
            }
#pragma unroll
            for (int mi = 0; mi < 4; mi++)
#pragma unroll
                for (int ni = 0; ni < 4; ni++)
                    mma_bf16(acc[mi][ni][0], acc[mi][ni][1], acc[mi][ni][2], acc[mi][ni][3],
                             a[mi][0], a[mi][1], a[mi][2], a[mi][3],
                             bq[ni >> 1][(ni & 1) * 2], bq[ni >> 1][(ni & 1) * 2 + 1]);
        }
    }

    const int lq = lane >> 2;
    const int lr = lane & 3;
#pragma unroll
    for (int mi = 0; mi < 4; mi++) {
        int row = (int)m0 + wm * 64 + mi * 16 + lq;
#pragma unroll
        for (int ni = 0; ni < 4; ni++) {
            int col = n0 + wn * 32 + ni * 8 + lr * 2;
            float b0 = 0.f, b1 = 0.f;
            if (bias) { b0 = bias[col]; b1 = bias[col + 1]; }
            float2 v0, v1;
            v0.x = acc[mi][ni][0] + b0; v0.y = acc[mi][ni][1] + b1;
            v1.x = acc[mi][ni][2] + b0; v1.y = acc[mi][ni][3] + b1;
            if (dotanh) {
                v0.x = tanhf(v0.x); v0.y = tanhf(v0.y);
                v1.x = tanhf(v1.x); v1.y = tanhf(v1.y);
            }
            __nv_bfloat162 w0, w1;
            w0.x = __float2bfloat16_rn(v0.x); w0.y = __float2bfloat16_rn(v0.y);
            w1.x = __float2bfloat16_rn(v1.x); w1.y = __float2bfloat16_rn(v1.y);
            *(__nv_bfloat162*)(C + (size_t)row * Hh + col) = w0;
            *(__nv_bfloat162*)(C + (size_t)(row + 8) * Hh + col) = w1;
        }
    }
}

// =================== weight prep / converts ===================
__global__ void transpose_bf_kernel(const float* __restrict__ in, bf16* __restrict__ out)
{
    __shared__ float tile[32][33];
    int k0 = blockIdx.y * 32, n0 = blockIdx.x * 32;
    int tx = threadIdx.x, ty = threadIdx.y;
    for (int r = ty; r < 32; r += 8) tile[r][tx] = in[(size_t)(k0 + r) * Hh + n0 + tx];
    __syncthreads();
    for (int r = ty; r < 32; r += 8)
        out[(size_t)(n0 + r) * Hh + k0 + tx] = __float2bfloat16_rn(tile[tx][r]);
}
__global__ void repack_gatWt_kernel(const float* __restrict__ gw, bf16* __restrict__ Wgt)
{
    int idx = blockIdx.x * 256 + threadIdx.x;
    int n = idx >> 10, f = idx & 1023;
    int h = n >> 7, d = n & 127;
    Wgt[idx] = __float2bfloat16_rn(gw[((size_t)(h << 10 | f)) * NHID + d]);
}
__global__ void cvt_bf_kernel(const float* __restrict__ a, bf16* __restrict__ oa)
{
    int idx = (blockIdx.x * 256 + threadIdx.x) * 4;
    float4 v = *(const float4*)(a + idx);
    __nv_bfloat162 w0, w1;
    w0.x = __float2bfloat16_rn(v.x); w0.y = __float2bfloat16_rn(v.y);
    w1.x = __float2bfloat16_rn(v.z); w1.y = __float2bfloat16_rn(v.w);
    *(__nv_bfloat162*)(oa + idx) = w0;
    *(__nv_bfloat162*)(oa + idx + 2) = w1;
}

__global__ void fold_u_kernel(const float* __restrict__ lin0W,
                              const float* __restrict__ clsW,
                              float* __restrict__ U0t, float* __restrict__ U1t)
{
    int r = blockIdx.x;
    int c = threadIdx.x >> 5, l = threadIdx.x & 31;
    const float* row = lin0W + (size_t)r * Hh;
    float acc = 0.f;
    for (int k = l; k < Hh; k += 32) acc += row[k] * clsW[k * NCLS + c];
    for (int o = 16; o > 0; o >>= 1) acc += __shfl_down_sync(0xffffffffu, acc, o);
    if (l == 0) {
        if (r < Hh) U0t[c * Hh + r] = acc;
        else        U1t[c * Hh + (r - Hh)] = acc;
    }
}
__global__ void fold_u2_kernel(const float* __restrict__ lin1W,
                               const float* __restrict__ U1t,
                               float* __restrict__ U2t)
{
    int r = blockIdx.x;
    int c = threadIdx.x >> 5, l = threadIdx.x & 31;
    const float* row = lin1W + (size_t)r * Hh;
    const float* u1 = U1t + c * Hh;
    float acc = 0.f;
    for (int k = l; k < Hh; k += 32) acc += row[k] * u1[k];
    for (int o = 16; o > 0; o >>= 1) acc += __shfl_down_sync(0xffffffffu, acc, o);
    if (l == 0) U2t[c * Hh + r] = acc;
}
__global__ void fold_cvec_kernel(const float* __restrict__ lin0b,
                                 const float* __restrict__ lin1b,
                                 const float* __restrict__ clsW,
                                 const float* __restrict__ clsb,
                                 const float* __restrict__ U1t,
                                 float* __restrict__ cvec)
{
    int c = threadIdx.x >> 5, l = threadIdx.x & 31;
    float acc = 0.f;
    for (int k = l; k < Hh; k += 32)
        acc += lin0b[k] * clsW[k * NCLS + c] + lin1b[k] * U1t[c * Hh + k];
    for (int o = 16; o > 0; o >>= 1) acc += __shfl_down_sync(0xffffffffu, acc, o);
    if (l == 0) cvec[c] = acc + clsb[c];
}

// =================== small kernels ===================
__device__ __forceinline__ float eluf(float x) { return x > 0.f ? x : expf(x) - 1.0f; }

__global__ void mean_row0_kernel(const bf16* __restrict__ X, bf16* __restrict__ h1)
{
    int b = blockIdx.y;
    int c = blockIdx.x * 256 + threadIdx.x;
    const bf16* p = X + (size_t)b * Nn * Hh + c;
    float s = 0.f;
    for (int n = 0; n < Nn; n++) s += __bfloat162float(p[(size_t)n * Hh]);
    h1[(size_t)b * Nn * Hh + c] = __float2bfloat16_rn(eluf(s * (1.0f / Nn)));
}

__global__ void att1_tile_kernel(const bf16* __restrict__ Wh,
                                 const float* __restrict__ gat_a1,
                                 const float* __restrict__ gat_a2,
                                 bf16* __restrict__ h1)
{
    __shared__ float sW[55][128];
    __shared__ float sc1[55], sc2[55];
    __shared__ float sw[32][24];
    int b = blockIdx.z, h = blockIdx.y, it = blockIdx.x;
    int i0 = it * 32;
    int jlo0 = i0 - 23; if (jlo0 < 0) jlo0 = 0;
    int nrows = (i0 + 31) - jlo0 + 1;          // <= 55
    int tid = threadIdx.x;
    int warp = tid >> 5, lane = tid & 31;
    const bf16* base = Wh + (size_t)b * Nn * Hh + h * NHID;
    for (int rr = 0; rr < nrows; rr++)
        sW[rr][tid] = __bfloat162float(base[(size_t)(jlo0 + rr) * Hh + tid]);
    __syncthreads();
    {
        float a1v[4], a2v[4];
#pragma unroll
        for (int t = 0; t < 4; t++) {
            a1v[t] = gat_a1[h * NHID + lane + 32 * t];
            a2v[t] = gat_a2[h * NHID + lane + 32 * t];
        }
        for (int rr = warp; rr < nrows; rr += 4) {
            float d1 = 0.f, d2 = 0.f;
#pragma unroll
            for (int t = 0; t < 4; t++) {
                float v = sW[rr][lane + 32 * t];
                d1 += v * a1v[t];
                d2 += v * a2v[t];
            }
            for (int o = 16; o > 0; o >>= 1) {
                d1 += __shfl_down_sync(0xffffffffu, d1, o);
                d2 += __shfl_down_sync(0xffffffffu, d2, o);
            }
            if (lane == 0) { sc1[rr] = d1; sc2[rr] = d2; }
        }
    }
    __syncthreads();
    if (tid < 32) {
        int i = i0 + tid;
        if (i > 0) {
            int jl = i - 23; if (jl < 0) jl = 0;
            int L = i - jl;
            float si = sc1[i - jlo0];
            float mx = -1e30f;
            for (int t = 0; t < L; t++) {
                float v = si + sc2[jl + t - jlo0];
                v = v > 0.f ? v : ALPHA_LRELU * v;
                sw[tid][t] = v; mx = fmaxf(mx, v);
            }
            float ssum = 0.f;
            for (int t = 0; t < L; t++) { float ex = expf(sw[tid][t] - mx); sw[tid][t] = ex; ssum += ex; }
            float inv = 1.0f / ssum;
            for (int t = 0; t < L; t++) sw[tid][t] *= inv;
        }
    }
    __syncthreads();
    for (int il = 0; il < 32; il++) {
        int i = i0 + il;
        if (i == 0) continue;
        int jl = i - 23; if (jl < 0) jl = 0;
        int L = i - jl, roff = jl - jlo0;
        float acc = 0.f;
        for (int t = 0; t < L; t++) acc += sw[il][t] * sW[roff + t][tid];
        h1[((size_t)b * Nn + i) * Hh + h * NHID + tid] = __float2bfloat16_rn(eluf(acc));
    }
}

__global__ void out_scores_kernel(const bf16* __restrict__ Wh2,
                                  const float* __restrict__ a1,
                                  const float* __restrict__ a2,
                                  float* __restrict__ s1, float* __restrict__ s2)
{
    int n = blockIdx.x;
    int tid = threadIdx.x;
    float x1 = 0.f, x2 = 0.f;
    const bf16* x = Wh2 + (size_t)n * Hh;
    for (int c = tid; c < Hh; c += 256) {
        float v = __bfloat162float(x[c]);
        x1 += v * a1[c]; x2 += v * a2[c];
    }
    __shared__ float sh1[8], sh2[8];
    for (int o = 16; o > 0; o >>= 1) {
        x1 += __shfl_down_sync(0xffffffffu, x1, o);
        x2 += __shfl_down_sync(0xffffffffu, x2, o);
    }
    if ((tid & 31) == 0) { sh1[tid >> 5] = x1; sh2[tid >> 5] = x2; }
    __syncthreads();
    if (tid == 0) {
        float t1 = 0.f, t2 = 0.f;
        for (int k = 0; k < 8; k++) { t1 += sh1[k]; t2 += sh2[k]; }
        s1[n] = t1; s2[n] = t2;
    }
}

__global__ void att2_tile_kernel(const bf16* __restrict__ Wh2,
                                 const float* __restrict__ s1,
                                 const float* __restrict__ s2,
                                 bf16* __restrict__ out)
{
    __shared__ float sW[54][128];
    __shared__ float sw[32][24];
    int b = blockIdx.z, ct = blockIdx.y, it = blockIdx.x;
    int i0 = it * 32, c0 = ct * 128;
    int jlo0 = i0 - 23; if (jlo0 < 0) jlo0 = 0;
    int nrows = (i0 + 30) - jlo0 + 1;
    int tid = threadIdx.x;
    const bf16* base = Wh2 + (size_t)b * Nn * Hh + c0;
    for (int rr = 0; rr < nrows; rr++)
        sW[rr][tid] = __bfloat162float(base[(size_t)(jlo0 + rr) * Hh + tid]);
    if (tid < 32) {
        int i = i0 + tid;
        if (i > 0) {
            int jl = i - 23; if (jl < 0) jl = 0;
            int L = i - jl;
            float si = s1[(size_t)b * Nn + i];
            float mx = -1e30f;
            for (int t = 0; t < L; t++) {
                float v = si + s2[(size_t)b * Nn + jl + t];
                v = v > 0.f ? v : ALPHA_LRELU * v;
                sw[tid][t] = v; mx = fmaxf(mx, v);
            }
            float ssum = 0.f;
            for (int t = 0; t < L; t++) { float ex = expf(sw[tid][t] - mx); sw[tid][t] = ex; ssum += ex; }
            float inv = 1.0f / ssum;
            for (int t = 0; t < L; t++) sw[tid][t] *= inv;
        }
    }
    __syncthreads();
    for (int il = 0; il < 32; il++) {
        int i = i0 + il;
        if (i == 0) continue;
        int jl = i - 23; if (jl < 0) jl = 0;
        int L = i - jl, roff = jl - jlo0;
        float acc = 0.f;
        for (int t = 0; t < L; t++) acc += sw[il][t] * sW[roff + t][tid];
        out[((size_t)b * Nn + i) * Hh + c0 + tid] = __float2bfloat16_rn(eluf(acc));
    }
}

__global__ void gat_logits_kernel(const bf16* __restrict__ fea_cls,
                                  const bf16* __restrict__ h2,
                                  const float* __restrict__ U0t,
                                  const float* __restrict__ U2t,
                                  const float* __restrict__ cvec,
                                  float* __restrict__ out)
{
    int n = blockIdx.x;
    int i = n & (Nn - 1);
    int c = threadIdx.x >> 5, l = threadIdx.x & 31;
    const bf16* frow = fea_cls + (size_t)n * Hh;
    const bf16* hrow = (i == 0) ? frow : h2 + (size_t)n * Hh;
    const float* u0 = U0t + c * Hh;
    const float* u2 = U2t + c * Hh;
    float acc = 0.f;
    for (int k = l; k < Hh; k += 32)
        acc += __bfloat162float(frow[k]) * u0[k] + __bfloat162float(hrow[k]) * u2[k];
    for (int o = 16; o > 0; o >>= 1) acc += __shfl_down_sync(0xffffffffu, acc, o);
    __shared__ float sh[NCLS];
    if (l == 0) sh[c] = acc + cvec[c];
    __syncthreads();
    if (threadIdx.x == 0) {
        float mx = sh[0];
        for (int k = 1; k < NCLS; k++) mx = fmaxf(mx, sh[k]);
        float e[NCLS], s = 0.f;
        for (int k = 0; k < NCLS; k++) { e[k] = expf(sh[k] - mx); s += e[k]; }
        float inv = 1.0f / s;
        for (int k = 0; k < NCLS; k++) out[n * NCLS + k] = e[k] * inv;
    }
}

__global__ void cls_softmax_kernel(const bf16* __restrict__ X,
                                   const float* __restrict__ W,
                                   const float* __restrict__ bcls,
                                   float* __restrict__ out)
{
    int n = blockIdx.x;
    int wid = threadIdx.x >> 5, l = threadIdx.x & 31;
    __shared__ float sh[NCLS];
    const bf16* x = X + (size_t)n * Hh;
    float acc = 0.f;
    for (int t = l; t < Hh; t += 32) acc += __bfloat162float(x[t]) * W[t * NCLS + wid];
    for (int o = 16; o > 0; o >>= 1) acc += __shfl_down_sync(0xffffffffu, acc, o);
    if (l == 0) sh[wid] = acc + bcls[wid];
    __syncthreads();
    if (threadIdx.x == 0) {
        float mx = sh[0];
        for (int k = 1; k < NCLS; k++) mx = fmaxf(mx, sh[k]);
        float e[NCLS], s = 0.f;
        for (int k = 0; k < NCLS; k++) { e[k] = expf(sh[k] - mx); s += e[k]; }
        float inv = 1.0f / s;
        for (int k = 0; k < NCLS; k++) out[n * NCLS + k] = e[k] * inv;
    }
}

__global__ void hmm_kernel(const float* __restrict__ Bprob,
                           const float* __restrict__ hmmA,
                           float* __restrict__ out)
{
    __shared__ float sAT[NCLS * NCLS];
    int tid = threadIdx.x;
    if (tid < NCLS * NCLS) sAT[tid] = hmmA[(tid % NCLS) * NCLS + (tid / NCLS)];
    __syncthreads();
    int gidx = blockIdx.x * 128 + tid;
    int b = gidx >> 8, i = gidx & 255;
    const float* Bp = Bprob + (size_t)b * Nn * NCLS;
    int t0 = i - (BAND - 1); if (t0 < 0) t0 = 0;
    float p[NCLS]; float s = 0.f;
#pragma unroll
    for (int r = 0; r < NCLS; r++) { p[r] = Bp[t0 * NCLS + r]; s += p[r]; }
    float inv = 1.0f / s;
#pragma unroll
    for (int r = 0; r < NCLS; r++) p[r] *= inv;
    for (int t = t0 + 1; t <= i; t++) {
        float q[NCLS]; s = 0.f;
#pragma unroll
        for (int r = 0; r < NCLS; r++) {
            float a = 0.f;
#pragma unroll
            for (int c = 0; c < NCLS; c++) a += sAT[r * NCLS + c] * p[c];
            a *= Bp[t * NCLS + r];
            q[r] = a; s += a;
        }
        inv = 1.0f / s;
#pragma unroll
        for (int r = 0; r < NCLS; r++) p[r] = q[r] * inv;
    }
#pragma unroll
    for (int r = 0; r < NCLS; r++) out[gidx * NCLS + r] = p[r];
}

__global__ void final_kernel(const float* __restrict__ log_gat,
                             const float* __restrict__ log_hmm,
                             const int* __restrict__ labels,
                             float* __restrict__ outLogits)
{
    int r = blockIdx.x * 256 + threadIdx.x;
    float lg[NCLS];
#pragma unroll
    for (int k = 0; k < NCLS; k++) {
        lg[k] = logf(0.5f * (log_gat[r * NCLS + k] + log_hmm[r * NCLS + k]));
        outLogits[r * NCLS + k] = lg[k];
    }
    int lab = labels[r];
    float picked = (lab >= 0) ? lg[lab] : 0.f;
    for (int o = 16; o > 0; o >>= 1) picked += __shfl_down_sync(0xffffffffu, picked, o);
    __shared__ float sh[8];
    if ((threadIdx.x & 31) == 0) sh[threadIdx.x >> 5] = picked;
    __syncthreads();
    if (threadIdx.x == 0) {
        float s = 0.f;
        for (int k = 0; k < 8; k++) s += sh[k];
        g_blocksums[blockIdx.x] = s;
    }
}

__global__ void finalize_kernel(float* d_out, int has_loss)
{
    if (has_loss) {
        float s = 0.f;
        for (int k = 0; k < 32; k++) s += g_blocksums[k];
        d_out[0] = -s / (float)ROWS;
    }
}

// ---------------- host launch ----------------
template <typename T>
static T* sym(const void* symbol)
{
    void* p = nullptr;
    cudaGetSymbolAddress(&p, symbol);
    return (T*)p;
}

extern "C" void kernel_launch(void* const* d_in, const int* in_sizes, int n_in,
                              void* d_out, int out_size)
{
    (void)in_sizes; (void)n_in;
    const float* hidden_cls = (const float*)d_in[0];
    const float* hidden_emo = (const float*)d_in[1];
    const int*   labels     = (const int*)d_in[3];
    const float* pooler_W   = (const float*)d_in[4];
    const float* pooler_b   = (const float*)d_in[5];
    const float* gat_W      = (const float*)d_in[6];
    const float* gat_a1     = (const float*)d_in[7];
    const float* gat_a2     = (const float*)d_in[8];
    const float* out_W      = (const float*)d_in[9];
    const float* out_a1     = (const float*)d_in[10];
    const float* out_a2     = (const float*)d_in[11];
    const float* lin1_W     = (const float*)d_in[12];
    const float* lin1_b     = (const float*)d_in[13];
    const float* lin0_W     = (const float*)d_in[14];
    const float* lin0_b     = (const float*)d_in[15];
    const float* cls_W      = (const float*)d_in[16];
    const float* cls_b      = (const float*)d_in[17];
    const float* hmm_A      = (const float*)d_in[18];

    float* s1b     = sym<float>(g_s1b);
    float* s2b     = sym<float>(g_s2b);
    float* loggat  = sym<float>(g_loggat);
    float* Bprob   = sym<float>(g_Bprob);
    float* loghmm  = sym<float>(g_loghmm);
    bf16* hidcbf   = sym<bf16>(g_hid_cls_bf);
    bf16* hidebf   = sym<bf16>(g_hid_emo_bf);
    bf16* feacbf   = sym<bf16>(g_fea_cls_bf);
    bf16* feaebf   = sym<bf16>(g_fea_emo_bf);
    bf16* Whbf     = sym<bf16>(g_Wh_bf);
    bf16* Wh2bf    = sym<bf16>(g_Wh2_bf);
    bf16* h1bf     = sym<bf16>(g_h1_bf);
    bf16* h2bf     = sym<bf16>(g_h2_bf);
    bf16* poolWt   = sym<bf16>(g_poolWt);
    bf16* Wgt      = sym<bf16>(g_Wgt);
    bf16* outWt    = sym<bf16>(g_outWt);
    float* U0t     = sym<float>(g_U0t);
    float* U1t     = sym<float>(g_U1t);
    float* U2t     = sym<float>(g_U2t);
    float* cvec    = sym<float>(g_cvec);

    cudaFuncSetAttribute(mma_gemm, cudaFuncAttributeMaxDynamicSharedMemorySize, GEMM_SMEM);

    int has_loss = (out_size == ROWS * NCLS + 1) ? 1 : 0;
    float* outLogits = has_loss ? ((float*)d_out + 1) : (float*)d_out;

    // side streams + events (created once; captured work identical each call)
    static cudaStream_t sPrep = nullptr, sHmm = nullptr;
    static cudaEvent_t eFork = nullptr, eWgt = nullptr, eTab = nullptr,
                       eTrans = nullptr, eHmm = nullptr;
    if (!sPrep) {
        cudaStreamCreateWithFlags(&sPrep, cudaStreamNonBlocking);
        cudaStreamCreateWithFlags(&sHmm, cudaStreamNonBlocking);
        cudaEventCreateWithFlags(&eFork, cudaEventDisableTiming);
        cudaEventCreateWithFlags(&eWgt, cudaEventDisableTiming);
        cudaEventCreateWithFlags(&eTab, cudaEventDisableTiming);
        cudaEventCreateWithFlags(&eTrans, cudaEventDisableTiming);
        cudaEventCreateWithFlags(&eHmm, cudaEventDisableTiming);
    }
    cudaStream_t s0 = 0;
    dim3 tblk(32, 8);

    // ---- fork prep stream ----
    cudaEventRecord(eFork, s0);
    cudaStreamWaitEvent(sPrep, eFork, 0);
    repack_gatWt_kernel<<<(Hh * Hh) / 256, 256, 0, sPrep>>>(gat_W, Wgt);
    cudaEventRecord(eWgt, sPrep);
    transpose_bf_kernel<<<dim3(Hh / 32, Hh / 32), tblk, 0, sPrep>>>(out_W, outWt);
    fold_u_kernel<<<2 * Hh, 224, 0, sPrep>>>(lin0_W, cls_W, U0t, U1t);
    fold_u2_kernel<<<Hh, 224, 0, sPrep>>>(lin1_W, U1t, U2t);
    fold_cvec_kernel<<<1, 224, 0, sPrep>>>(lin0_b, lin1_b, cls_W, cls_b, U1t, cvec);
    cudaEventRecord(eTab, sPrep);

    // ---- main chain: cls-pooler prereqs ----
    transpose_bf_kernel<<<dim3(Hh / 32, Hh / 32), tblk, 0, s0>>>(pooler_W, poolWt);
    cudaEventRecord(eTrans, s0);       // poolWt ready -> emo branch may start
    cvt_bf_kernel<<<ROWS * Hh / 1024, 256, 0, s0>>>(hidden_cls, hidcbf);
    mma_gemm<<<dim3(Hh / BN, ROWS / BM), 256, GEMM_SMEM, s0>>>(
        hidcbf, feacbf, poolWt, pooler_b, 1, Hh / BKg);

    // ---- emo/HMM branch on sHmm (off the critical path) ----
    cudaStreamWaitEvent(sHmm, eTrans, 0);
    cvt_bf_kernel<<<ROWS * Hh / 1024, 256, 0, sHmm>>>(hidden_emo, hidebf);
    mma_gemm<<<dim3(Hh / BN, ROWS / BM), 256, GEMM_SMEM, sHmm>>>(
        hidebf, feaebf, poolWt, pooler_b, 1, Hh / BKg);
    cls_softmax_kernel<<<ROWS, 224, 0, sHmm>>>(feaebf, cls_W, cls_b, Bprob);
    hmm_kernel<<<ROWS / 128, 128, 0, sHmm>>>(Bprob, hmm_A, loghmm);
    cudaEventRecord(eHmm, sHmm);

    // ---- GAT chain on s0 ----
    cudaStreamWaitEvent(s0, eWgt, 0);
    mma_gemm<<<dim3(Hh / BN, ROWS / BM), 256, GEMM_SMEM, s0>>>(
        feacbf, Whbf, Wgt, nullptr, 0, Hh / BKg);
    att1_tile_kernel<<<dim3(8, 8, Bc), 128, 0, s0>>>(Whbf, gat_a1, gat_a2, h1bf);
    mean_row0_kernel<<<dim3(Hh / 256, Bc), 256, 0, s0>>>(Whbf, h1bf);

    cudaStreamWaitEvent(s0, eTab, 0);      // outWt + U tables ready
    mma_gemm<<<dim3(Hh / BN, ROWS / BM), 256, GEMM_SMEM, s0>>>(
        h1bf, Wh2bf, outWt, nullptr, 0, Hh / BKg);
    out_scores_kernel<<<ROWS, 256, 0, s0>>>(Wh2bf, out_a1, out_a2, s1b, s2b);
    att2_tile_kernel<<<dim3(8, 8, Bc), 128, 0, s0>>>(Wh2bf, s1b, s2b, h2bf);

    gat_logits_kernel<<<ROWS, 224, 0, s0>>>(feacbf, h2bf, U0t, U2t, cvec, loggat);

    // ---- join HMM branch, final ----
    cudaStreamWaitEvent(s0, eHmm, 0);
    final_kernel<<<ROWS / 256, 256, 0, s0>>>(loggat, loghmm, labels, outLogits);
    finalize_kernel<<<1, 1, 0, s0>>>((float*)d_out, has_loss);
}

// round 15
// speedup vs baseline: 1.3068x; 1.0354x over previous
#include <cuda_runtime.h>
#include <cuda_bf16.h>
#include <math.h>
#include <stdint.h>

// Problem constants
#define Bc   32
#define Nn   256
#define Hh   1024
#define HEADS 8
#define NHID 128
#define NCLS 7
#define BAND 24
#define ROWS (Bc*Nn)          // 8192
#define ALPHA_LRELU 0.2f

typedef __nv_bfloat16 bf16;

// ---------------- device scratch (no allocs allowed) ----------------
__device__ float g_s1b[ROWS];
__device__ float g_s2b[ROWS];
__device__ float g_loggat[ROWS*NCLS];
__device__ float g_Bprob[ROWS*NCLS];
__device__ float g_loghmm[ROWS*NCLS];
__device__ float g_u0part[ROWS*NCLS];
__device__ float g_blocksums[32];
// bf16 tensors
__device__ bf16 g_hid_cls_bf[ROWS*Hh];
__device__ bf16 g_hid_emo_bf[ROWS*Hh];
__device__ bf16 g_fea_cls_bf[ROWS*Hh];
__device__ bf16 g_fea_emo_bf[ROWS*Hh];
__device__ bf16 g_Wh_bf[ROWS*Hh];
__device__ bf16 g_Wh2_bf[ROWS*Hh];
__device__ bf16 g_h1_bf[ROWS*Hh];
__device__ bf16 g_h2_bf[ROWS*Hh];
__device__ bf16 g_poolWt[Hh*Hh];   // [N][K] k-major
__device__ bf16 g_Wgt[Hh*Hh];
__device__ bf16 g_outWt[Hh*Hh];
// folded classifier tables ([7][1024] row-major)
__device__ float g_U0t[NCLS*Hh];
__device__ float g_U1t[NCLS*Hh];
__device__ float g_U2t[NCLS*Hh];
__device__ float g_cvec[NCLS];

// =================== bf16 mma.sync GEMM (4-stage cp.async pipeline) ==========
#define BM 128
#define BN 128
#define BKg 32
#define GSTG 4
#define APITCH 40                             // halves per smem row (80 B)
#define STAGE_BYTES (2 * BM * APITCH * 2)     // A + B = 20480 B
#define GEMM_SMEM (GSTG * STAGE_BYTES)        // 81920 B

__device__ __forceinline__ uint32_t smem_u32(const void* p) {
    uint32_t a;
    asm("{ .reg .u64 t; cvta.to.shared.u64 t, %1; cvt.u32.u64 %0, t; }" : "=r"(a) : "l"(p));
    return a;
}
__device__ __forceinline__ void cp16(uint32_t s, const void* g) {
    asm volatile("cp.async.cg.shared.global [%0], [%1], 16;" :: "r"(s), "l"(g));
}
#define CP_COMMIT() asm volatile("cp.async.commit_group;" ::: "memory")
#define CP_WAIT2()  asm volatile("cp.async.wait_group 2;" ::: "memory")

__device__ __forceinline__ void ldsm4(uint32_t& r0, uint32_t& r1, uint32_t& r2, uint32_t& r3,
                                      uint32_t addr) {
    asm volatile("ldmatrix.sync.aligned.m8n8.x4.shared.b16 {%0,%1,%2,%3}, [%4];"
                 : "=r"(r0), "=r"(r1), "=r"(r2), "=r"(r3) : "r"(addr));
}
__device__ __forceinline__ void mma_bf16(float& d0, float& d1, float& d2, float& d3,
                                         uint32_t a0, uint32_t a1, uint32_t a2, uint32_t a3,
                                         uint32_t b0, uint32_t b1) {
    asm volatile("mma.sync.aligned.m16n8k16.row.col.f32.bf16.bf16.f32 "
                 "{%0,%1,%2,%3}, {%4,%5,%6,%7}, {%8,%9}, {%0,%1,%2,%3};"
                 : "+f"(d0), "+f"(d1), "+f"(d2), "+f"(d3)
                 : "r"(a0), "r"(a1), "r"(a2), "r"(a3), "r"(b0), "r"(b1));
}

__device__ __forceinline__ void gemm_load_stage(uint32_t sb, int stage, int tid,
                                                const bf16* Ag, const bf16* Bg) {
    uint32_t abase = sb + stage * STAGE_BYTES;
    uint32_t bbase = abase + BM * APITCH * 2;
#pragma unroll
    for (int i = 0; i < 2; i++) {
        int idx = tid + 256 * i;
        int r = idx >> 2;
        int q = idx & 3;
        cp16(abase + r * (APITCH * 2) + q * 16, Ag + (size_t)r * Hh + q * 8);
        cp16(bbase + r * (APITCH * 2) + q * 16, Bg + (size_t)r * Hh + q * 8);
    }
}

__global__ void __launch_bounds__(256, 2)
mma_gemm(const bf16* __restrict__ A, bf16* __restrict__ C,
         const bf16* __restrict__ Bt,
         const float* __restrict__ bias, int dotanh, int T)
{
    extern __shared__ char smem[];
    uint32_t sb = smem_u32(smem);
    const int tid = threadIdx.x;
    const int wid = tid >> 5, lane = tid & 31;
    const int wm = wid >> 2, wn = wid & 3;   // 2x4 warp grid, warp tile 64x32
    const int n0 = blockIdx.x * BN;
    const size_t m0 = (size_t)blockIdx.y * BM;

    float acc[4][4][4];
#pragma unroll
    for (int mi = 0; mi < 4; mi++)
#pragma unroll
        for (int ni = 0; ni < 4; ni++)
#pragma unroll
            for (int k = 0; k < 4; k++) acc[mi][ni][k] = 0.f;

    const bf16* Arow = A + m0 * Hh;
    const bf16* Brow = Bt + (size_t)n0 * Hh;

    gemm_load_stage(sb, 0, tid, Arow, Brow);
    CP_COMMIT();
    gemm_load_stage(sb, 1, tid, Arow + BKg, Brow + BKg);
    CP_COMMIT();
    gemm_load_stage(sb, 2, tid, Arow + 2 * BKg, Brow + 2 * BKg);
    CP_COMMIT();

    const int tl = lane >> 3;          // ldmatrix tile selector
    const int l7 = lane & 7;

    for (int t = 0; t < T; t++) {
        CP_WAIT2();
        __syncthreads();
        int nc = t + 3;
        if (nc < T)
            gemm_load_stage(sb, nc % GSTG, tid, Arow + nc * BKg, Brow + nc * BKg);
        CP_COMMIT();   // always commit to keep group counting sound

        uint32_t sA = sb + (t % GSTG) * STAGE_BYTES;
        uint32_t sB = sA + BM * APITCH * 2;
#pragma unroll
        for (int ks = 0; ks < 2; ks++) {
            uint32_t a[4][4];
#pragma unroll
            for (int mi = 0; mi < 4; mi++) {
                int row = wm * 64 + mi * 16 + (tl & 1) * 8 + l7;
                int col = ks * 16 + (tl >> 1) * 8;
                ldsm4(a[mi][0], a[mi][1], a[mi][2], a[mi][3],
                      sA + row * (APITCH * 2) + col * 2);
            }
            uint32_t bq[2][4];
#pragma unroll
            for (int nn = 0; nn < 2; nn++) {
                int row = wn * 32 + nn * 16 + (tl >> 1) * 8 + l7;
                int col = ks * 16 + (tl & 1) * 8;
                ldsm4(bq[nn][0], bq[nn][1], bq[nn][2], bq[nn][3],
                      sB + row * (APITCH * 2) + col * 2);
            }
#pragma unroll
            for (int mi = 0; mi < 4; mi++)
#pragma unroll
                for (int ni = 0; ni < 4; ni++)
                    mma_bf16(acc[mi][ni][0], acc[mi][ni][1], acc[mi][ni][2], acc[mi][ni][3],
                             a[mi][0], a[mi][1], a[mi][2], a[mi][3],
                             bq[ni >> 1][(ni & 1) * 2], bq[ni >> 1][(ni & 1) * 2 + 1]);
        }
    }

    const int lq = lane >> 2;
    const int lr = lane & 3;
#pragma unroll
    for (int mi = 0; mi < 4; mi++) {
        int row = (int)m0 + wm * 64 + mi * 16 + lq;
#pragma unroll
        for (int ni = 0; ni < 4; ni++) {
            int col = n0 + wn * 32 + ni * 8 + lr * 2;
            float b0 = 0.f, b1 = 0.f;
            if (bias) { b0 = bias[col]; b1 = bias[col + 1]; }
            float2 v0, v1;
            v0.x = acc[mi][ni][0] + b0; v0.y = acc[mi][ni][1] + b1;
            v1.x = acc[mi][ni][2] + b0; v1.y = acc[mi][ni][3] + b1;
            if (dotanh) {
                v0.x = tanhf(v0.x); v0.y = tanhf(v0.y);
                v1.x = tanhf(v1.x); v1.y = tanhf(v1.y);
            }
            __nv_bfloat162 w0, w1;
            w0.x = __float2bfloat16_rn(v0.x); w0.y = __float2bfloat16_rn(v0.y);
            w1.x = __float2bfloat16_rn(v1.x); w1.y = __float2bfloat16_rn(v1.y);
            *(__nv_bfloat162*)(C + (size_t)row * Hh + col) = w0;
            *(__nv_bfloat162*)(C + (size_t)(row + 8) * Hh + col) = w1;
        }
    }
}

// =================== weight prep / converts ===================
__global__ void transpose_bf_kernel(const float* __restrict__ in, bf16* __restrict__ out)
{
    __shared__ float tile[32][33];
    int k0 = blockIdx.y * 32, n0 = blockIdx.x * 32;
    int tx = threadIdx.x, ty = threadIdx.y;
    for (int r = ty; r < 32; r += 8) tile[r][tx] = in[(size_t)(k0 + r) * Hh + n0 + tx];
    __syncthreads();
    for (int r = ty; r < 32; r += 8)
        out[(size_t)(n0 + r) * Hh + k0 + tx] = __float2bfloat16_rn(tile[tx][r]);
}
__global__ void repack_gatWt_kernel(const float* __restrict__ gw, bf16* __restrict__ Wgt)
{
    int idx = blockIdx.x * 256 + threadIdx.x;
    int n = idx >> 10, f = idx & 1023;
    int h = n >> 7, d = n & 127;
    Wgt[idx] = __float2bfloat16_rn(gw[((size_t)(h << 10 | f)) * NHID + d]);
}
__global__ void cvt_bf_kernel(const float* __restrict__ a, bf16* __restrict__ oa)
{
    int idx = (blockIdx.x * 256 + threadIdx.x) * 4;
    float4 v = *(const float4*)(a + idx);
    __nv_bfloat162 w0, w1;
    w0.x = __float2bfloat16_rn(v.x); w0.y = __float2bfloat16_rn(v.y);
    w1.x = __float2bfloat16_rn(v.z); w1.y = __float2bfloat16_rn(v.w);
    *(__nv_bfloat162*)(oa + idx) = w0;
    *(__nv_bfloat162*)(oa + idx + 2) = w1;
}

__global__ void fold_u_kernel(const float* __restrict__ lin0W,
                              const float* __restrict__ clsW,
                              float* __restrict__ U0t, float* __restrict__ U1t)
{
    int r = blockIdx.x;
    int c = threadIdx.x >> 5, l = threadIdx.x & 31;
    const float* row = lin0W + (size_t)r * Hh;
    float acc = 0.f;
    for (int k = l; k < Hh; k += 32) acc += row[k] * clsW[k * NCLS + c];
    for (int o = 16; o > 0; o >>= 1) acc += __shfl_down_sync(0xffffffffu, acc, o);
    if (l == 0) {
        if (r < Hh) U0t[c * Hh + r] = acc;
        else        U1t[c * Hh + (r - Hh)] = acc;
    }
}
__global__ void fold_u2_kernel(const float* __restrict__ lin1W,
                               const float* __restrict__ U1t,
                               float* __restrict__ U2t)
{
    int r = blockIdx.x;
    int c = threadIdx.x >> 5, l = threadIdx.x & 31;
    const float* row = lin1W + (size_t)r * Hh;
    const float* u1 = U1t + c * Hh;
    float acc = 0.f;
    for (int k = l; k < Hh; k += 32) acc += row[k] * u1[k];
    for (int o = 16; o > 0; o >>= 1) acc += __shfl_down_sync(0xffffffffu, acc, o);
    if (l == 0) U2t[c * Hh + r] = acc;
}
__global__ void fold_cvec_kernel(const float* __restrict__ lin0b,
                                 const float* __restrict__ lin1b,
                                 const float* __restrict__ clsW,
                                 const float* __restrict__ clsb,
                                 const float* __restrict__ U1t,
                                 float* __restrict__ cvec)
{
    int c = threadIdx.x >> 5, l = threadIdx.x & 31;
    float acc = 0.f;
    for (int k = l; k < Hh; k += 32)
        acc += lin0b[k] * clsW[k * NCLS + c] + lin1b[k] * U1t[c * Hh + k];
    for (int o = 16; o > 0; o >>= 1) acc += __shfl_down_sync(0xffffffffu, acc, o);
    if (l == 0) cvec[c] = acc + clsb[c];
}

// =================== small kernels ===================
__device__ __forceinline__ float eluf(float x) { return x > 0.f ? x : expf(x) - 1.0f; }

__global__ void mean_row0_kernel(const bf16* __restrict__ X, bf16* __restrict__ h1)
{
    int b = blockIdx.y;
    int c = blockIdx.x * 256 + threadIdx.x;
    const bf16* p = X + (size_t)b * Nn * Hh + c;
    float s = 0.f;
    for (int n = 0; n < Nn; n++) s += __bfloat162float(p[(size_t)n * Hh]);
    h1[(size_t)b * Nn * Hh + c] = __float2bfloat16_rn(eluf(s * (1.0f / Nn)));
}

__global__ void att1_tile_kernel(const bf16* __restrict__ Wh,
                                 const float* __restrict__ gat_a1,
                                 const float* __restrict__ gat_a2,
                                 bf16* __restrict__ h1)
{
    __shared__ float sW[55][128];
    __shared__ float sc1[55], sc2[55];
    __shared__ float sw[32][24];
    int b = blockIdx.z, h = blockIdx.y, it = blockIdx.x;
    int i0 = it * 32;
    int jlo0 = i0 - 23; if (jlo0 < 0) jlo0 = 0;
    int nrows = (i0 + 31) - jlo0 + 1;          // <= 55
    int tid = threadIdx.x;
    int warp = tid >> 5, lane = tid & 31;
    const bf16* base = Wh + (size_t)b * Nn * Hh + h * NHID;
    for (int rr = 0; rr < nrows; rr++)
        sW[rr][tid] = __bfloat162float(base[(size_t)(jlo0 + rr) * Hh + tid]);
    __syncthreads();
    {
        float a1v[4], a2v[4];
#pragma unroll
        for (int t = 0; t < 4; t++) {
            a1v[t] = gat_a1[h * NHID + lane + 32 * t];
            a2v[t] = gat_a2[h * NHID + lane + 32 * t];
        }
        for (int rr = warp; rr < nrows; rr += 4) {
            float d1 = 0.f, d2 = 0.f;
#pragma unroll
            for (int t = 0; t < 4; t++) {
                float v = sW[rr][lane + 32 * t];
                d1 += v * a1v[t];
                d2 += v * a2v[t];
            }
            for (int o = 16; o > 0; o >>= 1) {
                d1 += __shfl_down_sync(0xffffffffu, d1, o);
                d2 += __shfl_down_sync(0xffffffffu, d2, o);
            }
            if (lane == 0) { sc1[rr] = d1; sc2[rr] = d2; }
        }
    }
    __syncthreads();
    if (tid < 32) {
        int i = i0 + tid;
        if (i > 0) {
            int jl = i - 23; if (jl < 0) jl = 0;
            int L = i - jl;
            float si = sc1[i - jlo0];
            float mx = -1e30f;
            for (int t = 0; t < L; t++) {
                float v = si + sc2[jl + t - jlo0];
                v = v > 0.f ? v : ALPHA_LRELU * v;
                sw[tid][t] = v; mx = fmaxf(mx, v);
            }
            float ssum = 0.f;
            for (int t = 0; t < L; t++) { float ex = expf(sw[tid][t] - mx); sw[tid][t] = ex; ssum += ex; }
            float inv = 1.0f / ssum;
            for (int t = 0; t < L; t++) sw[tid][t] *= inv;
        }
    }
    __syncthreads();
    for (int il = 0; il < 32; il++) {
        int i = i0 + il;
        if (i == 0) continue;
        int jl = i - 23; if (jl < 0) jl = 0;
        int L = i - jl, roff = jl - jlo0;
        float acc = 0.f;
        for (int t = 0; t < L; t++) acc += sw[il][t] * sW[roff + t][tid];
        h1[((size_t)b * Nn + i) * Hh + h * NHID + tid] = __float2bfloat16_rn(eluf(acc));
    }
}

__global__ void out_scores_kernel(const bf16* __restrict__ Wh2,
                                  const float* __restrict__ a1,
                                  const float* __restrict__ a2,
                                  float* __restrict__ s1, float* __restrict__ s2)
{
    int n = blockIdx.x;
    int tid = threadIdx.x;
    float x1 = 0.f, x2 = 0.f;
    const bf16* x = Wh2 + (size_t)n * Hh;
    for (int c = tid; c < Hh; c += 256) {
        float v = __bfloat162float(x[c]);
        x1 += v * a1[c]; x2 += v * a2[c];
    }
    __shared__ float sh1[8], sh2[8];
    for (int o = 16; o > 0; o >>= 1) {
        x1 += __shfl_down_sync(0xffffffffu, x1, o);
        x2 += __shfl_down_sync(0xffffffffu, x2, o);
    }
    if ((tid & 31) == 0) { sh1[tid >> 5] = x1; sh2[tid >> 5] = x2; }
    __syncthreads();
    if (tid == 0) {
        float t1 = 0.f, t2 = 0.f;
        for (int k = 0; k < 8; k++) { t1 += sh1[k]; t2 += sh2[k]; }
        s1[n] = t1; s2[n] = t2;
    }
}

__global__ void att2_tile_kernel(const bf16* __restrict__ Wh2,
                                 const float* __restrict__ s1,
                                 const float* __restrict__ s2,
                                 bf16* __restrict__ out)
{
    __shared__ float sW[54][128];
    __shared__ float sw[32][24];
    int b = blockIdx.z, ct = blockIdx.y, it = blockIdx.x;
    int i0 = it * 32, c0 = ct * 128;
    int jlo0 = i0 - 23; if (jlo0 < 0) jlo0 = 0;
    int nrows = (i0 + 30) - jlo0 + 1;
    int tid = threadIdx.x;
    const bf16* base = Wh2 + (size_t)b * Nn * Hh + c0;
    for (int rr = 0; rr < nrows; rr++)
        sW[rr][tid] = __bfloat162float(base[(size_t)(jlo0 + rr) * Hh + tid]);
    if (tid < 32) {
        int i = i0 + tid;
        if (i > 0) {
            int jl = i - 23; if (jl < 0) jl = 0;
            int L = i - jl;
            float si = s1[(size_t)b * Nn + i];
            float mx = -1e30f;
            for (int t = 0; t < L; t++) {
                float v = si + s2[(size_t)b * Nn + jl + t];
                v = v > 0.f ? v : ALPHA_LRELU * v;
                sw[tid][t] = v; mx = fmaxf(mx, v);
            }
            float ssum = 0.f;
            for (int t = 0; t < L; t++) { float ex = expf(sw[tid][t] - mx); sw[tid][t] = ex; ssum += ex; }
            float inv = 1.0f / ssum;
            for (int t = 0; t < L; t++) sw[tid][t] *= inv;
        }
    }
    __syncthreads();
    for (int il = 0; il < 32; il++) {
        int i = i0 + il;
        if (i == 0) continue;
        int jl = i - 23; if (jl < 0) jl = 0;
        int L = i - jl, roff = jl - jlo0;
        float acc = 0.f;
        for (int t = 0; t < L; t++) acc += sw[il][t] * sW[roff + t][tid];
        out[((size_t)b * Nn + i) * Hh + c0 + tid] = __float2bfloat16_rn(eluf(acc));
    }
}

// part A: u0part[n][c] = fea_cls[n]·U0t[c]  (off critical path)
__global__ void u0part_kernel(const bf16* __restrict__ fea_cls,
                              const float* __restrict__ U0t,
                              float* __restrict__ part)
{
    int n = blockIdx.x;
    int c = threadIdx.x >> 5, l = threadIdx.x & 31;
    const bf16* frow = fea_cls + (size_t)n * Hh;
    const float* u0 = U0t + c * Hh;
    float acc = 0.f;
    for (int k = l; k < Hh; k += 32)
        acc += __bfloat162float(frow[k]) * u0[k];
    for (int o = 16; o > 0; o >>= 1) acc += __shfl_down_sync(0xffffffffu, acc, o);
    if (l == 0) part[n * NCLS + c] = acc;
}

// part B: loggat = softmax(u0part + hrow·U2 + cvec)
__global__ void gat_logits_kernel(const bf16* __restrict__ fea_cls,
                                  const bf16* __restrict__ h2,
                                  const float* __restrict__ part,
                                  const float* __restrict__ U2t,
                                  const float* __restrict__ cvec,
                                  float* __restrict__ out)
{
    int n = blockIdx.x;
    int i = n & (Nn - 1);
    int c = threadIdx.x >> 5, l = threadIdx.x & 31;
    const bf16* hrow = (i == 0) ? fea_cls + (size_t)n * Hh : h2 + (size_t)n * Hh;
    const float* u2 = U2t + c * Hh;
    float acc = 0.f;
    for (int k = l; k < Hh; k += 32)
        acc += __bfloat162float(hrow[k]) * u2[k];
    for (int o = 16; o > 0; o >>= 1) acc += __shfl_down_sync(0xffffffffu, acc, o);
    __shared__ float sh[NCLS];
    if (l == 0) sh[c] = acc + part[n * NCLS + c] + cvec[c];
    __syncthreads();
    if (threadIdx.x == 0) {
        float mx = sh[0];
        for (int k = 1; k < NCLS; k++) mx = fmaxf(mx, sh[k]);
        float e[NCLS], s = 0.f;
        for (int k = 0; k < NCLS; k++) { e[k] = expf(sh[k] - mx); s += e[k]; }
        float inv = 1.0f / s;
        for (int k = 0; k < NCLS; k++) out[n * NCLS + k] = e[k] * inv;
    }
}

__global__ void cls_softmax_kernel(const bf16* __restrict__ X,
                                   const float* __restrict__ W,
                                   const float* __restrict__ bcls,
                                   float* __restrict__ out)
{
    int n = blockIdx.x;
    int wid = threadIdx.x >> 5, l = threadIdx.x & 31;
    __shared__ float sh[NCLS];
    const bf16* x = X + (size_t)n * Hh;
    float acc = 0.f;
    for (int t = l; t < Hh; t += 32) acc += __bfloat162float(x[t]) * W[t * NCLS + wid];
    for (int o = 16; o > 0; o >>= 1) acc += __shfl_down_sync(0xffffffffu, acc, o);
    if (l == 0) sh[wid] = acc + bcls[wid];
    __syncthreads();
    if (threadIdx.x == 0) {
        float mx = sh[0];
        for (int k = 1; k < NCLS; k++) mx = fmaxf(mx, sh[k]);
        float e[NCLS], s = 0.f;
        for (int k = 0; k < NCLS; k++) { e[k] = expf(sh[k] - mx); s += e[k]; }
        float inv = 1.0f / s;
        for (int k = 0; k < NCLS; k++) out[n * NCLS + k] = e[k] * inv;
    }
}

__global__ void hmm_kernel(const float* __restrict__ Bprob,
                           const float* __restrict__ hmmA,
                           float* __restrict__ out)
{
    __shared__ float sAT[NCLS * NCLS];
    int tid = threadIdx.x;
    if (tid < NCLS * NCLS) sAT[tid] = hmmA[(tid % NCLS) * NCLS + (tid / NCLS)];
    __syncthreads();
    int gidx = blockIdx.x * 128 + tid;
    int b = gidx >> 8, i = gidx & 255;
    const float* Bp = Bprob + (size_t)b * Nn * NCLS;
    int t0 = i - (BAND - 1); if (t0 < 0) t0 = 0;
    float p[NCLS]; float s = 0.f;
#pragma unroll
    for (int r = 0; r < NCLS; r++) { p[r] = Bp[t0 * NCLS + r]; s += p[r]; }
    float inv = 1.0f / s;
#pragma unroll
    for (int r = 0; r < NCLS; r++) p[r] *= inv;
    for (int t = t0 + 1; t <= i; t++) {
        float q[NCLS]; s = 0.f;
#pragma unroll
        for (int r = 0; r < NCLS; r++) {
            float a = 0.f;
#pragma unroll
            for (int c = 0; c < NCLS; c++) a += sAT[r * NCLS + c] * p[c];
            a *= Bp[t * NCLS + r];
            q[r] = a; s += a;
        }
        inv = 1.0f / s;
#pragma unroll
        for (int r = 0; r < NCLS; r++) p[r] = q[r] * inv;
    }
#pragma unroll
    for (int r = 0; r < NCLS; r++) out[gidx * NCLS + r] = p[r];
}

__global__ void final_kernel(const float* __restrict__ log_gat,
                             const float* __restrict__ log_hmm,
                             const int* __restrict__ labels,
                             float* __restrict__ outLogits)
{
    int r = blockIdx.x * 256 + threadIdx.x;
    float lg[NCLS];
#pragma unroll
    for (int k = 0; k < NCLS; k++) {
        lg[k] = logf(0.5f * (log_gat[r * NCLS + k] + log_hmm[r * NCLS + k]));
        outLogits[r * NCLS + k] = lg[k];
    }
    int lab = labels[r];
    float picked = (lab >= 0) ? lg[lab] : 0.f;
    for (int o = 16; o > 0; o >>= 1) picked += __shfl_down_sync(0xffffffffu, picked, o);
    __shared__ float sh[8];
    if ((threadIdx.x & 31) == 0) sh[threadIdx.x >> 5] = picked;
    __syncthreads();
    if (threadIdx.x == 0) {
        float s = 0.f;
        for (int k = 0; k < 8; k++) s += sh[k];
        g_blocksums[blockIdx.x] = s;
    }
}

__global__ void finalize_kernel(float* d_out, int has_loss)
{
    if (has_loss) {
        float s = 0.f;
        for (int k = 0; k < 32; k++) s += g_blocksums[k];
        d_out[0] = -s / (float)ROWS;
    }
}

// ---------------- host launch ----------------
template <typename T>
static T* sym(const void* symbol)
{
    void* p = nullptr;
    cudaGetSymbolAddress(&p, symbol);
    return (T*)p;
}

extern "C" void kernel_launch(void* const* d_in, const int* in_sizes, int n_in,
                              void* d_out, int out_size)
{
    (void)in_sizes; (void)n_in;
    const float* hidden_cls = (const float*)d_in[0];
    const float* hidden_emo = (const float*)d_in[1];
    const int*   labels     = (const int*)d_in[3];
    const float* pooler_W   = (const float*)d_in[4];
    const float* pooler_b   = (const float*)d_in[5];
    const float* gat_W      = (const float*)d_in[6];
    const float* gat_a1     = (const float*)d_in[7];
    const float* gat_a2     = (const float*)d_in[8];
    const float* out_W      = (const float*)d_in[9];
    const float* out_a1     = (const float*)d_in[10];
    const float* out_a2     = (const float*)d_in[11];
    const float* lin1_W     = (const float*)d_in[12];
    const float* lin1_b     = (const float*)d_in[13];
    const float* lin0_W     = (const float*)d_in[14];
    const float* lin0_b     = (const float*)d_in[15];
    const float* cls_W      = (const float*)d_in[16];
    const float* cls_b      = (const float*)d_in[17];
    const float* hmm_A      = (const float*)d_in[18];

    float* s1b     = sym<float>(g_s1b);
    float* s2b     = sym<float>(g_s2b);
    float* loggat  = sym<float>(g_loggat);
    float* Bprob   = sym<float>(g_Bprob);
    float* loghmm  = sym<float>(g_loghmm);
    float* u0part  = sym<float>(g_u0part);
    bf16* hidcbf   = sym<bf16>(g_hid_cls_bf);
    bf16* hidebf   = sym<bf16>(g_hid_emo_bf);
    bf16* feacbf   = sym<bf16>(g_fea_cls_bf);
    bf16* feaebf   = sym<bf16>(g_fea_emo_bf);
    bf16* Whbf     = sym<bf16>(g_Wh_bf);
    bf16* Wh2bf    = sym<bf16>(g_Wh2_bf);
    bf16* h1bf     = sym<bf16>(g_h1_bf);
    bf16* h2bf     = sym<bf16>(g_h2_bf);
    bf16* poolWt   = sym<bf16>(g_poolWt);
    bf16* Wgt      = sym<bf16>(g_Wgt);
    bf16* outWt    = sym<bf16>(g_outWt);
    float* U0t     = sym<float>(g_U0t);
    float* U1t     = sym<float>(g_U1t);
    float* U2t     = sym<float>(g_U2t);
    float* cvec    = sym<float>(g_cvec);

    cudaFuncSetAttribute(mma_gemm, cudaFuncAttributeMaxDynamicSharedMemorySize, GEMM_SMEM);

    int has_loss = (out_size == ROWS * NCLS + 1) ? 1 : 0;
    float* outLogits = has_loss ? ((float*)d_out + 1) : (float*)d_out;

    // side streams + events (created once; captured work identical each call)
    static cudaStream_t sPrep = nullptr, sHmm = nullptr;
    static cudaEvent_t eFork = nullptr, eWgt = nullptr, eTab = nullptr,
                       eTrans = nullptr, eCvt = nullptr, ePoolC = nullptr,
                       ePart = nullptr, eHmm = nullptr;
    if (!sPrep) {
        cudaStreamCreateWithFlags(&sPrep, cudaStreamNonBlocking);
        cudaStreamCreateWithFlags(&sHmm, cudaStreamNonBlocking);
        cudaEventCreateWithFlags(&eFork, cudaEventDisableTiming);
        cudaEventCreateWithFlags(&eWgt, cudaEventDisableTiming);
        cudaEventCreateWithFlags(&eTab, cudaEventDisableTiming);
        cudaEventCreateWithFlags(&eTrans, cudaEventDisableTiming);
        cudaEventCreateWithFlags(&eCvt, cudaEventDisableTiming);
        cudaEventCreateWithFlags(&ePoolC, cudaEventDisableTiming);
        cudaEventCreateWithFlags(&ePart, cudaEventDisableTiming);
        cudaEventCreateWithFlags(&eHmm, cudaEventDisableTiming);
    }
    cudaStream_t s0 = 0;
    dim3 tblk(32, 8);

    // ---- fork ----
    cudaEventRecord(eFork, s0);
    cudaStreamWaitEvent(sPrep, eFork, 0);
    cudaStreamWaitEvent(sHmm, eFork, 0);

    // ---- prep stream: weights + tables ----
    repack_gatWt_kernel<<<(Hh * Hh) / 256, 256, 0, sPrep>>>(gat_W, Wgt);
    cudaEventRecord(eWgt, sPrep);
    transpose_bf_kernel<<<dim3(Hh / 32, Hh / 32), tblk, 0, sPrep>>>(out_W, outWt);
    fold_u_kernel<<<2 * Hh, 224, 0, sPrep>>>(lin0_W, cls_W, U0t, U1t);
    fold_u2_kernel<<<Hh, 224, 0, sPrep>>>(lin1_W, U1t, U2t);
    fold_cvec_kernel<<<1, 224, 0, sPrep>>>(lin0_b, lin1_b, cls_W, cls_b, U1t, cvec);
    cudaEventRecord(eTab, sPrep);

    // ---- HMM stream: cvt_cls early (concurrent with poolW transpose) ----
    cvt_bf_kernel<<<ROWS * Hh / 1024, 256, 0, sHmm>>>(hidden_cls, hidcbf);
    cudaEventRecord(eCvt, sHmm);

    // ---- main chain ----
    transpose_bf_kernel<<<dim3(Hh / 32, Hh / 32), tblk, 0, s0>>>(pooler_W, poolWt);
    cudaEventRecord(eTrans, s0);       // poolWt ready -> emo branch may start
    cudaStreamWaitEvent(s0, eCvt, 0);
    mma_gemm<<<dim3(Hh / BN, ROWS / BM), 256, GEMM_SMEM, s0>>>(
        hidcbf, feacbf, poolWt, pooler_b, 1, Hh / BKg);
    cudaEventRecord(ePoolC, s0);

    // ---- emo/HMM branch on sHmm (off the critical path) ----
    cudaStreamWaitEvent(sHmm, eTrans, 0);
    cvt_bf_kernel<<<ROWS * Hh / 1024, 256, 0, sHmm>>>(hidden_emo, hidebf);
    mma_gemm<<<dim3(Hh / BN, ROWS / BM), 256, GEMM_SMEM, sHmm>>>(
        hidebf, feaebf, poolWt, pooler_b, 1, Hh / BKg);
    cls_softmax_kernel<<<ROWS, 224, 0, sHmm>>>(feaebf, cls_W, cls_b, Bprob);
    hmm_kernel<<<ROWS / 128, 128, 0, sHmm>>>(Bprob, hmm_A, loghmm);
    cudaEventRecord(eHmm, sHmm);

    // ---- u0 partial on sPrep (off the critical path) ----
    cudaStreamWaitEvent(sPrep, ePoolC, 0);
    u0part_kernel<<<ROWS, 224, 0, sPrep>>>(feacbf, U0t, u0part);
    cudaEventRecord(ePart, sPrep);

    // ---- GAT chain on s0 ----
    cudaStreamWaitEvent(s0, eWgt, 0);
    mma_gemm<<<dim3(Hh / BN, ROWS / BM), 256, GEMM_SMEM, s0>>>(
        feacbf, Whbf, Wgt, nullptr, 0, Hh / BKg);
    att1_tile_kernel<<<dim3(8, 8, Bc), 128, 0, s0>>>(Whbf, gat_a1, gat_a2, h1bf);
    mean_row0_kernel<<<dim3(Hh / 256, Bc), 256, 0, s0>>>(Whbf, h1bf);

    cudaStreamWaitEvent(s0, eTab, 0);      // outWt + U tables ready
    mma_gemm<<<dim3(Hh / BN, ROWS / BM), 256, GEMM_SMEM, s0>>>(
        h1bf, Wh2bf, outWt, nullptr, 0, Hh / BKg);
    out_scores_kernel<<<ROWS, 256, 0, s0>>>(Wh2bf, out_a1, out_a2, s1b, s2b);
    att2_tile_kernel<<<dim3(8, 8, Bc), 128, 0, s0>>>(Wh2bf, s1b, s2b, h2bf);

    cudaStreamWaitEvent(s0, ePart, 0);
    gat_logits_kernel<<<ROWS, 224, 0, s0>>>(feacbf, h2bf, u0part, U2t, cvec, loggat);

    // ---- join HMM branch, final ----
    cudaStreamWaitEvent(s0, eHmm, 0);
    final_kernel<<<ROWS / 256, 256, 0, s0>>>(loggat, loghmm, labels, outLogits);
    finalize_kernel<<<1, 1, 0, s0>>>((float*)d_out, has_loss);
}

// round 16
// speedup vs baseline: 1.3070x; 1.0001x over previous
#include <cuda_runtime.h>
#include <cuda_bf16.h>
#include <math.h>
#include <stdint.h>

// Problem constants
#define Bc   32
#define Nn   256
#define Hh   1024
#define HEADS 8
#define NHID 128
#define NCLS 7
#define BAND 24
#define ROWS (Bc*Nn)          // 8192
#define ALPHA_LRELU 0.2f

typedef __nv_bfloat16 bf16;

// ---------------- device scratch (no allocs allowed) ----------------
__device__ float g_s1b[ROWS];
__device__ float g_s2b[ROWS];
__device__ float g_loggat[ROWS*NCLS];
__device__ float g_Bprob[ROWS*NCLS];
__device__ float g_loghmm[ROWS*NCLS];
__device__ float g_u0part[ROWS*NCLS];
__device__ float g_blocksums[32];
// bf16 tensors
__device__ bf16 g_hid_cls_bf[ROWS*Hh];
__device__ bf16 g_hid_emo_bf[ROWS*Hh];
__device__ bf16 g_fea_cls_bf[ROWS*Hh];
__device__ bf16 g_fea_emo_bf[ROWS*Hh];
__device__ bf16 g_Wh_bf[ROWS*Hh];
__device__ bf16 g_Wh2_bf[ROWS*Hh];
__device__ bf16 g_h1_bf[ROWS*Hh];
__device__ bf16 g_h2_bf[ROWS*Hh];
__device__ bf16 g_poolWt[Hh*Hh];   // [N][K] k-major
__device__ bf16 g_Wgt[Hh*Hh];
__device__ bf16 g_outWt[Hh*Hh];
// folded classifier tables ([7][1024] row-major)
__device__ float g_U0t[NCLS*Hh];
__device__ float g_U1t[NCLS*Hh];
__device__ float g_U2t[NCLS*Hh];
__device__ float g_cvec[NCLS];

// =================== bf16 mma.sync GEMM (4-stage cp.async pipeline) ==========
#define BM 128
#define BN 128
#define BKg 32
#define GSTG 4
#define APITCH 40                             // halves per smem row (80 B)
#define STAGE_BYTES (2 * BM * APITCH * 2)     // A + B = 20480 B
#define GEMM_SMEM (GSTG * STAGE_BYTES)        // 81920 B

__device__ __forceinline__ uint32_t smem_u32(const void* p) {
    uint32_t a;
    asm("{ .reg .u64 t; cvta.to.shared.u64 t, %1; cvt.u32.u64 %0, t; }" : "=r"(a) : "l"(p));
    return a;
}
__device__ __forceinline__ void cp16(uint32_t s, const void* g) {
    asm volatile("cp.async.cg.shared.global [%0], [%1], 16;" :: "r"(s), "l"(g));
}
#define CP_COMMIT() asm volatile("cp.async.commit_group;" ::: "memory")
#define CP_WAIT2()  asm volatile("cp.async.wait_group 2;" ::: "memory")

__device__ __forceinline__ void ldsm4(uint32_t& r0, uint32_t& r1, uint32_t& r2, uint32_t& r3,
                                      uint32_t addr) {
    asm volatile("ldmatrix.sync.aligned.m8n8.x4.shared.b16 {%0,%1,%2,%3}, [%4];"
                 : "=r"(r0), "=r"(r1), "=r"(r2), "=r"(r3) : "r"(addr));
}
__device__ __forceinline__ void mma_bf16(float& d0, float& d1, float& d2, float& d3,
                                         uint32_t a0, uint32_t a1, uint32_t a2, uint32_t a3,
                                         uint32_t b0, uint32_t b1) {
    asm volatile("mma.sync.aligned.m16n8k16.row.col.f32.bf16.bf16.f32 "
                 "{%0,%1,%2,%3}, {%4,%5,%6,%7}, {%8,%9}, {%0,%1,%2,%3};"
                 : "+f"(d0), "+f"(d1), "+f"(d2), "+f"(d3)
                 : "r"(a0), "r"(a1), "r"(a2), "r"(a3), "r"(b0), "r"(b1));
}

__device__ __forceinline__ void gemm_load_stage(uint32_t sb, int stage, int tid,
                                                const bf16* Ag, const bf16* Bg) {
    uint32_t abase = sb + stage * STAGE_BYTES;
    uint32_t bbase = abase + BM * APITCH * 2;
#pragma unroll
    for (int i = 0; i < 2; i++) {
        int idx = tid + 256 * i;
        int r = idx >> 2;
        int q = idx & 3;
        cp16(abase + r * (APITCH * 2) + q * 16, Ag + (size_t)r * Hh + q * 8);
        cp16(bbase + r * (APITCH * 2) + q * 16, Bg + (size_t)r * Hh + q * 8);
    }
}

__global__ void __launch_bounds__(256, 2)
mma_gemm(const bf16* __restrict__ A, bf16* __restrict__ C,
         const bf16* __restrict__ Bt,
         const float* __restrict__ bias, int dotanh, int T)
{
    extern __shared__ char smem[];
    uint32_t sb = smem_u32(smem);
    const int tid = threadIdx.x;
    const int wid = tid >> 5, lane = tid & 31;
    const int wm = wid >> 2, wn = wid & 3;   // 2x4 warp grid, warp tile 64x32
    const int n0 = blockIdx.x * BN;
    const size_t m0 = (size_t)blockIdx.y * BM;

    float acc[4][4][4];
#pragma unroll
    for (int mi = 0; mi < 4; mi++)
#pragma unroll
        for (int ni = 0; ni < 4; ni++)
#pragma unroll
            for (int k = 0; k < 4; k++) acc[mi][ni][k] = 0.f;

    const bf16* Arow = A + m0 * Hh;
    const bf16* Brow = Bt + (size_t)n0 * Hh;

    gemm_load_stage(sb, 0, tid, Arow, Brow);
    CP_COMMIT();
    gemm_load_stage(sb, 1, tid, Arow + BKg, Brow + BKg);
    CP_COMMIT();
    gemm_load_stage(sb, 2, tid, Arow + 2 * BKg, Brow + 2 * BKg);
    CP_COMMIT();

    const int tl = lane >> 3;          // ldmatrix tile selector
    const int l7 = lane & 7;

    for (int t = 0; t < T; t++) {
        CP_WAIT2();
        __syncthreads();
        int nc = t + 3;
        if (nc < T)
            gemm_load_stage(sb, nc % GSTG, tid, Arow + nc * BKg, Brow + nc * BKg);
        CP_COMMIT();   // always commit to keep group counting sound

        uint32_t sA = sb + (t % GSTG) * STAGE_BYTES;
        uint32_t sB = sA + BM * APITCH * 2;
#pragma unroll
        for (int ks = 0; ks < 2; ks++) {
            uint32_t a[4][4];
#pragma unroll
            for (int mi = 0; mi < 4; mi++) {
                int row = wm * 64 + mi * 16 + (tl & 1) * 8 + l7;
                int col = ks * 16 + (tl >> 1) * 8;
                ldsm4(a[mi][0], a[mi][1], a[mi][2], a[mi][3],
                      sA + row * (APITCH * 2) + col * 2);
            }
            uint32_t bq[2][4];
#pragma unroll
            for (int nn = 0; nn < 2; nn++) {
                int row = wn * 32 + nn * 16 + (tl >> 1) * 8 + l7;
                int col = ks * 16 + (tl & 1) * 8;
                ldsm4(bq[nn][0], bq[nn][1], bq[nn][2], bq[nn][3],
                      sB + row * (APITCH * 2) + col * 2);
            }
#pragma unroll
            for (int mi = 0; mi < 4; mi++)
#pragma unroll
                for (int ni = 0; ni < 4; ni++)
                    mma_bf16(acc[mi][ni][0], acc[mi][ni][1], acc[mi][ni][2], acc[mi][ni][3],
                             a[mi][0], a[mi][1], a[mi][2], a[mi][3],
                             bq[ni >> 1][(ni & 1) * 2], bq[ni >> 1][(ni & 1) * 2 + 1]);
        }
    }

    const int lq = lane >> 2;
    const int lr = lane & 3;
#pragma unroll
    for (int mi = 0; mi < 4; mi++) {
        int row = (int)m0 + wm * 64 + mi * 16 + lq;
#pragma unroll
        for (int ni = 0; ni < 4; ni++) {
            int col = n0 + wn * 32 + ni * 8 + lr * 2;
            float b0 = 0.f, b1 = 0.f;
            if (bias) { b0 = bias[col]; b1 = bias[col + 1]; }
            float2 v0, v1;
            v0.x = acc[mi][ni][0] + b0; v0.y = acc[mi][ni][1] + b1;
            v1.x = acc[mi][ni][2] + b0; v1.y = acc[mi][ni][3] + b1;
            if (dotanh) {
                v0.x = tanhf(v0.x); v0.y = tanhf(v0.y);
                v1.x = tanhf(v1.x); v1.y = tanhf(v1.y);
            }
            __nv_bfloat162 w0, w1;
            w0.x = __float2bfloat16_rn(v0.x); w0.y = __float2bfloat16_rn(v0.y);
            w1.x = __float2bfloat16_rn(v1.x); w1.y = __float2bfloat16_rn(v1.y);
            *(__nv_bfloat162*)(C + (size_t)row * Hh + col) = w0;
            *(__nv_bfloat162*)(C + (size_t)(row + 8) * Hh + col) = w1;
        }
    }
}

// =================== weight prep / converts ===================
__global__ void transpose_bf_kernel(const float* __restrict__ in, bf16* __restrict__ out)
{
    __shared__ float tile[32][33];
    int k0 = blockIdx.y * 32, n0 = blockIdx.x * 32;
    int tx = threadIdx.x, ty = threadIdx.y;
    for (int r = ty; r < 32; r += 8) tile[r][tx] = in[(size_t)(k0 + r) * Hh + n0 + tx];
    __syncthreads();
    for (int r = ty; r < 32; r += 8)
        out[(size_t)(n0 + r) * Hh + k0 + tx] = __float2bfloat16_rn(tile[tx][r]);
}
__global__ void repack_gatWt_kernel(const float* __restrict__ gw, bf16* __restrict__ Wgt)
{
    int idx = blockIdx.x * 256 + threadIdx.x;
    int n = idx >> 10, f = idx & 1023;
    int h = n >> 7, d = n & 127;
    Wgt[idx] = __float2bfloat16_rn(gw[((size_t)(h << 10 | f)) * NHID + d]);
}
__global__ void cvt_bf_kernel(const float* __restrict__ a, bf16* __restrict__ oa)
{
    int idx = (blockIdx.x * 256 + threadIdx.x) * 4;
    float4 v = *(const float4*)(a + idx);
    __nv_bfloat162 w0, w1;
    w0.x = __float2bfloat16_rn(v.x); w0.y = __float2bfloat16_rn(v.y);
    w1.x = __float2bfloat16_rn(v.z); w1.y = __float2bfloat16_rn(v.w);
    *(__nv_bfloat162*)(oa + idx) = w0;
    *(__nv_bfloat162*)(oa + idx + 2) = w1;
}

__global__ void fold_u_kernel(const float* __restrict__ lin0W,
                              const float* __restrict__ clsW,
                              float* __restrict__ U0t, float* __restrict__ U1t)
{
    int r = blockIdx.x;
    int c = threadIdx.x >> 5, l = threadIdx.x & 31;
    const float* row = lin0W + (size_t)r * Hh;
    float acc = 0.f;
    for (int k = l; k < Hh; k += 32) acc += row[k] * clsW[k * NCLS + c];
    for (int o = 16; o > 0; o >>= 1) acc += __shfl_down_sync(0xffffffffu, acc, o);
    if (l == 0) {
        if (r < Hh) U0t[c * Hh + r] = acc;
        else        U1t[c * Hh + (r - Hh)] = acc;
    }
}
__global__ void fold_u2_kernel(const float* __restrict__ lin1W,
                               const float* __restrict__ U1t,
                               float* __restrict__ U2t)
{
    int r = blockIdx.x;
    int c = threadIdx.x >> 5, l = threadIdx.x & 31;
    const float* row = lin1W + (size_t)r * Hh;
    const float* u1 = U1t + c * Hh;
    float acc = 0.f;
    for (int k = l; k < Hh; k += 32) acc += row[k] * u1[k];
    for (int o = 16; o > 0; o >>= 1) acc += __shfl_down_sync(0xffffffffu, acc, o);
    if (l == 0) U2t[c * Hh + r] = acc;
}
__global__ void fold_cvec_kernel(const float* __restrict__ lin0b,
                                 const float* __restrict__ lin1b,
                                 const float* __restrict__ clsW,
                                 const float* __restrict__ clsb,
                                 const float* __restrict__ U1t,
                                 float* __restrict__ cvec)
{
    int c = threadIdx.x >> 5, l = threadIdx.x & 31;
    float acc = 0.f;
    for (int k = l; k < Hh; k += 32)
        acc += lin0b[k] * clsW[k * NCLS + c] + lin1b[k] * U1t[c * Hh + k];
    for (int o = 16; o > 0; o >>= 1) acc += __shfl_down_sync(0xffffffffu, acc, o);
    if (l == 0) cvec[c] = acc + clsb[c];
}

// =================== small kernels ===================
__device__ __forceinline__ float eluf(float x) { return x > 0.f ? x : expf(x) - 1.0f; }

__global__ void mean_row0_kernel(const bf16* __restrict__ X, bf16* __restrict__ h1)
{
    int b = blockIdx.y;
    int c = blockIdx.x * 256 + threadIdx.x;
    const bf16* p = X + (size_t)b * Nn * Hh + c;
    float s = 0.f;
    for (int n = 0; n < Nn; n++) s += __bfloat162float(p[(size_t)n * Hh]);
    h1[(size_t)b * Nn * Hh + c] = __float2bfloat16_rn(eluf(s * (1.0f / Nn)));
}

__global__ void att1_tile_kernel(const bf16* __restrict__ Wh,
                                 const float* __restrict__ gat_a1,
                                 const float* __restrict__ gat_a2,
                                 bf16* __restrict__ h1)
{
    __shared__ float sW[55][128];
    __shared__ float sc1[55], sc2[55];
    __shared__ float sw[32][24];
    int b = blockIdx.z, h = blockIdx.y, it = blockIdx.x;
    int i0 = it * 32;
    int jlo0 = i0 - 23; if (jlo0 < 0) jlo0 = 0;
    int nrows = (i0 + 31) - jlo0 + 1;          // <= 55
    int tid = threadIdx.x;
    int warp = tid >> 5, lane = tid & 31;
    const bf16* base = Wh + (size_t)b * Nn * Hh + h * NHID;
    for (int rr = 0; rr < nrows; rr++)
        sW[rr][tid] = __bfloat162float(base[(size_t)(jlo0 + rr) * Hh + tid]);
    __syncthreads();
    {
        float a1v[4], a2v[4];
#pragma unroll
        for (int t = 0; t < 4; t++) {
            a1v[t] = gat_a1[h * NHID + lane + 32 * t];
            a2v[t] = gat_a2[h * NHID + lane + 32 * t];
        }
        for (int rr = warp; rr < nrows; rr += 4) {
            float d1 = 0.f, d2 = 0.f;
#pragma unroll
            for (int t = 0; t < 4; t++) {
                float v = sW[rr][lane + 32 * t];
                d1 += v * a1v[t];
                d2 += v * a2v[t];
            }
            for (int o = 16; o > 0; o >>= 1) {
                d1 += __shfl_down_sync(0xffffffffu, d1, o);
                d2 += __shfl_down_sync(0xffffffffu, d2, o);
            }
            if (lane == 0) { sc1[rr] = d1; sc2[rr] = d2; }
        }
    }
    __syncthreads();
    if (tid < 32) {
        int i = i0 + tid;
        if (i > 0) {
            int jl = i - 23; if (jl < 0) jl = 0;
            int L = i - jl;
            float si = sc1[i - jlo0];
            float mx = -1e30f;
            for (int t = 0; t < L; t++) {
                float v = si + sc2[jl + t - jlo0];
                v = v > 0.f ? v : ALPHA_LRELU * v;
                sw[tid][t] = v; mx = fmaxf(mx, v);
            }
            float ssum = 0.f;
            for (int t = 0; t < L; t++) { float ex = expf(sw[tid][t] - mx); sw[tid][t] = ex; ssum += ex; }
            float inv = 1.0f / ssum;
            for (int t = 0; t < L; t++) sw[tid][t] *= inv;
        }
    }
    __syncthreads();
    for (int il = 0; il < 32; il++) {
        int i = i0 + il;
        if (i == 0) continue;
        int jl = i - 23; if (jl < 0) jl = 0;
        int L = i - jl, roff = jl - jlo0;
        float acc = 0.f;
        for (int t = 0; t < L; t++) acc += sw[il][t] * sW[roff + t][tid];
        h1[((size_t)b * Nn + i) * Hh + h * NHID + tid] = __float2bfloat16_rn(eluf(acc));
    }
}

__global__ void out_scores_kernel(const bf16* __restrict__ Wh2,
                                  const float* __restrict__ a1,
                                  const float* __restrict__ a2,
                                  float* __restrict__ s1, float* __restrict__ s2)
{
    int n = blockIdx.x;
    int tid = threadIdx.x;
    float x1 = 0.f, x2 = 0.f;
    const bf16* x = Wh2 + (size_t)n * Hh;
    for (int c = tid; c < Hh; c += 256) {
        float v = __bfloat162float(x[c]);
        x1 += v * a1[c]; x2 += v * a2[c];
    }
    __shared__ float sh1[8], sh2[8];
    for (int o = 16; o > 0; o >>= 1) {
        x1 += __shfl_down_sync(0xffffffffu, x1, o);
        x2 += __shfl_down_sync(0xffffffffu, x2, o);
    }
    if ((tid & 31) == 0) { sh1[tid >> 5] = x1; sh2[tid >> 5] = x2; }
    __syncthreads();
    if (tid == 0) {
        float t1 = 0.f, t2 = 0.f;
        for (int k = 0; k < 8; k++) { t1 += sh1[k]; t2 += sh2[k]; }
        s1[n] = t1; s2[n] = t2;
    }
}

__global__ void att2_tile_kernel(const bf16* __restrict__ Wh2,
                                 const float* __restrict__ s1,
                                 const float* __restrict__ s2,
                                 bf16* __restrict__ out)
{
    __shared__ float sW[54][128];
    __shared__ float sw[32][24];
    int b = blockIdx.z, ct = blockIdx.y, it = blockIdx.x;
    int i0 = it * 32, c0 = ct * 128;
    int jlo0 = i0 - 23; if (jlo0 < 0) jlo0 = 0;
    int nrows = (i0 + 30) - jlo0 + 1;
    int tid = threadIdx.x;
    const bf16* base = Wh2 + (size_t)b * Nn * Hh + c0;
    for (int rr = 0; rr < nrows; rr++)
        sW[rr][tid] = __bfloat162float(base[(size_t)(jlo0 + rr) * Hh + tid]);
    if (tid < 32) {
        int i = i0 + tid;
        if (i > 0) {
            int jl = i - 23; if (jl < 0) jl = 0;
            int L = i - jl;
            float si = s1[(size_t)b * Nn + i];
            float mx = -1e30f;
            for (int t = 0; t < L; t++) {
                float v = si + s2[(size_t)b * Nn + jl + t];
                v = v > 0.f ? v : ALPHA_LRELU * v;
                sw[tid][t] = v; mx = fmaxf(mx, v);
            }
            float ssum = 0.f;
            for (int t = 0; t < L; t++) { float ex = expf(sw[tid][t] - mx); sw[tid][t] = ex; ssum += ex; }
            float inv = 1.0f / ssum;
            for (int t = 0; t < L; t++) sw[tid][t] *= inv;
        }
    }
    __syncthreads();
    for (int il = 0; il < 32; il++) {
        int i = i0 + il;
        if (i == 0) continue;
        int jl = i - 23; if (jl < 0) jl = 0;
        int L = i - jl, roff = jl - jlo0;
        float acc = 0.f;
        for (int t = 0; t < L; t++) acc += sw[il][t] * sW[roff + t][tid];
        out[((size_t)b * Nn + i) * Hh + c0 + tid] = __float2bfloat16_rn(eluf(acc));
    }
}

// part A: u0part[n][c] = fea_cls[n]·U0t[c]  (off critical path)
__global__ void u0part_kernel(const bf16* __restrict__ fea_cls,
                              const float* __restrict__ U0t,
                              float* __restrict__ part)
{
    int n = blockIdx.x;
    int c = threadIdx.x >> 5, l = threadIdx.x & 31;
    const bf16* frow = fea_cls + (size_t)n * Hh;
    const float* u0 = U0t + c * Hh;
    float acc = 0.f;
    for (int k = l; k < Hh; k += 32)
        acc += __bfloat162float(frow[k]) * u0[k];
    for (int o = 16; o > 0; o >>= 1) acc += __shfl_down_sync(0xffffffffu, acc, o);
    if (l == 0) part[n * NCLS + c] = acc;
}

// part B: loggat = softmax(u0part + hrow·U2 + cvec)
__global__ void gat_logits_kernel(const bf16* __restrict__ fea_cls,
                                  const bf16* __restrict__ h2,
                                  const float* __restrict__ part,
                                  const float* __restrict__ U2t,
                                  const float* __restrict__ cvec,
                                  float* __restrict__ out)
{
    int n = blockIdx.x;
    int i = n & (Nn - 1);
    int c = threadIdx.x >> 5, l = threadIdx.x & 31;
    const bf16* hrow = (i == 0) ? fea_cls + (size_t)n * Hh : h2 + (size_t)n * Hh;
    const float* u2 = U2t + c * Hh;
    float acc = 0.f;
    for (int k = l; k < Hh; k += 32)
        acc += __bfloat162float(hrow[k]) * u2[k];
    for (int o = 16; o > 0; o >>= 1) acc += __shfl_down_sync(0xffffffffu, acc, o);
    __shared__ float sh[NCLS];
    if (l == 0) sh[c] = acc + part[n * NCLS + c] + cvec[c];
    __syncthreads();
    if (threadIdx.x == 0) {
        float mx = sh[0];
        for (int k = 1; k < NCLS; k++) mx = fmaxf(mx, sh[k]);
        float e[NCLS], s = 0.f;
        for (int k = 0; k < NCLS; k++) { e[k] = expf(sh[k] - mx); s += e[k]; }
        float inv = 1.0f / s;
        for (int k = 0; k < NCLS; k++) out[n * NCLS + k] = e[k] * inv;
    }
}

__global__ void cls_softmax_kernel(const bf16* __restrict__ X,
                                   const float* __restrict__ W,
                                   const float* __restrict__ bcls,
                                   float* __restrict__ out)
{
    int n = blockIdx.x;
    int wid = threadIdx.x >> 5, l = threadIdx.x & 31;
    __shared__ float sh[NCLS];
    const bf16* x = X + (size_t)n * Hh;
    float acc = 0.f;
    for (int t = l; t < Hh; t += 32) acc += __bfloat162float(x[t]) * W[t * NCLS + wid];
    for (int o = 16; o > 0; o >>= 1) acc += __shfl_down_sync(0xffffffffu, acc, o);
    if (l == 0) sh[wid] = acc + bcls[wid];
    __syncthreads();
    if (threadIdx.x == 0) {
        float mx = sh[0];
        for (int k = 1; k < NCLS; k++) mx = fmaxf(mx, sh[k]);
        float e[NCLS], s = 0.f;
        for (int k = 0; k < NCLS; k++) { e[k] = expf(sh[k] - mx); s += e[k]; }
        float inv = 1.0f / s;
        for (int k = 0; k < NCLS; k++) out[n * NCLS + k] = e[k] * inv;
    }
}

__global__ void hmm_kernel(const float* __restrict__ Bprob,
                           const float* __restrict__ hmmA,
                           float* __restrict__ out)
{
    __shared__ float sAT[NCLS * NCLS];
    int tid = threadIdx.x;
    if (tid < NCLS * NCLS) sAT[tid] = hmmA[(tid % NCLS) * NCLS + (tid / NCLS)];
    __syncthreads();
    int gidx = blockIdx.x * 128 + tid;
    int b = gidx >> 8, i = gidx & 255;
    const float* Bp = Bprob + (size_t)b * Nn * NCLS;
    int t0 = i - (BAND - 1); if (t0 < 0) t0 = 0;
    float p[NCLS]; float s = 0.f;
#pragma unroll
    for (int r = 0; r < NCLS; r++) { p[r] = Bp[t0 * NCLS + r]; s += p[r]; }
    float inv = 1.0f / s;
#pragma unroll
    for (int r = 0; r < NCLS; r++) p[r] *= inv;
    for (int t = t0 + 1; t <= i; t++) {
        float q[NCLS]; s = 0.f;
#pragma unroll
        for (int r = 0; r < NCLS; r++) {
            float a = 0.f;
#pragma unroll
            for (int c = 0; c < NCLS; c++) a += sAT[r * NCLS + c] * p[c];
            a *= Bp[t * NCLS + r];
            q[r] = a; s += a;
        }
        inv = 1.0f / s;
#pragma unroll
        for (int r = 0; r < NCLS; r++) p[r] = q[r] * inv;
    }
#pragma unroll
    for (int r = 0; r < NCLS; r++) out[gidx * NCLS + r] = p[r];
}

__global__ void final_kernel(const float* __restrict__ log_gat,
                             const float* __restrict__ log_hmm,
                             const int* __restrict__ labels,
                             float* __restrict__ outLogits)
{
    int r = blockIdx.x * 256 + threadIdx.x;
    float lg[NCLS];
#pragma unroll
    for (int k = 0; k < NCLS; k++) {
        lg[k] = logf(0.5f * (log_gat[r * NCLS + k] + log_hmm[r * NCLS + k]));
        outLogits[r * NCLS + k] = lg[k];
    }
    int lab = labels[r];
    float picked = (lab >= 0) ? lg[lab] : 0.f;
    for (int o = 16; o > 0; o >>= 1) picked += __shfl_down_sync(0xffffffffu, picked, o);
    __shared__ float sh[8];
    if ((threadIdx.x & 31) == 0) sh[threadIdx.x >> 5] = picked;
    __syncthreads();
    if (threadIdx.x == 0) {
        float s = 0.f;
        for (int k = 0; k < 8; k++) s += sh[k];
        g_blocksums[blockIdx.x] = s;
    }
}

__global__ void finalize_kernel(float* d_out, int has_loss)
{
    if (has_loss) {
        float s = 0.f;
        for (int k = 0; k < 32; k++) s += g_blocksums[k];
        d_out[0] = -s / (float)ROWS;
    }
}

// ---------------- host launch ----------------
template <typename T>
static T* sym(const void* symbol)
{
    void* p = nullptr;
    cudaGetSymbolAddress(&p, symbol);
    return (T*)p;
}

extern "C" void kernel_launch(void* const* d_in, const int* in_sizes, int n_in,
                              void* d_out, int out_size)
{
    (void)in_sizes; (void)n_in;
    const float* hidden_cls = (const float*)d_in[0];
    const float* hidden_emo = (const float*)d_in[1];
    const int*   labels     = (const int*)d_in[3];
    const float* pooler_W   = (const float*)d_in[4];
    const float* pooler_b   = (const float*)d_in[5];
    const float* gat_W      = (const float*)d_in[6];
    const float* gat_a1     = (const float*)d_in[7];
    const float* gat_a2     = (const float*)d_in[8];
    const float* out_W      = (const float*)d_in[9];
    const float* out_a1     = (const float*)d_in[10];
    const float* out_a2     = (const float*)d_in[11];
    const float* lin1_W     = (const float*)d_in[12];
    const float* lin1_b     = (const float*)d_in[13];
    const float* lin0_W     = (const float*)d_in[14];
    const float* lin0_b     = (const float*)d_in[15];
    const float* cls_W      = (const float*)d_in[16];
    const float* cls_b      = (const float*)d_in[17];
    const float* hmm_A      = (const float*)d_in[18];

    float* s1b     = sym<float>(g_s1b);
    float* s2b     = sym<float>(g_s2b);
    float* loggat  = sym<float>(g_loggat);
    float* Bprob   = sym<float>(g_Bprob);
    float* loghmm  = sym<float>(g_loghmm);
    float* u0part  = sym<float>(g_u0part);
    bf16* hidcbf   = sym<bf16>(g_hid_cls_bf);
    bf16* hidebf   = sym<bf16>(g_hid_emo_bf);
    bf16* feacbf   = sym<bf16>(g_fea_cls_bf);
    bf16* feaebf   = sym<bf16>(g_fea_emo_bf);
    bf16* Whbf     = sym<bf16>(g_Wh_bf);
    bf16* Wh2bf    = sym<bf16>(g_Wh2_bf);
    bf16* h1bf     = sym<bf16>(g_h1_bf);
    bf16* h2bf     = sym<bf16>(g_h2_bf);
    bf16* poolWt   = sym<bf16>(g_poolWt);
    bf16* Wgt      = sym<bf16>(g_Wgt);
    bf16* outWt    = sym<bf16>(g_outWt);
    float* U0t     = sym<float>(g_U0t);
    float* U1t     = sym<float>(g_U1t);
    float* U2t     = sym<float>(g_U2t);
    float* cvec    = sym<float>(g_cvec);

    cudaFuncSetAttribute(mma_gemm, cudaFuncAttributeMaxDynamicSharedMemorySize, GEMM_SMEM);

    int has_loss = (out_size == ROWS * NCLS + 1) ? 1 : 0;
    float* outLogits = has_loss ? ((float*)d_out + 1) : (float*)d_out;

    // side streams + events (created once; captured work identical each call)
    static cudaStream_t sPrep = nullptr, sHmm = nullptr;
    static cudaEvent_t eFork = nullptr, eWgt = nullptr, eTab = nullptr,
                       eTrans = nullptr, eCvt = nullptr, ePoolC = nullptr,
                       ePart = nullptr, eWh = nullptr, eMean = nullptr,
                       eWh2 = nullptr, eScore = nullptr, eHmm = nullptr;
    if (!sPrep) {
        cudaStreamCreateWithFlags(&sPrep, cudaStreamNonBlocking);
        cudaStreamCreateWithFlags(&sHmm, cudaStreamNonBlocking);
        cudaEventCreateWithFlags(&eFork, cudaEventDisableTiming);
        cudaEventCreateWithFlags(&eWgt, cudaEventDisableTiming);
        cudaEventCreateWithFlags(&eTab, cudaEventDisableTiming);
        cudaEventCreateWithFlags(&eTrans, cudaEventDisableTiming);
        cudaEventCreateWithFlags(&eCvt, cudaEventDisableTiming);
        cudaEventCreateWithFlags(&ePoolC, cudaEventDisableTiming);
        cudaEventCreateWithFlags(&ePart, cudaEventDisableTiming);
        cudaEventCreateWithFlags(&eWh, cudaEventDisableTiming);
        cudaEventCreateWithFlags(&eMean, cudaEventDisableTiming);
        cudaEventCreateWithFlags(&eWh2, cudaEventDisableTiming);
        cudaEventCreateWithFlags(&eScore, cudaEventDisableTiming);
        cudaEventCreateWithFlags(&eHmm, cudaEventDisableTiming);
    }
    cudaStream_t s0 = 0;
    dim3 tblk(32, 8);

    // ---- fork ----
    cudaEventRecord(eFork, s0);
    cudaStreamWaitEvent(sPrep, eFork, 0);
    cudaStreamWaitEvent(sHmm, eFork, 0);

    // ---- prep stream: weights + tables ----
    repack_gatWt_kernel<<<(Hh * Hh) / 256, 256, 0, sPrep>>>(gat_W, Wgt);
    cudaEventRecord(eWgt, sPrep);
    transpose_bf_kernel<<<dim3(Hh / 32, Hh / 32), tblk, 0, sPrep>>>(out_W, outWt);
    fold_u_kernel<<<2 * Hh, 224, 0, sPrep>>>(lin0_W, cls_W, U0t, U1t);
    fold_u2_kernel<<<Hh, 224, 0, sPrep>>>(lin1_W, U1t, U2t);
    fold_cvec_kernel<<<1, 224, 0, sPrep>>>(lin0_b, lin1_b, cls_W, cls_b, U1t, cvec);
    cudaEventRecord(eTab, sPrep);

    // ---- HMM stream: cvt_cls early (concurrent with poolW transpose) ----
    cvt_bf_kernel<<<ROWS * Hh / 1024, 256, 0, sHmm>>>(hidden_cls, hidcbf);
    cudaEventRecord(eCvt, sHmm);

    // ---- main chain ----
    transpose_bf_kernel<<<dim3(Hh / 32, Hh / 32), tblk, 0, s0>>>(pooler_W, poolWt);
    cudaEventRecord(eTrans, s0);       // poolWt ready -> emo branch may start
    cudaStreamWaitEvent(s0, eCvt, 0);
    mma_gemm<<<dim3(Hh / BN, ROWS / BM), 256, GEMM_SMEM, s0>>>(
        hidcbf, feacbf, poolWt, pooler_b, 1, Hh / BKg);
    cudaEventRecord(ePoolC, s0);

    // ---- emo/HMM branch on sHmm (off the critical path) ----
    cudaStreamWaitEvent(sHmm, eTrans, 0);
    cvt_bf_kernel<<<ROWS * Hh / 1024, 256, 0, sHmm>>>(hidden_emo, hidebf);
    mma_gemm<<<dim3(Hh / BN, ROWS / BM), 256, GEMM_SMEM, sHmm>>>(
        hidebf, feaebf, poolWt, pooler_b, 1, Hh / BKg);
    cls_softmax_kernel<<<ROWS, 224, 0, sHmm>>>(feaebf, cls_W, cls_b, Bprob);
    hmm_kernel<<<ROWS / 128, 128, 0, sHmm>>>(Bprob, hmm_A, loghmm);
    cudaEventRecord(eHmm, sHmm);

    // ---- u0 partial on sPrep (off the critical path) ----
    cudaStreamWaitEvent(sPrep, ePoolC, 0);
    u0part_kernel<<<ROWS, 224, 0, sPrep>>>(feacbf, U0t, u0part);

    // ---- GAT chain on s0 ----
    cudaStreamWaitEvent(s0, eWgt, 0);
    mma_gemm<<<dim3(Hh / BN, ROWS / BM), 256, GEMM_SMEM, s0>>>(
        feacbf, Whbf, Wgt, nullptr, 0, Hh / BKg);
    cudaEventRecord(eWh, s0);
    att1_tile_kernel<<<dim3(8, 8, Bc), 128, 0, s0>>>(Whbf, gat_a1, gat_a2, h1bf);

    // mean_row0 concurrent with att1 on sPrep (disjoint h1 rows)
    cudaStreamWaitEvent(sPrep, eWh, 0);
    mean_row0_kernel<<<dim3(Hh / 256, Bc), 256, 0, sPrep>>>(Whbf, h1bf);
    cudaEventRecord(eMean, sPrep);
    cudaEventRecord(ePart, sPrep);     // ePart also covers u0part (ordered on sPrep)

    cudaStreamWaitEvent(s0, eTab, 0);      // outWt + U tables ready
    cudaStreamWaitEvent(s0, eMean, 0);     // h1 row 0 ready
    mma_gemm<<<dim3(Hh / BN, ROWS / BM), 256, GEMM_SMEM, s0>>>(
        h1bf, Wh2bf, outWt, nullptr, 0, Hh / BKg);
    cudaEventRecord(eWh2, s0);

    // out_scores on sHmm (idle after hmm) -> fills gemm3's wave tail
    cudaStreamWaitEvent(sHmm, eWh2, 0);
    out_scores_kernel<<<ROWS, 256, 0, sHmm>>>(Wh2bf, out_a1, out_a2, s1b, s2b);
    cudaEventRecord(eScore, sHmm);

    cudaStreamWaitEvent(s0, eScore, 0);
    att2_tile_kernel<<<dim3(8, 8, Bc), 128, 0, s0>>>(Wh2bf, s1b, s2b, h2bf);

    cudaStreamWaitEvent(s0, ePart, 0);
    gat_logits_kernel<<<ROWS, 224, 0, s0>>>(feacbf, h2bf, u0part, U2t, cvec, loggat);

    // ---- join HMM branch, final ----
    cudaStreamWaitEvent(s0, eHmm, 0);
    final_kernel<<<ROWS / 256, 256, 0, s0>>>(loggat, loghmm, labels, outLogits);
    finalize_kernel<<<1, 1, 0, s0>>>((float*)d_out, has_loss);
}

// round 17
// speedup vs baseline: 1.3311x; 1.0185x over previous
#include <cuda_runtime.h>
#include <cuda_bf16.h>
#include <math.h>
#include <stdint.h>

// Problem constants
#define Bc   32
#define Nn   256
#define Hh   1024
#define HEADS 8
#define NHID 128
#define NCLS 7
#define BAND 24
#define ROWS (Bc*Nn)          // 8192
#define ALPHA_LRELU 0.2f

typedef __nv_bfloat16 bf16;

// ---------------- device scratch (no allocs allowed) ----------------
__device__ float g_s1b[ROWS];
__device__ float g_s2b[ROWS];
__device__ float g_va1[Hh];
__device__ float g_va2[Hh];
__device__ float g_loggat[ROWS*NCLS];
__device__ float g_Bprob[ROWS*NCLS];
__device__ float g_loghmm[ROWS*NCLS];
__device__ float g_u0part[ROWS*NCLS];
__device__ float g_blocksums[32];
// bf16 tensors
__device__ bf16 g_hid_cls_bf[ROWS*Hh];
__device__ bf16 g_hid_emo_bf[ROWS*Hh];
__device__ bf16 g_fea_cls_bf[ROWS*Hh];
__device__ bf16 g_fea_emo_bf[ROWS*Hh];
__device__ bf16 g_Wh_bf[ROWS*Hh];
__device__ bf16 g_Wh2_bf[ROWS*Hh];
__device__ bf16 g_h1_bf[ROWS*Hh];
__device__ bf16 g_h2_bf[ROWS*Hh];
__device__ bf16 g_poolWt[Hh*Hh];   // [N][K] k-major
__device__ bf16 g_Wgt[Hh*Hh];
__device__ bf16 g_outWt[Hh*Hh];
// folded classifier tables ([7][1024] row-major)
__device__ float g_U0t[NCLS*Hh];
__device__ float g_U1t[NCLS*Hh];
__device__ float g_U2t[NCLS*Hh];
__device__ float g_cvec[NCLS];

// =================== bf16 mma.sync GEMM (4-stage cp.async pipeline) ==========
#define BM 128
#define BN 128
#define BKg 32
#define GSTG 4
#define APITCH 40                             // halves per smem row (80 B)
#define STAGE_BYTES (2 * BM * APITCH * 2)     // A + B = 20480 B
#define GEMM_SMEM (GSTG * STAGE_BYTES)        // 81920 B

__device__ __forceinline__ uint32_t smem_u32(const void* p) {
    uint32_t a;
    asm("{ .reg .u64 t; cvta.to.shared.u64 t, %1; cvt.u32.u64 %0, t; }" : "=r"(a) : "l"(p));
    return a;
}
__device__ __forceinline__ void cp16(uint32_t s, const void* g) {
    asm volatile("cp.async.cg.shared.global [%0], [%1], 16;" :: "r"(s), "l"(g));
}
#define CP_COMMIT() asm volatile("cp.async.commit_group;" ::: "memory")
#define CP_WAIT2()  asm volatile("cp.async.wait_group 2;" ::: "memory")

__device__ __forceinline__ void ldsm4(uint32_t& r0, uint32_t& r1, uint32_t& r2, uint32_t& r3,
                                      uint32_t addr) {
    asm volatile("ldmatrix.sync.aligned.m8n8.x4.shared.b16 {%0,%1,%2,%3}, [%4];"
                 : "=r"(r0), "=r"(r1), "=r"(r2), "=r"(r3) : "r"(addr));
}
__device__ __forceinline__ void mma_bf16(float& d0, float& d1, float& d2, float& d3,
                                         uint32_t a0, uint32_t a1, uint32_t a2, uint32_t a3,
                                         uint32_t b0, uint32_t b1) {
    asm volatile("mma.sync.aligned.m16n8k16.row.col.f32.bf16.bf16.f32 "
                 "{%0,%1,%2,%3}, {%4,%5,%6,%7}, {%8,%9}, {%0,%1,%2,%3};"
                 : "+f"(d0), "+f"(d1), "+f"(d2), "+f"(d3)
                 : "r"(a0), "r"(a1), "r"(a2), "r"(a3), "r"(b0), "r"(b1));
}

__device__ __forceinline__ void gemm_load_stage(uint32_t sb, int stage, int tid,
                                                const bf16* Ag, const bf16* Bg) {
    uint32_t abase = sb + stage * STAGE_BYTES;
    uint32_t bbase = abase + BM * APITCH * 2;
#pragma unroll
    for (int i = 0; i < 2; i++) {
        int idx = tid + 256 * i;
        int r = idx >> 2;
        int q = idx & 3;
        cp16(abase + r * (APITCH * 2) + q * 16, Ag + (size_t)r * Hh + q * 8);
        cp16(bbase + r * (APITCH * 2) + q * 16, Bg + (size_t)r * Hh + q * 8);
    }
}

__global__ void __launch_bounds__(256, 2)
mma_gemm(const bf16* __restrict__ A, bf16* __restrict__ C,
         const bf16* __restrict__ Bt,
         const float* __restrict__ bias, int dotanh, int T)
{
    extern __shared__ char smem[];
    uint32_t sb = smem_u32(smem);
    const int tid = threadIdx.x;
    const int wid = tid >> 5, lane = tid & 31;
    const int wm = wid >> 2, wn = wid & 3;   // 2x4 warp grid, warp tile 64x32
    const int n0 = blockIdx.x * BN;
    const size_t m0 = (size_t)blockIdx.y * BM;

    float acc[4][4][4];
#pragma unroll
    for (int mi = 0; mi < 4; mi++)
#pragma unroll
        for (int ni = 0; ni < 4; ni++)
#pragma unroll
            for (int k = 0; k < 4; k++) acc[mi][ni][k] = 0.f;

    const bf16* Arow = A + m0 * Hh;
    const bf16* Brow = Bt + (size_t)n0 * Hh;

    gemm_load_stage(sb, 0, tid, Arow, Brow);
    CP_COMMIT();
    gemm_load_stage(sb, 1, tid, Arow + BKg, Brow + BKg);
    CP_COMMIT();
    gemm_load_stage(sb, 2, tid, Arow + 2 * BKg, Brow + 2 * BKg);
    CP_COMMIT();

    const int tl = lane >> 3;          // ldmatrix tile selector
    const int l7 = lane & 7;

    for (int t = 0; t < T; t++) {
        CP_WAIT2();
        __syncthreads();
        int nc = t + 3;
        if (nc < T)
            gemm_load_stage(sb, nc % GSTG, tid, Arow + nc * BKg, Brow + nc * BKg);
        CP_COMMIT();   // always commit to keep group counting sound

        uint32_t sA = sb + (t % GSTG) * STAGE_BYTES;
        uint32_t sB = sA + BM * APITCH * 2;
#pragma unroll
        for (int ks = 0; ks < 2; ks++) {
            uint32_t a[4][4];
#pragma unroll
            for (int mi = 0; mi < 4; mi++) {
                int row = wm * 64 + mi * 16 + (tl & 1) * 8 + l7;
                int col = ks * 16 + (tl >> 1) * 8;
                ldsm4(a[mi][0], a[mi][1], a[mi][2], a[mi][3],
                      sA + row * (APITCH * 2) + col * 2);
            }
            uint32_t bq[2][4];
#pragma unroll
            for (int nn = 0; nn < 2; nn++) {
                int row = wn * 32 + nn * 16 + (tl >> 1) * 8 + l7;
                int col = ks * 16 + (tl & 1) * 8;
                ldsm4(bq[nn][0], bq[nn][1], bq[nn][2], bq[nn][3],
                      sB + row * (APITCH * 2) + col * 2);
            }
#pragma unroll
            for (int mi = 0; mi < 4; mi++)
#pragma unroll
                for (int ni = 0; ni < 4; ni++)
                    mma_bf16(acc[mi][ni][0], acc[mi][ni][1], acc[mi][ni][2], acc[mi][ni][3],
                             a[mi][0], a[mi][1], a[mi][2], a[mi][3],
                             bq[ni >> 1][(ni & 1) * 2], bq[ni >> 1][(ni & 1) * 2 + 1]);
        }
    }

    const int lq = lane >> 2;
    const int lr = lane & 3;
#pragma unroll
    for (int mi = 0; mi < 4; mi++) {
        int row = (int)m0 + wm * 64 + mi * 16 + lq;
#pragma unroll
        for (int ni = 0; ni < 4; ni++) {
            int col = n0 + wn * 32 + ni * 8 + lr * 2;
            float b0 = 0.f, b1 = 0.f;
            if (bias) { b0 = bias[col]; b1 = bias[col + 1]; }
            float2 v0, v1;
            v0.x = acc[mi][ni][0] + b0; v0.y = acc[mi][ni][1] + b1;
            v1.x = acc[mi][ni][2] + b0; v1.y = acc[mi][ni][3] + b1;
            if (dotanh) {
                v0.x = tanhf(v0.x); v0.y = tanhf(v0.y);
                v1.x = tanhf(v1.x); v1.y = tanhf(v1.y);
            }
            __nv_bfloat162 w0, w1;
            w0.x = __float2bfloat16_rn(v0.x); w0.y = __float2bfloat16_rn(v0.y);
            w1.x = __float2bfloat16_rn(v1.x); w1.y = __float2bfloat16_rn(v1.y);
            *(__nv_bfloat162*)(C + (size_t)row * Hh + col) = w0;
            *(__nv_bfloat162*)(C + (size_t)(row + 8) * Hh + col) = w1;
        }
    }
}

// =================== weight prep / converts ===================
__global__ void transpose_bf_kernel(const float* __restrict__ in, bf16* __restrict__ out)
{
    __shared__ float tile[32][33];
    int k0 = blockIdx.y * 32, n0 = blockIdx.x * 32;
    int tx = threadIdx.x, ty = threadIdx.y;
    for (int r = ty; r < 32; r += 8) tile[r][tx] = in[(size_t)(k0 + r) * Hh + n0 + tx];
    __syncthreads();
    for (int r = ty; r < 32; r += 8)
        out[(size_t)(n0 + r) * Hh + k0 + tx] = __float2bfloat16_rn(tile[tx][r]);
}
__global__ void repack_gatWt_kernel(const float* __restrict__ gw, bf16* __restrict__ Wgt)
{
    int idx = blockIdx.x * 256 + threadIdx.x;
    int n = idx >> 10, f = idx & 1023;
    int h = n >> 7, d = n & 127;
    Wgt[idx] = __float2bfloat16_rn(gw[((size_t)(h << 10 | f)) * NHID + d]);
}
__global__ void cvt_bf_kernel(const float* __restrict__ a, bf16* __restrict__ oa)
{
    int idx = (blockIdx.x * 256 + threadIdx.x) * 4;
    float4 v = *(const float4*)(a + idx);
    __nv_bfloat162 w0, w1;
    w0.x = __float2bfloat16_rn(v.x); w0.y = __float2bfloat16_rn(v.y);
    w1.x = __float2bfloat16_rn(v.z); w1.y = __float2bfloat16_rn(v.w);
    *(__nv_bfloat162*)(oa + idx) = w0;
    *(__nv_bfloat162*)(oa + idx + 2) = w1;
}

__global__ void fold_u_kernel(const float* __restrict__ lin0W,
                              const float* __restrict__ clsW,
                              float* __restrict__ U0t, float* __restrict__ U1t)
{
    int r = blockIdx.x;
    int c = threadIdx.x >> 5, l = threadIdx.x & 31;
    const float* row = lin0W + (size_t)r * Hh;
    float acc = 0.f;
    for (int k = l; k < Hh; k += 32) acc += row[k] * clsW[k * NCLS + c];
    for (int o = 16; o > 0; o >>= 1) acc += __shfl_down_sync(0xffffffffu, acc, o);
    if (l == 0) {
        if (r < Hh) U0t[c * Hh + r] = acc;
        else        U1t[c * Hh + (r - Hh)] = acc;
    }
}
__global__ void fold_u2_kernel(const float* __restrict__ lin1W,
                               const float* __restrict__ U1t,
                               float* __restrict__ U2t)
{
    int r = blockIdx.x;
    int c = threadIdx.x >> 5, l = threadIdx.x & 31;
    const float* row = lin1W + (size_t)r * Hh;
    const float* u1 = U1t + c * Hh;
    float acc = 0.f;
    for (int k = l; k < Hh; k += 32) acc += row[k] * u1[k];
    for (int o = 16; o > 0; o >>= 1) acc += __shfl_down_sync(0xffffffffu, acc, o);
    if (l == 0) U2t[c * Hh + r] = acc;
}
__global__ void fold_cvec_kernel(const float* __restrict__ lin0b,
                                 const float* __restrict__ lin1b,
                                 const float* __restrict__ clsW,
                                 const float* __restrict__ clsb,
                                 const float* __restrict__ U1t,
                                 float* __restrict__ cvec)
{
    int c = threadIdx.x >> 5, l = threadIdx.x & 31;
    float acc = 0.f;
    for (int k = l; k < Hh; k += 32)
        acc += lin0b[k] * clsW[k * NCLS + c] + lin1b[k] * U1t[c * Hh + k];
    for (int o = 16; o > 0; o >>= 1) acc += __shfl_down_sync(0xffffffffu, acc, o);
    if (l == 0) cvec[c] = acc + clsb[c];
}
// va1[r] = out_W[r]·out_a1, va2[r] = out_W[r]·out_a2. grid Hh, 64 threads.
__global__ void fold_va_kernel(const float* __restrict__ outW,
                               const float* __restrict__ a1,
                               const float* __restrict__ a2,
                               float* __restrict__ va1, float* __restrict__ va2)
{
    int r = blockIdx.x;
    int w = threadIdx.x >> 5, l = threadIdx.x & 31;
    const float* row = outW + (size_t)r * Hh;
    const float* a = w ? a2 : a1;
    float acc = 0.f;
    for (int k = l; k < Hh; k += 32) acc += row[k] * a[k];
    for (int o = 16; o > 0; o >>= 1) acc += __shfl_down_sync(0xffffffffu, acc, o);
    if (l == 0) { if (w) va2[r] = acc; else va1[r] = acc; }
}

// =================== small kernels ===================
__device__ __forceinline__ float eluf(float x) { return x > 0.f ? x : expf(x) - 1.0f; }

__global__ void mean_row0_kernel(const bf16* __restrict__ X, bf16* __restrict__ h1)
{
    int b = blockIdx.y;
    int c = blockIdx.x * 256 + threadIdx.x;
    const bf16* p = X + (size_t)b * Nn * Hh + c;
    float s = 0.f;
    for (int n = 0; n < Nn; n++) s += __bfloat162float(p[(size_t)n * Hh]);
    h1[(size_t)b * Nn * Hh + c] = __float2bfloat16_rn(eluf(s * (1.0f / Nn)));
}

__global__ void att1_tile_kernel(const bf16* __restrict__ Wh,
                                 const float* __restrict__ gat_a1,
                                 const float* __restrict__ gat_a2,
                                 bf16* __restrict__ h1)
{
    __shared__ float sW[55][128];
    __shared__ float sc1[55], sc2[55];
    __shared__ float sw[32][24];
    int b = blockIdx.z, h = blockIdx.y, it = blockIdx.x;
    int i0 = it * 32;
    int jlo0 = i0 - 23; if (jlo0 < 0) jlo0 = 0;
    int nrows = (i0 + 31) - jlo0 + 1;          // <= 55
    int tid = threadIdx.x;
    int warp = tid >> 5, lane = tid & 31;
    const bf16* base = Wh + (size_t)b * Nn * Hh + h * NHID;
    for (int rr = 0; rr < nrows; rr++)
        sW[rr][tid] = __bfloat162float(base[(size_t)(jlo0 + rr) * Hh + tid]);
    __syncthreads();
    {
        float a1v[4], a2v[4];
#pragma unroll
        for (int t = 0; t < 4; t++) {
            a1v[t] = gat_a1[h * NHID + lane + 32 * t];
            a2v[t] = gat_a2[h * NHID + lane + 32 * t];
        }
        for (int rr = warp; rr < nrows; rr += 4) {
            float d1 = 0.f, d2 = 0.f;
#pragma unroll
            for (int t = 0; t < 4; t++) {
                float v = sW[rr][lane + 32 * t];
                d1 += v * a1v[t];
                d2 += v * a2v[t];
            }
            for (int o = 16; o > 0; o >>= 1) {
                d1 += __shfl_down_sync(0xffffffffu, d1, o);
                d2 += __shfl_down_sync(0xffffffffu, d2, o);
            }
            if (lane == 0) { sc1[rr] = d1; sc2[rr] = d2; }
        }
    }
    __syncthreads();
    if (tid < 32) {
        int i = i0 + tid;
        if (i > 0) {
            int jl = i - 23; if (jl < 0) jl = 0;
            int L = i - jl;
            float si = sc1[i - jlo0];
            float mx = -1e30f;
            for (int t = 0; t < L; t++) {
                float v = si + sc2[jl + t - jlo0];
                v = v > 0.f ? v : ALPHA_LRELU * v;
                sw[tid][t] = v; mx = fmaxf(mx, v);
            }
            float ssum = 0.f;
            for (int t = 0; t < L; t++) { float ex = expf(sw[tid][t] - mx); sw[tid][t] = ex; ssum += ex; }
            float inv = 1.0f / ssum;
            for (int t = 0; t < L; t++) sw[tid][t] *= inv;
        }
    }
    __syncthreads();
    for (int il = 0; il < 32; il++) {
        int i = i0 + il;
        if (i == 0) continue;
        int jl = i - 23; if (jl < 0) jl = 0;
        int L = i - jl, roff = jl - jlo0;
        float acc = 0.f;
        for (int t = 0; t < L; t++) acc += sw[il][t] * sW[roff + t][tid];
        h1[((size_t)b * Nn + i) * Hh + h * NHID + tid] = __float2bfloat16_rn(eluf(acc));
    }
}

// scores from h1: s1b[n] = h1[n]·va1, s2b[n] = h1[n]·va2 (concurrent with gemm3)
__global__ void h1_scores_kernel(const bf16* __restrict__ h1,
                                 const float* __restrict__ va1,
                                 const float* __restrict__ va2,
                                 float* __restrict__ s1, float* __restrict__ s2)
{
    int n = blockIdx.x;
    int tid = threadIdx.x;
    float x1 = 0.f, x2 = 0.f;
    const bf16* x = h1 + (size_t)n * Hh;
    for (int c = tid; c < Hh; c += 256) {
        float v = __bfloat162float(x[c]);
        x1 += v * va1[c]; x2 += v * va2[c];
    }
    __shared__ float sh1[8], sh2[8];
    for (int o = 16; o > 0; o >>= 1) {
        x1 += __shfl_down_sync(0xffffffffu, x1, o);
        x2 += __shfl_down_sync(0xffffffffu, x2, o);
    }
    if ((tid & 31) == 0) { sh1[tid >> 5] = x1; sh2[tid >> 5] = x2; }
    __syncthreads();
    if (tid == 0) {
        float t1 = 0.f, t2 = 0.f;
        for (int k = 0; k < 8; k++) { t1 += sh1[k]; t2 += sh2[k]; }
        s1[n] = t1; s2[n] = t2;
    }
}

__global__ void att2_tile_kernel(const bf16* __restrict__ Wh2,
                                 const float* __restrict__ s1,
                                 const float* __restrict__ s2,
                                 bf16* __restrict__ out)
{
    __shared__ float sW[54][128];
    __shared__ float sw[32][24];
    int b = blockIdx.z, ct = blockIdx.y, it = blockIdx.x;
    int i0 = it * 32, c0 = ct * 128;
    int jlo0 = i0 - 23; if (jlo0 < 0) jlo0 = 0;
    int nrows = (i0 + 30) - jlo0 + 1;
    int tid = threadIdx.x;
    const bf16* base = Wh2 + (size_t)b * Nn * Hh + c0;
    for (int rr = 0; rr < nrows; rr++)
        sW[rr][tid] = __bfloat162float(base[(size_t)(jlo0 + rr) * Hh + tid]);
    if (tid < 32) {
        int i = i0 + tid;
        if (i > 0) {
            int jl = i - 23; if (jl < 0) jl = 0;
            int L = i - jl;
            float si = s1[(size_t)b * Nn + i];
            float mx = -1e30f;
            for (int t = 0; t < L; t++) {
                float v = si + s2[(size_t)b * Nn + jl + t];
                v = v > 0.f ? v : ALPHA_LRELU * v;
                sw[tid][t] = v; mx = fmaxf(mx, v);
            }
            float ssum = 0.f;
            for (int t = 0; t < L; t++) { float ex = expf(sw[tid][t] - mx); sw[tid][t] = ex; ssum += ex; }
            float inv = 1.0f / ssum;
            for (int t = 0; t < L; t++) sw[tid][t] *= inv;
        }
    }
    __syncthreads();
    for (int il = 0; il < 32; il++) {
        int i = i0 + il;
        if (i == 0) continue;
        int jl = i - 23; if (jl < 0) jl = 0;
        int L = i - jl, roff = jl - jlo0;
        float acc = 0.f;
        for (int t = 0; t < L; t++) acc += sw[il][t] * sW[roff + t][tid];
        out[((size_t)b * Nn + i) * Hh + c0 + tid] = __float2bfloat16_rn(eluf(acc));
    }
}

// part A: u0part[n][c] = fea_cls[n]·U0t[c]  (off critical path)
__global__ void u0part_kernel(const bf16* __restrict__ fea_cls,
                              const float* __restrict__ U0t,
                              float* __restrict__ part)
{
    int n = blockIdx.x;
    int c = threadIdx.x >> 5, l = threadIdx.x & 31;
    const bf16* frow = fea_cls + (size_t)n * Hh;
    const float* u0 = U0t + c * Hh;
    float acc = 0.f;
    for (int k = l; k < Hh; k += 32)
        acc += __bfloat162float(frow[k]) * u0[k];
    for (int o = 16; o > 0; o >>= 1) acc += __shfl_down_sync(0xffffffffu, acc, o);
    if (l == 0) part[n * NCLS + c] = acc;
}

// part B: loggat = softmax(u0part + hrow·U2 + cvec)
__global__ void gat_logits_kernel(const bf16* __restrict__ fea_cls,
                                  const bf16* __restrict__ h2,
                                  const float* __restrict__ part,
                                  const float* __restrict__ U2t,
                                  const float* __restrict__ cvec,
                                  float* __restrict__ out)
{
    int n = blockIdx.x;
    int i = n & (Nn - 1);
    int c = threadIdx.x >> 5, l = threadIdx.x & 31;
    const bf16* hrow = (i == 0) ? fea_cls + (size_t)n * Hh : h2 + (size_t)n * Hh;
    const float* u2 = U2t + c * Hh;
    float acc = 0.f;
    for (int k = l; k < Hh; k += 32)
        acc += __bfloat162float(hrow[k]) * u2[k];
    for (int o = 16; o > 0; o >>= 1) acc += __shfl_down_sync(0xffffffffu, acc, o);
    __shared__ float sh[NCLS];
    if (l == 0) sh[c] = acc + part[n * NCLS + c] + cvec[c];
    __syncthreads();
    if (threadIdx.x == 0) {
        float mx = sh[0];
        for (int k = 1; k < NCLS; k++) mx = fmaxf(mx, sh[k]);
        float e[NCLS], s = 0.f;
        for (int k = 0; k < NCLS; k++) { e[k] = expf(sh[k] - mx); s += e[k]; }
        float inv = 1.0f / s;
        for (int k = 0; k < NCLS; k++) out[n * NCLS + k] = e[k] * inv;
    }
}

__global__ void cls_softmax_kernel(const bf16* __restrict__ X,
                                   const float* __restrict__ W,
                                   const float* __restrict__ bcls,
                                   float* __restrict__ out)
{
    int n = blockIdx.x;
    int wid = threadIdx.x >> 5, l = threadIdx.x & 31;
    __shared__ float sh[NCLS];
    const bf16* x = X + (size_t)n * Hh;
    float acc = 0.f;
    for (int t = l; t < Hh; t += 32) acc += __bfloat162float(x[t]) * W[t * NCLS + wid];
    for (int o = 16; o > 0; o >>= 1) acc += __shfl_down_sync(0xffffffffu, acc, o);
    if (l == 0) sh[wid] = acc + bcls[wid];
    __syncthreads();
    if (threadIdx.x == 0) {
        float mx = sh[0];
        for (int k = 1; k < NCLS; k++) mx = fmaxf(mx, sh[k]);
        float e[NCLS], s = 0.f;
        for (int k = 0; k < NCLS; k++) { e[k] = expf(sh[k] - mx); s += e[k]; }
        float inv = 1.0f / s;
        for (int k = 0; k < NCLS; k++) out[n * NCLS + k] = e[k] * inv;
    }
}

__global__ void hmm_kernel(const float* __restrict__ Bprob,
                           const float* __restrict__ hmmA,
                           float* __restrict__ out)
{
    __shared__ float sAT[NCLS * NCLS];
    int tid = threadIdx.x;
    if (tid < NCLS * NCLS) sAT[tid] = hmmA[(tid % NCLS) * NCLS + (tid / NCLS)];
    __syncthreads();
    int gidx = blockIdx.x * 128 + tid;
    int b = gidx >> 8, i = gidx & 255;
    const float* Bp = Bprob + (size_t)b * Nn * NCLS;
    int t0 = i - (BAND - 1); if (t0 < 0) t0 = 0;
    float p[NCLS]; float s = 0.f;
#pragma unroll
    for (int r = 0; r < NCLS; r++) { p[r] = Bp[t0 * NCLS + r]; s += p[r]; }
    float inv = 1.0f / s;
#pragma unroll
    for (int r = 0; r < NCLS; r++) p[r] *= inv;
    for (int t = t0 + 1; t <= i; t++) {
        float q[NCLS]; s = 0.f;
#pragma unroll
        for (int r = 0; r < NCLS; r++) {
            float a = 0.f;
#pragma unroll
            for (int c = 0; c < NCLS; c++) a += sAT[r * NCLS + c] * p[c];
            a *= Bp[t * NCLS + r];
            q[r] = a; s += a;
        }
        inv = 1.0f / s;
#pragma unroll
        for (int r = 0; r < NCLS; r++) p[r] = q[r] * inv;
    }
#pragma unroll
    for (int r = 0; r < NCLS; r++) out[gidx * NCLS + r] = p[r];
}

__global__ void final_kernel(const float* __restrict__ log_gat,
                             const float* __restrict__ log_hmm,
                             const int* __restrict__ labels,
                             float* __restrict__ outLogits)
{
    int r = blockIdx.x * 256 + threadIdx.x;
    float lg[NCLS];
#pragma unroll
    for (int k = 0; k < NCLS; k++) {
        lg[k] = logf(0.5f * (log_gat[r * NCLS + k] + log_hmm[r * NCLS + k]));
        outLogits[r * NCLS + k] = lg[k];
    }
    int lab = labels[r];
    float picked = (lab >= 0) ? lg[lab] : 0.f;
    for (int o = 16; o > 0; o >>= 1) picked += __shfl_down_sync(0xffffffffu, picked, o);
    __shared__ float sh[8];
    if ((threadIdx.x & 31) == 0) sh[threadIdx.x >> 5] = picked;
    __syncthreads();
    if (threadIdx.x == 0) {
        float s = 0.f;
        for (int k = 0; k < 8; k++) s += sh[k];
        g_blocksums[blockIdx.x] = s;
    }
}

__global__ void finalize_kernel(float* d_out, int has_loss)
{
    if (has_loss) {
        float s = 0.f;
        for (int k = 0; k < 32; k++) s += g_blocksums[k];
        d_out[0] = -s / (float)ROWS;
    }
}

// ---------------- host launch ----------------
template <typename T>
static T* sym(const void* symbol)
{
    void* p = nullptr;
    cudaGetSymbolAddress(&p, symbol);
    return (T*)p;
}

extern "C" void kernel_launch(void* const* d_in, const int* in_sizes, int n_in,
                              void* d_out, int out_size)
{
    (void)in_sizes; (void)n_in;
    const float* hidden_cls = (const float*)d_in[0];
    const float* hidden_emo = (const float*)d_in[1];
    const int*   labels     = (const int*)d_in[3];
    const float* pooler_W   = (const float*)d_in[4];
    const float* pooler_b   = (const float*)d_in[5];
    const float* gat_W      = (const float*)d_in[6];
    const float* gat_a1     = (const float*)d_in[7];
    const float* gat_a2     = (const float*)d_in[8];
    const float* out_W      = (const float*)d_in[9];
    const float* out_a1     = (const float*)d_in[10];
    const float* out_a2     = (const float*)d_in[11];
    const float* lin1_W     = (const float*)d_in[12];
    const float* lin1_b     = (const float*)d_in[13];
    const float* lin0_W     = (const float*)d_in[14];
    const float* lin0_b     = (const float*)d_in[15];
    const float* cls_W      = (const float*)d_in[16];
    const float* cls_b      = (const float*)d_in[17];
    const float* hmm_A      = (const float*)d_in[18];

    float* s1b     = sym<float>(g_s1b);
    float* s2b     = sym<float>(g_s2b);
    float* va1     = sym<float>(g_va1);
    float* va2     = sym<float>(g_va2);
    float* loggat  = sym<float>(g_loggat);
    float* Bprob   = sym<float>(g_Bprob);
    float* loghmm  = sym<float>(g_loghmm);
    float* u0part  = sym<float>(g_u0part);
    bf16* hidcbf   = sym<bf16>(g_hid_cls_bf);
    bf16* hidebf   = sym<bf16>(g_hid_emo_bf);
    bf16* feacbf   = sym<bf16>(g_fea_cls_bf);
    bf16* feaebf   = sym<bf16>(g_fea_emo_bf);
    bf16* Whbf     = sym<bf16>(g_Wh_bf);
    bf16* Wh2bf    = sym<bf16>(g_Wh2_bf);
    bf16* h1bf     = sym<bf16>(g_h1_bf);
    bf16* h2bf     = sym<bf16>(g_h2_bf);
    bf16* poolWt   = sym<bf16>(g_poolWt);
    bf16* Wgt      = sym<bf16>(g_Wgt);
    bf16* outWt    = sym<bf16>(g_outWt);
    float* U0t     = sym<float>(g_U0t);
    float* U1t     = sym<float>(g_U1t);
    float* U2t     = sym<float>(g_U2t);
    float* cvec    = sym<float>(g_cvec);

    cudaFuncSetAttribute(mma_gemm, cudaFuncAttributeMaxDynamicSharedMemorySize, GEMM_SMEM);

    int has_loss = (out_size == ROWS * NCLS + 1) ? 1 : 0;
    float* outLogits = has_loss ? ((float*)d_out + 1) : (float*)d_out;

    // side streams + events (created once; captured work identical each call)
    static cudaStream_t sPrep = nullptr, sHmm = nullptr;
    static cudaEvent_t eFork = nullptr, eWgt = nullptr, eTab = nullptr,
                       eTrans = nullptr, eCvt = nullptr, ePoolC = nullptr,
                       ePart = nullptr, eWh = nullptr, eMean = nullptr,
                       eAtt1 = nullptr, eScore = nullptr, eHmm = nullptr;
    if (!sPrep) {
        cudaStreamCreateWithFlags(&sPrep, cudaStreamNonBlocking);
        cudaStreamCreateWithFlags(&sHmm, cudaStreamNonBlocking);
        cudaEventCreateWithFlags(&eFork, cudaEventDisableTiming);
        cudaEventCreateWithFlags(&eWgt, cudaEventDisableTiming);
        cudaEventCreateWithFlags(&eTab, cudaEventDisableTiming);
        cudaEventCreateWithFlags(&eTrans, cudaEventDisableTiming);
        cudaEventCreateWithFlags(&eCvt, cudaEventDisableTiming);
        cudaEventCreateWithFlags(&ePoolC, cudaEventDisableTiming);
        cudaEventCreateWithFlags(&ePart, cudaEventDisableTiming);
        cudaEventCreateWithFlags(&eWh, cudaEventDisableTiming);
        cudaEventCreateWithFlags(&eMean, cudaEventDisableTiming);
        cudaEventCreateWithFlags(&eAtt1, cudaEventDisableTiming);
        cudaEventCreateWithFlags(&eScore, cudaEventDisableTiming);
        cudaEventCreateWithFlags(&eHmm, cudaEventDisableTiming);
    }
    cudaStream_t s0 = 0;
    dim3 tblk(32, 8);

    // ---- fork ----
    cudaEventRecord(eFork, s0);
    cudaStreamWaitEvent(sPrep, eFork, 0);
    cudaStreamWaitEvent(sHmm, eFork, 0);

    // ---- prep stream: weights + tables ----
    repack_gatWt_kernel<<<(Hh * Hh) / 256, 256, 0, sPrep>>>(gat_W, Wgt);
    cudaEventRecord(eWgt, sPrep);
    transpose_bf_kernel<<<dim3(Hh / 32, Hh / 32), tblk, 0, sPrep>>>(out_W, outWt);
    fold_va_kernel<<<Hh, 64, 0, sPrep>>>(out_W, out_a1, out_a2, va1, va2);
    fold_u_kernel<<<2 * Hh, 224, 0, sPrep>>>(lin0_W, cls_W, U0t, U1t);
    fold_u2_kernel<<<Hh, 224, 0, sPrep>>>(lin1_W, U1t, U2t);
    fold_cvec_kernel<<<1, 224, 0, sPrep>>>(lin0_b, lin1_b, cls_W, cls_b, U1t, cvec);
    cudaEventRecord(eTab, sPrep);

    // ---- HMM stream: cvt_cls early (concurrent with poolW transpose) ----
    cvt_bf_kernel<<<ROWS * Hh / 1024, 256, 0, sHmm>>>(hidden_cls, hidcbf);
    cudaEventRecord(eCvt, sHmm);

    // ---- main chain ----
    transpose_bf_kernel<<<dim3(Hh / 32, Hh / 32), tblk, 0, s0>>>(pooler_W, poolWt);
    cudaEventRecord(eTrans, s0);       // poolWt ready -> emo branch may start
    cudaStreamWaitEvent(s0, eCvt, 0);
    mma_gemm<<<dim3(Hh / BN, ROWS / BM), 256, GEMM_SMEM, s0>>>(
        hidcbf, feacbf, poolWt, pooler_b, 1, Hh / BKg);
    cudaEventRecord(ePoolC, s0);

    // ---- emo/HMM branch on sHmm (off the critical path) ----
    cudaStreamWaitEvent(sHmm, eTrans, 0);
    cvt_bf_kernel<<<ROWS * Hh / 1024, 256, 0, sHmm>>>(hidden_emo, hidebf);
    mma_gemm<<<dim3(Hh / BN, ROWS / BM), 256, GEMM_SMEM, sHmm>>>(
        hidebf, feaebf, poolWt, pooler_b, 1, Hh / BKg);
    cls_softmax_kernel<<<ROWS, 224, 0, sHmm>>>(feaebf, cls_W, cls_b, Bprob);
    hmm_kernel<<<ROWS / 128, 128, 0, sHmm>>>(Bprob, hmm_A, loghmm);
    cudaEventRecord(eHmm, sHmm);

    // ---- u0 partial on sPrep (off the critical path) ----
    cudaStreamWaitEvent(sPrep, ePoolC, 0);
    u0part_kernel<<<ROWS, 224, 0, sPrep>>>(feacbf, U0t, u0part);

    // ---- GAT chain on s0 ----
    cudaStreamWaitEvent(s0, eWgt, 0);
    mma_gemm<<<dim3(Hh / BN, ROWS / BM), 256, GEMM_SMEM, s0>>>(
        feacbf, Whbf, Wgt, nullptr, 0, Hh / BKg);
    cudaEventRecord(eWh, s0);
    att1_tile_kernel<<<dim3(8, 8, Bc), 128, 0, s0>>>(Whbf, gat_a1, gat_a2, h1bf);
    cudaEventRecord(eAtt1, s0);

    // mean_row0 concurrent with att1 on sPrep (disjoint h1 rows)
    cudaStreamWaitEvent(sPrep, eWh, 0);
    mean_row0_kernel<<<dim3(Hh / 256, Bc), 256, 0, sPrep>>>(Whbf, h1bf);
    cudaEventRecord(eMean, sPrep);
    cudaEventRecord(ePart, sPrep);     // ePart also covers u0part (ordered on sPrep)

    // h1-based attention-2 scores on sHmm, concurrent with gemm3
    cudaStreamWaitEvent(sHmm, eAtt1, 0);
    cudaStreamWaitEvent(sHmm, eMean, 0);
    cudaStreamWaitEvent(sHmm, eTab, 0);    // va1/va2 ready
    h1_scores_kernel<<<ROWS, 256, 0, sHmm>>>(h1bf, va1, va2, s1b, s2b);
    cudaEventRecord(eScore, sHmm);

    cudaStreamWaitEvent(s0, eTab, 0);      // outWt ready
    cudaStreamWaitEvent(s0, eMean, 0);     // h1 row 0 ready
    mma_gemm<<<dim3(Hh / BN, ROWS / BM), 256, GEMM_SMEM, s0>>>(
        h1bf, Wh2bf, outWt, nullptr, 0, Hh / BKg);

    cudaStreamWaitEvent(s0, eScore, 0);    // scores computed during gemm3
    att2_tile_kernel<<<dim3(8, 8, Bc), 128, 0, s0>>>(Wh2bf, s1b, s2b, h2bf);

    cudaStreamWaitEvent(s0, ePart, 0);
    gat_logits_kernel<<<ROWS, 224, 0, s0>>>(feacbf, h2bf, u0part, U2t, cvec, loggat);

    // ---- join HMM branch, final ----
    cudaStreamWaitEvent(s0, eHmm, 0);
    final_kernel<<<ROWS / 256, 256, 0, s0>>>(loggat, loghmm, labels, outLogits);
    finalize_kernel<<<1, 1, 0, s0>>>((float*)d_out, has_loss);
}